// round 1
// baseline (speedup 1.0000x reference)
#include <cuda_runtime.h>
#include <math.h>
#include <stdint.h>

// Problem constants
#define BATCH 8
#define CH    512
#define SP    1024      // H*W = 32*32
#define NHEAD 8
#define HDIM  64
#define NGRP  32
#define GCH   16        // channels per group

// Scratch (device globals: allocation-free per harness rules)
__device__ float g_h[BATCH * CH * SP];        // groupnorm output      (16 MB)
__device__ float g_qkv[BATCH * 3 * CH * SP];  // qkv projections       (50 MB)
__device__ float g_att[BATCH * CH * SP];      // attention output      (16 MB)

// ---------------------------------------------------------------------------
// GroupNorm: one block per (batch, group). 16 ch * 1024 = 16384 elems/group.
// ---------------------------------------------------------------------------
__global__ void gn_kernel(const float* __restrict__ x,
                          const float* __restrict__ gamma,
                          const float* __restrict__ beta,
                          float* __restrict__ h) {
    int b = blockIdx.x >> 5;
    int g = blockIdx.x & 31;
    const float* xp = x + ((size_t)b * CH + g * GCH) * SP;
    float* hp       = h + ((size_t)b * CH + g * GCH) * SP;
    int t = threadIdx.x;

    float sum = 0.f, sq = 0.f;
    for (int i4 = t; i4 < GCH * SP / 4; i4 += 256) {
        float4 v = *(const float4*)(xp + i4 * 4);
        sum += v.x + v.y + v.z + v.w;
        sq  += v.x * v.x + v.y * v.y + v.z * v.z + v.w * v.w;
    }
    __shared__ float s1[256], s2[256];
    s1[t] = sum; s2[t] = sq;
    __syncthreads();
    for (int off = 128; off > 0; off >>= 1) {
        if (t < off) { s1[t] += s1[t + off]; s2[t] += s2[t + off]; }
        __syncthreads();
    }
    const float invN = 1.f / (GCH * SP);
    float mean = s1[0] * invN;
    float var  = s2[0] * invN - mean * mean;
    float inv  = rsqrtf(var + 1e-6f);

    for (int i4 = t; i4 < GCH * SP / 4; i4 += 256) {
        int c = i4 >> 8;  // (i4*4)/1024
        float ga = gamma[g * GCH + c];
        float be = beta[g * GCH + c];
        float4 v = *(const float4*)(xp + i4 * 4);
        float4 o;
        o.x = (v.x - mean) * inv * ga + be;
        o.y = (v.y - mean) * inv * ga + be;
        o.z = (v.z - mean) * inv * ga + be;
        o.w = (v.w - mean) * inv * ga + be;
        *(float4*)(hp + i4 * 4) = o;
    }
}

// ---------------------------------------------------------------------------
// SGEMM: C[bz] = A[M,K] @ B[bz][K,N] + bias[M] (+ resid[bz][M,N])
// BM=BN=128, BK=16, 256 threads, 8x8 micro-tile per thread.
// ---------------------------------------------------------------------------
__global__ __launch_bounds__(256) void sgemm_kernel(
    const float* __restrict__ A, const float* __restrict__ Bm,
    const float* __restrict__ bias, const float* __restrict__ resid,
    float* __restrict__ C, int M, int N, int K) {
    __shared__ float As[16 * 128];   // As[k][m]
    __shared__ float Bs[16 * 128];   // Bs[k][n]

    int tid = threadIdx.x;
    int tx = tid & 15, ty = tid >> 4;
    int m0 = blockIdx.y * 128, n0 = blockIdx.x * 128;

    const float* Bp = Bm + (size_t)blockIdx.z * K * N;
    float* Cp       = C  + (size_t)blockIdx.z * M * N;
    const float* Rp = resid ? resid + (size_t)blockIdx.z * M * N : nullptr;

    float acc[8][8];
#pragma unroll
    for (int i = 0; i < 8; i++)
#pragma unroll
        for (int j = 0; j < 8; j++) acc[i][j] = 0.f;

    int am = tid >> 1;             // 0..127
    int ak = (tid & 1) * 8;        // 0 or 8
    int bk = tid >> 4;             // 0..15
    int bn = (tid & 15) * 8;       // 0..120

    for (int k0 = 0; k0 < K; k0 += 16) {
        float4 a0 = *(const float4*)&A[(size_t)(m0 + am) * K + k0 + ak];
        float4 a1 = *(const float4*)&A[(size_t)(m0 + am) * K + k0 + ak + 4];
        As[(ak + 0) * 128 + am] = a0.x;
        As[(ak + 1) * 128 + am] = a0.y;
        As[(ak + 2) * 128 + am] = a0.z;
        As[(ak + 3) * 128 + am] = a0.w;
        As[(ak + 4) * 128 + am] = a1.x;
        As[(ak + 5) * 128 + am] = a1.y;
        As[(ak + 6) * 128 + am] = a1.z;
        As[(ak + 7) * 128 + am] = a1.w;

        float4 b0 = *(const float4*)&Bp[(size_t)(k0 + bk) * N + n0 + bn];
        float4 b1 = *(const float4*)&Bp[(size_t)(k0 + bk) * N + n0 + bn + 4];
        *(float4*)&Bs[bk * 128 + bn]     = b0;
        *(float4*)&Bs[bk * 128 + bn + 4] = b1;
        __syncthreads();

#pragma unroll
        for (int kk = 0; kk < 16; kk++) {
            float ra[8], rb[8];
            *(float4*)&ra[0] = *(const float4*)&As[kk * 128 + ty * 8];
            *(float4*)&ra[4] = *(const float4*)&As[kk * 128 + ty * 8 + 4];
            *(float4*)&rb[0] = *(const float4*)&Bs[kk * 128 + tx * 8];
            *(float4*)&rb[4] = *(const float4*)&Bs[kk * 128 + tx * 8 + 4];
#pragma unroll
            for (int i = 0; i < 8; i++)
#pragma unroll
                for (int j = 0; j < 8; j++) acc[i][j] += ra[i] * rb[j];
        }
        __syncthreads();
    }

#pragma unroll
    for (int i = 0; i < 8; i++) {
        int m = m0 + ty * 8 + i;
        float bv = bias[m];
        int n = n0 + tx * 8;
        float4 o0, o1;
        o0.x = acc[i][0] + bv; o0.y = acc[i][1] + bv;
        o0.z = acc[i][2] + bv; o0.w = acc[i][3] + bv;
        o1.x = acc[i][4] + bv; o1.y = acc[i][5] + bv;
        o1.z = acc[i][6] + bv; o1.w = acc[i][7] + bv;
        if (Rp) {
            float4 r0 = *(const float4*)&Rp[(size_t)m * N + n];
            float4 r1 = *(const float4*)&Rp[(size_t)m * N + n + 4];
            o0.x += r0.x; o0.y += r0.y; o0.z += r0.z; o0.w += r0.w;
            o1.x += r1.x; o1.y += r1.y; o1.z += r1.z; o1.w += r1.w;
        }
        *(float4*)&Cp[(size_t)m * N + n]     = o0;
        *(float4*)&Cp[(size_t)m * N + n + 4] = o1;
    }
}

// ---------------------------------------------------------------------------
// Flash attention, fp32. Block = (b, head, q-tile of 128). 256 threads (16x16).
// Per k-tile (128 keys): S = Q^T K (8x8/thread), online softmax, P staged in
// smem, O += P @ V^T (8 qi x 4 c /thread).
// smem layout (floats): p_s[128*128] | qs[16*128] | ks[16*128] | vT[128*68]
// total = 29184 floats = 116736 B (dynamic).
// ---------------------------------------------------------------------------
#define ATTN_SMEM_BYTES 116736

__global__ __launch_bounds__(256, 1) void attn_kernel(
    const float* __restrict__ qkv, float* __restrict__ out) {
    extern __shared__ float sm[];
    float* p_s = sm;                 // 128 x 128, pitch 128
    float* qs  = sm + 16384;         // 16 x 128
    float* ks  = sm + 16384 + 2048;  // 16 x 128
    float* vT  = sm + 16384 + 4096;  // 128 x 64, pitch 68 (vT[ki][c])

    int tid = threadIdx.x;
    int tx = tid & 15, ty = tid >> 4;
    int qt = blockIdx.x * 128;
    int hn = blockIdx.y, b = blockIdx.z;

    const float* qg = qkv + ((size_t)b * 3 * CH + hn * HDIM) * SP;
    const float* kg = qg + (size_t)CH * SP;
    const float* vg = kg + (size_t)CH * SP;
    float* og = out + ((size_t)b * CH + hn * HDIM) * SP;

    float m_run[8], l_run[8], o[8][4];
#pragma unroll
    for (int i = 0; i < 8; i++) {
        m_run[i] = -INFINITY; l_run[i] = 0.f;
        o[i][0] = o[i][1] = o[i][2] = o[i][3] = 0.f;
    }

    for (int kt = 0; kt < SP; kt += 128) {
        // Load V tile transposed: vT[ki][c]
#pragma unroll
        for (int l = 0; l < 8; l++) {
            int slot = tid + l * 256;          // 0..2047
            int c = slot >> 5;                 // 0..63
            int ki4 = (slot & 31) * 4;         // 0..124
            float4 v = *(const float4*)&vg[(size_t)c * SP + kt + ki4];
            vT[(ki4 + 0) * 68 + c] = v.x;
            vT[(ki4 + 1) * 68 + c] = v.y;
            vT[(ki4 + 2) * 68 + c] = v.z;
            vT[(ki4 + 3) * 68 + c] = v.w;
        }

        // Phase 1: S = Q^T K over c-chunks of 16
        float acc[8][8];
#pragma unroll
        for (int i = 0; i < 8; i++)
#pragma unroll
            for (int j = 0; j < 8; j++) acc[i][j] = 0.f;

        for (int c0 = 0; c0 < HDIM; c0 += 16) {
#pragma unroll
            for (int l = 0; l < 2; l++) {
                int slot = tid + l * 256;      // 0..511
                int r = slot >> 5;             // 0..15
                int c4 = (slot & 31) * 4;      // 0..124
                *(float4*)&qs[r * 128 + c4] =
                    *(const float4*)&qg[(size_t)(c0 + r) * SP + qt + c4];
                *(float4*)&ks[r * 128 + c4] =
                    *(const float4*)&kg[(size_t)(c0 + r) * SP + kt + c4];
            }
            __syncthreads();
#pragma unroll
            for (int kk = 0; kk < 16; kk++) {
                float ra[8], rb[8];
                *(float4*)&ra[0] = *(const float4*)&qs[kk * 128 + ty * 8];
                *(float4*)&ra[4] = *(const float4*)&qs[kk * 128 + ty * 8 + 4];
                *(float4*)&rb[0] = *(const float4*)&ks[kk * 128 + tx * 8];
                *(float4*)&rb[4] = *(const float4*)&ks[kk * 128 + tx * 8 + 4];
#pragma unroll
                for (int i = 0; i < 8; i++)
#pragma unroll
                    for (int j = 0; j < 8; j++) acc[i][j] += ra[i] * rb[j];
            }
            __syncthreads();
        }

        // Online softmax per qi row (row = 16 tx threads of a half-warp)
#pragma unroll
        for (int i = 0; i < 8; i++) {
            float mloc = -INFINITY;
#pragma unroll
            for (int j = 0; j < 8; j++) {
                acc[i][j] *= 0.125f;  // 1/sqrt(64)
                mloc = fmaxf(mloc, acc[i][j]);
            }
#pragma unroll
            for (int off = 1; off < 16; off <<= 1)
                mloc = fmaxf(mloc, __shfl_xor_sync(0xffffffffu, mloc, off));
            float mnew = fmaxf(m_run[i], mloc);
            float corr = __expf(m_run[i] - mnew);
            float pv[8], ps = 0.f;
#pragma unroll
            for (int j = 0; j < 8; j++) {
                pv[j] = __expf(acc[i][j] - mnew);
                ps += pv[j];
            }
#pragma unroll
            for (int off = 1; off < 16; off <<= 1)
                ps += __shfl_xor_sync(0xffffffffu, ps, off);
            l_run[i] = l_run[i] * corr + ps;
            m_run[i] = mnew;
            o[i][0] *= corr; o[i][1] *= corr; o[i][2] *= corr; o[i][3] *= corr;
            *(float4*)&p_s[(ty * 8 + i) * 128 + tx * 8] =
                make_float4(pv[0], pv[1], pv[2], pv[3]);
            *(float4*)&p_s[(ty * 8 + i) * 128 + tx * 8 + 4] =
                make_float4(pv[4], pv[5], pv[6], pv[7]);
        }
        __syncthreads();

        // Phase 2: O += P @ V^T   (thread: 8 qi rows x 4 c cols)
        for (int k4 = 0; k4 < 128; k4 += 4) {
            float pr[8][4];
#pragma unroll
            for (int i = 0; i < 8; i++) {
                float4 t4 = *(const float4*)&p_s[(ty * 8 + i) * 128 + k4];
                pr[i][0] = t4.x; pr[i][1] = t4.y; pr[i][2] = t4.z; pr[i][3] = t4.w;
            }
#pragma unroll
            for (int u = 0; u < 4; u++) {
                float4 vv = *(const float4*)&vT[(k4 + u) * 68 + tx * 4];
#pragma unroll
                for (int i = 0; i < 8; i++) {
                    float p = pr[i][u];
                    o[i][0] += p * vv.x;
                    o[i][1] += p * vv.y;
                    o[i][2] += p * vv.z;
                    o[i][3] += p * vv.w;
                }
            }
        }
        __syncthreads();
    }

    // Epilogue: out[b, head*64 + c, s]
#pragma unroll
    for (int i = 0; i < 8; i++) {
        float inv = 1.f / l_run[i];
        int s = qt + ty * 8 + i;
#pragma unroll
        for (int j = 0; j < 4; j++)
            og[(size_t)(tx * 4 + j) * SP + s] = o[i][j] * inv;
    }
}

// ---------------------------------------------------------------------------
extern "C" void kernel_launch(void* const* d_in, const int* in_sizes, int n_in,
                              void* d_out, int out_size) {
    const float* x     = (const float*)d_in[0];
    const float* gamma = (const float*)d_in[1];
    const float* beta  = (const float*)d_in[2];
    const float* w_in  = (const float*)d_in[3];
    const float* b_in  = (const float*)d_in[4];
    const float* w_out = (const float*)d_in[5];
    const float* b_out = (const float*)d_in[6];
    float* out = (float*)d_out;

    float *h, *qkv, *att;
    cudaGetSymbolAddress((void**)&h,   g_h);
    cudaGetSymbolAddress((void**)&qkv, g_qkv);
    cudaGetSymbolAddress((void**)&att, g_att);

    // 1. GroupNorm
    gn_kernel<<<BATCH * NGRP, 256>>>(x, gamma, beta, h);

    // 2. QKV projection: [1536,512] @ [512,1024] per batch
    sgemm_kernel<<<dim3(SP / 128, (3 * CH) / 128, BATCH), 256>>>(
        w_in, h, b_in, nullptr, qkv, 3 * CH, SP, CH);

    // 3. Attention
    cudaFuncSetAttribute(attn_kernel, cudaFuncAttributeMaxDynamicSharedMemorySize,
                         ATTN_SMEM_BYTES);
    attn_kernel<<<dim3(SP / 128, NHEAD, BATCH), 256, ATTN_SMEM_BYTES>>>(qkv, att);

    // 4. Output projection + bias + residual
    sgemm_kernel<<<dim3(SP / 128, CH / 128, BATCH), 256>>>(
        w_out, att, b_out, x, out, CH, SP, CH);
}

// round 2
// speedup vs baseline: 1.4082x; 1.4082x over previous
#include <cuda_runtime.h>
#include <math.h>
#include <stdint.h>

// Problem constants
#define BATCH 8
#define CH    512
#define SP    1024      // H*W = 32*32
#define NHEAD 8
#define HDIM  64
#define NGRP  32
#define GCH   16        // channels per group

// Scratch (device globals: allocation-free per harness rules)
__device__ float g_h[BATCH * CH * SP];        // groupnorm output      (16 MB)
__device__ float g_qkv[BATCH * 3 * CH * SP];  // qkv projections       (50 MB)
__device__ float g_att[BATCH * CH * SP];      // attention output      (16 MB)

// ---------------------------------------------------------------------------
// GroupNorm: one block per (batch, group). 16 ch * 1024 = 16384 elems/group.
// ---------------------------------------------------------------------------
__global__ void gn_kernel(const float* __restrict__ x,
                          const float* __restrict__ gamma,
                          const float* __restrict__ beta,
                          float* __restrict__ h) {
    int b = blockIdx.x >> 5;
    int g = blockIdx.x & 31;
    const float* xp = x + ((size_t)b * CH + g * GCH) * SP;
    float* hp       = h + ((size_t)b * CH + g * GCH) * SP;
    int t = threadIdx.x;

    float sum = 0.f, sq = 0.f;
    for (int i4 = t; i4 < GCH * SP / 4; i4 += 256) {
        float4 v = *(const float4*)(xp + i4 * 4);
        sum += v.x + v.y + v.z + v.w;
        sq  += v.x * v.x + v.y * v.y + v.z * v.z + v.w * v.w;
    }
    __shared__ float s1[256], s2[256];
    s1[t] = sum; s2[t] = sq;
    __syncthreads();
    for (int off = 128; off > 0; off >>= 1) {
        if (t < off) { s1[t] += s1[t + off]; s2[t] += s2[t + off]; }
        __syncthreads();
    }
    const float invN = 1.f / (GCH * SP);
    float mean = s1[0] * invN;
    float var  = s2[0] * invN - mean * mean;
    float inv  = rsqrtf(var + 1e-6f);

    for (int i4 = t; i4 < GCH * SP / 4; i4 += 256) {
        int c = i4 >> 8;
        float ga = gamma[g * GCH + c];
        float be = beta[g * GCH + c];
        float4 v = *(const float4*)(xp + i4 * 4);
        float4 o;
        o.x = (v.x - mean) * inv * ga + be;
        o.y = (v.y - mean) * inv * ga + be;
        o.z = (v.z - mean) * inv * ga + be;
        o.w = (v.w - mean) * inv * ga + be;
        *(float4*)(hp + i4 * 4) = o;
    }
}

// ---------------------------------------------------------------------------
// TF32 tensor-core GEMM: C[bz] = A[M,K] @ B[bz][K,N] + bias[M] (+ resid)
// Block 128x128, K-tile 32. 8 warps, warp tile 32x64, mma.m16n8k8 tf32.
// smem pitch 136 floats -> fragment LDS are bank-conflict-free
// (bank = (8k + m) % 32 hits all 32 banks across a warp).
// ---------------------------------------------------------------------------
#define GPITCH 136

__device__ __forceinline__ uint32_t f2tf32(float f) {
    uint32_t r;
    asm("cvt.rna.tf32.f32 %0, %1;" : "=r"(r) : "f"(f));
    return r;
}

#define MMA_TF32(d, a, b0, b1)                                              \
    asm volatile(                                                           \
        "mma.sync.aligned.m16n8k8.row.col.f32.tf32.tf32.f32 "               \
        "{%0,%1,%2,%3}, {%4,%5,%6,%7}, {%8,%9}, {%0,%1,%2,%3};"             \
        : "+f"(d[0]), "+f"(d[1]), "+f"(d[2]), "+f"(d[3])                    \
        : "r"(a[0]), "r"(a[1]), "r"(a[2]), "r"(a[3]), "r"(b0), "r"(b1))

__global__ __launch_bounds__(256) void tf32_gemm_kernel(
    const float* __restrict__ A, const float* __restrict__ Bm,
    const float* __restrict__ bias, const float* __restrict__ resid,
    float* __restrict__ C, int M, int N, int K) {
    __shared__ uint32_t As[32 * GPITCH];  // [k][m]
    __shared__ uint32_t Bs[32 * GPITCH];  // [k][n]

    int tid  = threadIdx.x;
    int warp = tid >> 5, lane = tid & 31;
    int gid = lane >> 2, tg = lane & 3;        // mma fragment coords
    int wm = (warp >> 1) * 32, wn = (warp & 1) * 64;
    int m0 = blockIdx.y * 128, n0 = blockIdx.x * 128;

    const float* Bp = Bm + (size_t)blockIdx.z * K * N;
    float* Cp       = C  + (size_t)blockIdx.z * M * N;
    const float* Rp = resid ? resid + (size_t)blockIdx.z * M * N : nullptr;

    float acc[2][8][4];
#pragma unroll
    for (int mt = 0; mt < 2; mt++)
#pragma unroll
        for (int nt = 0; nt < 8; nt++)
#pragma unroll
            for (int e = 0; e < 4; e++) acc[mt][nt][e] = 0.f;

    // Global-load mappings
    int a_row = tid >> 1;                 // 0..127 (m)
    int a_k   = (tid & 1) * 16;           // 0 or 16 (k base, 16 floats each)
    const float* Ap = A + (size_t)(m0 + a_row) * K + a_k;

    float4 pa[4], pb[4];

    // Prefetch tile 0
#pragma unroll
    for (int j = 0; j < 4; j++) pa[j] = *(const float4*)(Ap + j * 4);
#pragma unroll
    for (int l = 0; l < 4; l++) {
        int slot = tid + l * 256;
        int br = slot >> 5, bc = (slot & 31) * 4;
        pb[l] = *(const float4*)&Bp[(size_t)br * N + n0 + bc];
    }

    for (int k0 = 0; k0 < K; k0 += 32) {
        // Store prefetched tile to smem (convert to tf32)
#pragma unroll
        for (int j = 0; j < 4; j++) {
            As[(a_k + j * 4 + 0) * GPITCH + a_row] = f2tf32(pa[j].x);
            As[(a_k + j * 4 + 1) * GPITCH + a_row] = f2tf32(pa[j].y);
            As[(a_k + j * 4 + 2) * GPITCH + a_row] = f2tf32(pa[j].z);
            As[(a_k + j * 4 + 3) * GPITCH + a_row] = f2tf32(pa[j].w);
        }
#pragma unroll
        for (int l = 0; l < 4; l++) {
            int slot = tid + l * 256;
            int br = slot >> 5, bc = (slot & 31) * 4;
            uint4 u;
            u.x = f2tf32(pb[l].x); u.y = f2tf32(pb[l].y);
            u.z = f2tf32(pb[l].z); u.w = f2tf32(pb[l].w);
            *(uint4*)&Bs[br * GPITCH + bc] = u;
        }
        __syncthreads();

        // Prefetch next tile
        if (k0 + 32 < K) {
#pragma unroll
            for (int j = 0; j < 4; j++)
                pa[j] = *(const float4*)(Ap + k0 + 32 + j * 4);
#pragma unroll
            for (int l = 0; l < 4; l++) {
                int slot = tid + l * 256;
                int br = slot >> 5, bc = (slot & 31) * 4;
                pb[l] = *(const float4*)&Bp[(size_t)(k0 + 32 + br) * N + n0 + bc];
            }
        }

        // Compute: 4 k-steps of 8
#pragma unroll
        for (int kk = 0; kk < 4; kk++) {
            int kb = kk * 8;
            uint32_t af[2][4];
#pragma unroll
            for (int mt = 0; mt < 2; mt++) {
                int mr = wm + mt * 16 + gid;
                af[mt][0] = As[(kb + tg) * GPITCH + mr];
                af[mt][1] = As[(kb + tg) * GPITCH + mr + 8];
                af[mt][2] = As[(kb + tg + 4) * GPITCH + mr];
                af[mt][3] = As[(kb + tg + 4) * GPITCH + mr + 8];
            }
#pragma unroll
            for (int nt = 0; nt < 8; nt++) {
                uint32_t b0 = Bs[(kb + tg) * GPITCH + wn + nt * 8 + gid];
                uint32_t b1 = Bs[(kb + tg + 4) * GPITCH + wn + nt * 8 + gid];
                MMA_TF32(acc[0][nt], af[0], b0, b1);
                MMA_TF32(acc[1][nt], af[1], b0, b1);
            }
        }
        __syncthreads();
    }

    // Epilogue: c{0,1} at row gid, c{2,3} at row gid+8; cols 2*tg, 2*tg+1
#pragma unroll
    for (int mt = 0; mt < 2; mt++) {
        int r0 = m0 + wm + mt * 16 + gid;
        int r1 = r0 + 8;
        float bv0 = bias[r0], bv1 = bias[r1];
#pragma unroll
        for (int nt = 0; nt < 8; nt++) {
            int col = n0 + wn + nt * 8 + tg * 2;
            float2 v0, v1;
            v0.x = acc[mt][nt][0] + bv0; v0.y = acc[mt][nt][1] + bv0;
            v1.x = acc[mt][nt][2] + bv1; v1.y = acc[mt][nt][3] + bv1;
            if (Rp) {
                float2 q0 = *(const float2*)&Rp[(size_t)r0 * N + col];
                float2 q1 = *(const float2*)&Rp[(size_t)r1 * N + col];
                v0.x += q0.x; v0.y += q0.y;
                v1.x += q1.x; v1.y += q1.y;
            }
            *(float2*)&Cp[(size_t)r0 * N + col] = v0;
            *(float2*)&Cp[(size_t)r1 * N + col] = v1;
        }
    }
}

// ---------------------------------------------------------------------------
// Flash attention, fp32 (unchanged from R1).
// ---------------------------------------------------------------------------
#define ATTN_SMEM_BYTES 116736

__global__ __launch_bounds__(256, 1) void attn_kernel(
    const float* __restrict__ qkv, float* __restrict__ out) {
    extern __shared__ float sm[];
    float* p_s = sm;                 // 128 x 128, pitch 128
    float* qs  = sm + 16384;         // 16 x 128
    float* ks  = sm + 16384 + 2048;  // 16 x 128
    float* vT  = sm + 16384 + 4096;  // 128 x 64, pitch 68

    int tid = threadIdx.x;
    int tx = tid & 15, ty = tid >> 4;
    int qt = blockIdx.x * 128;
    int hn = blockIdx.y, b = blockIdx.z;

    const float* qg = qkv + ((size_t)b * 3 * CH + hn * HDIM) * SP;
    const float* kg = qg + (size_t)CH * SP;
    const float* vg = kg + (size_t)CH * SP;
    float* og = out + ((size_t)b * CH + hn * HDIM) * SP;

    float m_run[8], l_run[8], o[8][4];
#pragma unroll
    for (int i = 0; i < 8; i++) {
        m_run[i] = -INFINITY; l_run[i] = 0.f;
        o[i][0] = o[i][1] = o[i][2] = o[i][3] = 0.f;
    }

    for (int kt = 0; kt < SP; kt += 128) {
#pragma unroll
        for (int l = 0; l < 8; l++) {
            int slot = tid + l * 256;
            int c = slot >> 5;
            int ki4 = (slot & 31) * 4;
            float4 v = *(const float4*)&vg[(size_t)c * SP + kt + ki4];
            vT[(ki4 + 0) * 68 + c] = v.x;
            vT[(ki4 + 1) * 68 + c] = v.y;
            vT[(ki4 + 2) * 68 + c] = v.z;
            vT[(ki4 + 3) * 68 + c] = v.w;
        }

        float acc[8][8];
#pragma unroll
        for (int i = 0; i < 8; i++)
#pragma unroll
            for (int j = 0; j < 8; j++) acc[i][j] = 0.f;

        for (int c0 = 0; c0 < HDIM; c0 += 16) {
#pragma unroll
            for (int l = 0; l < 2; l++) {
                int slot = tid + l * 256;
                int r = slot >> 5;
                int c4 = (slot & 31) * 4;
                *(float4*)&qs[r * 128 + c4] =
                    *(const float4*)&qg[(size_t)(c0 + r) * SP + qt + c4];
                *(float4*)&ks[r * 128 + c4] =
                    *(const float4*)&kg[(size_t)(c0 + r) * SP + kt + c4];
            }
            __syncthreads();
#pragma unroll
            for (int kk = 0; kk < 16; kk++) {
                float ra[8], rb[8];
                *(float4*)&ra[0] = *(const float4*)&qs[kk * 128 + ty * 8];
                *(float4*)&ra[4] = *(const float4*)&qs[kk * 128 + ty * 8 + 4];
                *(float4*)&rb[0] = *(const float4*)&ks[kk * 128 + tx * 8];
                *(float4*)&rb[4] = *(const float4*)&ks[kk * 128 + tx * 8 + 4];
#pragma unroll
                for (int i = 0; i < 8; i++)
#pragma unroll
                    for (int j = 0; j < 8; j++) acc[i][j] += ra[i] * rb[j];
            }
            __syncthreads();
        }

#pragma unroll
        for (int i = 0; i < 8; i++) {
            float mloc = -INFINITY;
#pragma unroll
            for (int j = 0; j < 8; j++) {
                acc[i][j] *= 0.125f;
                mloc = fmaxf(mloc, acc[i][j]);
            }
#pragma unroll
            for (int off = 1; off < 16; off <<= 1)
                mloc = fmaxf(mloc, __shfl_xor_sync(0xffffffffu, mloc, off));
            float mnew = fmaxf(m_run[i], mloc);
            float corr = __expf(m_run[i] - mnew);
            float pv[8], ps = 0.f;
#pragma unroll
            for (int j = 0; j < 8; j++) {
                pv[j] = __expf(acc[i][j] - mnew);
                ps += pv[j];
            }
#pragma unroll
            for (int off = 1; off < 16; off <<= 1)
                ps += __shfl_xor_sync(0xffffffffu, ps, off);
            l_run[i] = l_run[i] * corr + ps;
            m_run[i] = mnew;
            o[i][0] *= corr; o[i][1] *= corr; o[i][2] *= corr; o[i][3] *= corr;
            *(float4*)&p_s[(ty * 8 + i) * 128 + tx * 8] =
                make_float4(pv[0], pv[1], pv[2], pv[3]);
            *(float4*)&p_s[(ty * 8 + i) * 128 + tx * 8 + 4] =
                make_float4(pv[4], pv[5], pv[6], pv[7]);
        }
        __syncthreads();

        for (int k4 = 0; k4 < 128; k4 += 4) {
            float pr[8][4];
#pragma unroll
            for (int i = 0; i < 8; i++) {
                float4 t4 = *(const float4*)&p_s[(ty * 8 + i) * 128 + k4];
                pr[i][0] = t4.x; pr[i][1] = t4.y; pr[i][2] = t4.z; pr[i][3] = t4.w;
            }
#pragma unroll
            for (int u = 0; u < 4; u++) {
                float4 vv = *(const float4*)&vT[(k4 + u) * 68 + tx * 4];
#pragma unroll
                for (int i = 0; i < 8; i++) {
                    float p = pr[i][u];
                    o[i][0] += p * vv.x;
                    o[i][1] += p * vv.y;
                    o[i][2] += p * vv.z;
                    o[i][3] += p * vv.w;
                }
            }
        }
        __syncthreads();
    }

#pragma unroll
    for (int i = 0; i < 8; i++) {
        float inv = 1.f / l_run[i];
        int s = qt + ty * 8 + i;
#pragma unroll
        for (int j = 0; j < 4; j++)
            og[(size_t)(tx * 4 + j) * SP + s] = o[i][j] * inv;
    }
}

// ---------------------------------------------------------------------------
extern "C" void kernel_launch(void* const* d_in, const int* in_sizes, int n_in,
                              void* d_out, int out_size) {
    const float* x     = (const float*)d_in[0];
    const float* gamma = (const float*)d_in[1];
    const float* beta  = (const float*)d_in[2];
    const float* w_in  = (const float*)d_in[3];
    const float* b_in  = (const float*)d_in[4];
    const float* w_out = (const float*)d_in[5];
    const float* b_out = (const float*)d_in[6];
    float* out = (float*)d_out;

    float *h, *qkv, *att;
    cudaGetSymbolAddress((void**)&h,   g_h);
    cudaGetSymbolAddress((void**)&qkv, g_qkv);
    cudaGetSymbolAddress((void**)&att, g_att);

    // 1. GroupNorm
    gn_kernel<<<BATCH * NGRP, 256>>>(x, gamma, beta, h);

    // 2. QKV projection: [1536,512] @ [512,1024] per batch (tf32 tensor cores)
    tf32_gemm_kernel<<<dim3(SP / 128, (3 * CH) / 128, BATCH), 256>>>(
        w_in, h, b_in, nullptr, qkv, 3 * CH, SP, CH);

    // 3. Attention
    cudaFuncSetAttribute(attn_kernel, cudaFuncAttributeMaxDynamicSharedMemorySize,
                         ATTN_SMEM_BYTES);
    attn_kernel<<<dim3(SP / 128, NHEAD, BATCH), 256, ATTN_SMEM_BYTES>>>(qkv, att);

    // 4. Output projection + bias + residual (tf32 tensor cores)
    tf32_gemm_kernel<<<dim3(SP / 128, CH / 128, BATCH), 256>>>(
        w_out, att, b_out, x, out, CH, SP, CH);
}

// round 3
// speedup vs baseline: 1.7526x; 1.2445x over previous
#include <cuda_runtime.h>
#include <math.h>
#include <stdint.h>

// Problem constants
#define BATCH 8
#define CH    512
#define SP    1024      // H*W = 32*32
#define NHEAD 8
#define HDIM  64
#define NGRP  32
#define GCH   16        // channels per group

// Scratch (device globals: allocation-free per harness rules)
__device__ float g_h[BATCH * CH * SP];        // groupnorm output
__device__ float g_qkv[BATCH * 3 * CH * SP];  // qkv projections
__device__ float g_att[BATCH * CH * SP];      // attention output

// ---------------------------------------------------------------------------
// GroupNorm (unchanged)
// ---------------------------------------------------------------------------
__global__ void gn_kernel(const float* __restrict__ x,
                          const float* __restrict__ gamma,
                          const float* __restrict__ beta,
                          float* __restrict__ h) {
    int b = blockIdx.x >> 5;
    int g = blockIdx.x & 31;
    const float* xp = x + ((size_t)b * CH + g * GCH) * SP;
    float* hp       = h + ((size_t)b * CH + g * GCH) * SP;
    int t = threadIdx.x;

    float sum = 0.f, sq = 0.f;
    for (int i4 = t; i4 < GCH * SP / 4; i4 += 256) {
        float4 v = *(const float4*)(xp + i4 * 4);
        sum += v.x + v.y + v.z + v.w;
        sq  += v.x * v.x + v.y * v.y + v.z * v.z + v.w * v.w;
    }
    __shared__ float s1[256], s2[256];
    s1[t] = sum; s2[t] = sq;
    __syncthreads();
    for (int off = 128; off > 0; off >>= 1) {
        if (t < off) { s1[t] += s1[t + off]; s2[t] += s2[t + off]; }
        __syncthreads();
    }
    const float invN = 1.f / (GCH * SP);
    float mean = s1[0] * invN;
    float var  = s2[0] * invN - mean * mean;
    float inv  = rsqrtf(var + 1e-6f);

    for (int i4 = t; i4 < GCH * SP / 4; i4 += 256) {
        int c = i4 >> 8;
        float ga = gamma[g * GCH + c];
        float be = beta[g * GCH + c];
        float4 v = *(const float4*)(xp + i4 * 4);
        float4 o;
        o.x = (v.x - mean) * inv * ga + be;
        o.y = (v.y - mean) * inv * ga + be;
        o.z = (v.z - mean) * inv * ga + be;
        o.w = (v.w - mean) * inv * ga + be;
        *(float4*)(hp + i4 * 4) = o;
    }
}

// ---------------------------------------------------------------------------
// TF32 tensor-core GEMM (unchanged from R2)
// ---------------------------------------------------------------------------
#define GPITCH 136

__device__ __forceinline__ uint32_t f2tf32(float f) {
    uint32_t r;
    asm("cvt.rna.tf32.f32 %0, %1;" : "=r"(r) : "f"(f));
    return r;
}

#define MMA_TF32(d, a, b0, b1)                                              \
    asm volatile(                                                           \
        "mma.sync.aligned.m16n8k8.row.col.f32.tf32.tf32.f32 "               \
        "{%0,%1,%2,%3}, {%4,%5,%6,%7}, {%8,%9}, {%0,%1,%2,%3};"             \
        : "+f"(d[0]), "+f"(d[1]), "+f"(d[2]), "+f"(d[3])                    \
        : "r"(a[0]), "r"(a[1]), "r"(a[2]), "r"(a[3]), "r"(b0), "r"(b1))

__global__ __launch_bounds__(256) void tf32_gemm_kernel(
    const float* __restrict__ A, const float* __restrict__ Bm,
    const float* __restrict__ bias, const float* __restrict__ resid,
    float* __restrict__ C, int M, int N, int K) {
    __shared__ uint32_t As[32 * GPITCH];
    __shared__ uint32_t Bs[32 * GPITCH];

    int tid  = threadIdx.x;
    int warp = tid >> 5, lane = tid & 31;
    int gid = lane >> 2, tg = lane & 3;
    int wm = (warp >> 1) * 32, wn = (warp & 1) * 64;
    int m0 = blockIdx.y * 128, n0 = blockIdx.x * 128;

    const float* Bp = Bm + (size_t)blockIdx.z * K * N;
    float* Cp       = C  + (size_t)blockIdx.z * M * N;
    const float* Rp = resid ? resid + (size_t)blockIdx.z * M * N : nullptr;

    float acc[2][8][4];
#pragma unroll
    for (int mt = 0; mt < 2; mt++)
#pragma unroll
        for (int nt = 0; nt < 8; nt++)
#pragma unroll
            for (int e = 0; e < 4; e++) acc[mt][nt][e] = 0.f;

    int a_row = tid >> 1;
    int a_k   = (tid & 1) * 16;
    const float* Ap = A + (size_t)(m0 + a_row) * K + a_k;

    float4 pa[4], pb[4];
#pragma unroll
    for (int j = 0; j < 4; j++) pa[j] = *(const float4*)(Ap + j * 4);
#pragma unroll
    for (int l = 0; l < 4; l++) {
        int slot = tid + l * 256;
        int br = slot >> 5, bc = (slot & 31) * 4;
        pb[l] = *(const float4*)&Bp[(size_t)br * N + n0 + bc];
    }

    for (int k0 = 0; k0 < K; k0 += 32) {
#pragma unroll
        for (int j = 0; j < 4; j++) {
            As[(a_k + j * 4 + 0) * GPITCH + a_row] = f2tf32(pa[j].x);
            As[(a_k + j * 4 + 1) * GPITCH + a_row] = f2tf32(pa[j].y);
            As[(a_k + j * 4 + 2) * GPITCH + a_row] = f2tf32(pa[j].z);
            As[(a_k + j * 4 + 3) * GPITCH + a_row] = f2tf32(pa[j].w);
        }
#pragma unroll
        for (int l = 0; l < 4; l++) {
            int slot = tid + l * 256;
            int br = slot >> 5, bc = (slot & 31) * 4;
            uint4 u;
            u.x = f2tf32(pb[l].x); u.y = f2tf32(pb[l].y);
            u.z = f2tf32(pb[l].z); u.w = f2tf32(pb[l].w);
            *(uint4*)&Bs[br * GPITCH + bc] = u;
        }
        __syncthreads();

        if (k0 + 32 < K) {
#pragma unroll
            for (int j = 0; j < 4; j++)
                pa[j] = *(const float4*)(Ap + k0 + 32 + j * 4);
#pragma unroll
            for (int l = 0; l < 4; l++) {
                int slot = tid + l * 256;
                int br = slot >> 5, bc = (slot & 31) * 4;
                pb[l] = *(const float4*)&Bp[(size_t)(k0 + 32 + br) * N + n0 + bc];
            }
        }

#pragma unroll
        for (int kk = 0; kk < 4; kk++) {
            int kb = kk * 8;
            uint32_t af[2][4];
#pragma unroll
            for (int mt = 0; mt < 2; mt++) {
                int mr = wm + mt * 16 + gid;
                af[mt][0] = As[(kb + tg) * GPITCH + mr];
                af[mt][1] = As[(kb + tg) * GPITCH + mr + 8];
                af[mt][2] = As[(kb + tg + 4) * GPITCH + mr];
                af[mt][3] = As[(kb + tg + 4) * GPITCH + mr + 8];
            }
#pragma unroll
            for (int nt = 0; nt < 8; nt++) {
                uint32_t b0 = Bs[(kb + tg) * GPITCH + wn + nt * 8 + gid];
                uint32_t b1 = Bs[(kb + tg + 4) * GPITCH + wn + nt * 8 + gid];
                MMA_TF32(acc[0][nt], af[0], b0, b1);
                MMA_TF32(acc[1][nt], af[1], b0, b1);
            }
        }
        __syncthreads();
    }

#pragma unroll
    for (int mt = 0; mt < 2; mt++) {
        int r0 = m0 + wm + mt * 16 + gid;
        int r1 = r0 + 8;
        float bv0 = bias[r0], bv1 = bias[r1];
#pragma unroll
        for (int nt = 0; nt < 8; nt++) {
            int col = n0 + wn + nt * 8 + tg * 2;
            float2 v0, v1;
            v0.x = acc[mt][nt][0] + bv0; v0.y = acc[mt][nt][1] + bv0;
            v1.x = acc[mt][nt][2] + bv1; v1.y = acc[mt][nt][3] + bv1;
            if (Rp) {
                float2 q0 = *(const float2*)&Rp[(size_t)r0 * N + col];
                float2 q1 = *(const float2*)&Rp[(size_t)r1 * N + col];
                v0.x += q0.x; v0.y += q0.y;
                v1.x += q1.x; v1.y += q1.y;
            }
            *(float2*)&Cp[(size_t)r0 * N + col] = v0;
            *(float2*)&Cp[(size_t)r1 * N + col] = v1;
        }
    }
}

// ---------------------------------------------------------------------------
// TF32 flash attention.
// Block = (q-tile 128, head, batch), 256 threads = 8 warps.
// Each warp owns 16 q rows (wm = warp*16) across the full 128-wide k tile.
// Phase 1: S = Q^T K  (m=q16, n=k128 as 16 n-tiles, k=c in 8 chunks).
// Phase 2: O^T = V @ P^T (m=c64 as 4 m-tiles, n=q16 as 2 n-tiles, k=k128).
// smem (tf32 words): qs[64][132], ks[64][132], vs[64][132], p_s[128][132].
// ---------------------------------------------------------------------------
#define APITCH 132
#define ATTN_SMEM_BYTES ((3 * 64 * APITCH + 128 * APITCH) * 4)

__global__ __launch_bounds__(256, 1) void attn_tc_kernel(
    const float* __restrict__ qkv, float* __restrict__ out) {
    extern __shared__ uint32_t smw[];
    uint32_t* qs  = smw;                       // [c][q]  64 x 132
    uint32_t* ks  = qs + 64 * APITCH;          // [c][k]  64 x 132
    uint32_t* vs  = ks + 64 * APITCH;          // [c][k]  64 x 132
    uint32_t* p_s = vs + 64 * APITCH;          // [q][k] 128 x 132 (fp32 bits)
    __shared__ float corr_s[8][16];
    __shared__ float l_s[8][16];

    int tid  = threadIdx.x;
    int warp = tid >> 5, lane = tid & 31;
    int gid = lane >> 2, tg = lane & 3;
    int wm = warp * 16;
    int qt = blockIdx.x * 128;
    int hn = blockIdx.y, b = blockIdx.z;

    const float* qg = qkv + ((size_t)b * 3 * CH + hn * HDIM) * SP;
    const float* kg = qg + (size_t)CH * SP;
    const float* vg = kg + (size_t)CH * SP;
    float* og = out + ((size_t)b * CH + hn * HDIM) * SP;

    // Load Q tile once: qs[c][q], c=0..63, q=0..127 (tf32-converted)
#pragma unroll
    for (int l = 0; l < 8; l++) {
        int slot = tid + l * 256;         // 0..2047
        int r = slot >> 5;                // c row 0..63
        int c4 = (slot & 31) * 4;         // q 0..124
        float4 v = *(const float4*)&qg[(size_t)r * SP + qt + c4];
        uint4 u;
        u.x = f2tf32(v.x); u.y = f2tf32(v.y);
        u.z = f2tf32(v.z); u.w = f2tf32(v.w);
        *(uint4*)&qs[r * APITCH + c4] = u;
    }

    // Online-softmax state: this thread owns rows wm+gid and wm+gid+8.
    float m_run0 = -INFINITY, m_run1 = -INFINITY;
    float l_run0 = 0.f, l_run1 = 0.f;

    float acc_o[4][2][4];   // [c m-tile][q n-tile][frag]
#pragma unroll
    for (int mt = 0; mt < 4; mt++)
#pragma unroll
        for (int nq = 0; nq < 2; nq++)
#pragma unroll
            for (int e = 0; e < 4; e++) acc_o[mt][nq][e] = 0.f;

    for (int kt = 0; kt < SP; kt += 128) {
        __syncthreads();   // prev tile done with ks/vs (covers Q-load on iter 0)
        // Load K and V tiles: [c][k]
#pragma unroll
        for (int l = 0; l < 8; l++) {
            int slot = tid + l * 256;
            int r = slot >> 5;
            int c4 = (slot & 31) * 4;
            float4 kv = *(const float4*)&kg[(size_t)r * SP + kt + c4];
            float4 vv = *(const float4*)&vg[(size_t)r * SP + kt + c4];
            uint4 uk, uv;
            uk.x = f2tf32(kv.x); uk.y = f2tf32(kv.y);
            uk.z = f2tf32(kv.z); uk.w = f2tf32(kv.w);
            uv.x = f2tf32(vv.x); uv.y = f2tf32(vv.y);
            uv.z = f2tf32(vv.z); uv.w = f2tf32(vv.w);
            *(uint4*)&ks[r * APITCH + c4] = uk;
            *(uint4*)&vs[r * APITCH + c4] = uv;
        }
        __syncthreads();

        // ---- Phase 1: S[q16][k128] ----
        float acc_s[16][4];
#pragma unroll
        for (int nt = 0; nt < 16; nt++)
#pragma unroll
            for (int e = 0; e < 4; e++) acc_s[nt][e] = 0.f;

#pragma unroll
        for (int kc = 0; kc < 8; kc++) {
            int c0 = kc * 8;
            uint32_t af[4];
            af[0] = qs[(c0 + tg) * APITCH + wm + gid];
            af[1] = qs[(c0 + tg) * APITCH + wm + gid + 8];
            af[2] = qs[(c0 + tg + 4) * APITCH + wm + gid];
            af[3] = qs[(c0 + tg + 4) * APITCH + wm + gid + 8];
#pragma unroll
            for (int nt = 0; nt < 16; nt++) {
                uint32_t b0 = ks[(c0 + tg) * APITCH + nt * 8 + gid];
                uint32_t b1 = ks[(c0 + tg + 4) * APITCH + nt * 8 + gid];
                MMA_TF32(acc_s[nt], af, b0, b1);
            }
        }

        // ---- Online softmax (rows fully within quad tg=0..3) ----
        float mx0 = -INFINITY, mx1 = -INFINITY;
#pragma unroll
        for (int nt = 0; nt < 16; nt++) {
            acc_s[nt][0] *= 0.125f; acc_s[nt][1] *= 0.125f;
            acc_s[nt][2] *= 0.125f; acc_s[nt][3] *= 0.125f;
            mx0 = fmaxf(mx0, fmaxf(acc_s[nt][0], acc_s[nt][1]));
            mx1 = fmaxf(mx1, fmaxf(acc_s[nt][2], acc_s[nt][3]));
        }
        mx0 = fmaxf(mx0, __shfl_xor_sync(0xffffffffu, mx0, 1));
        mx0 = fmaxf(mx0, __shfl_xor_sync(0xffffffffu, mx0, 2));
        mx1 = fmaxf(mx1, __shfl_xor_sync(0xffffffffu, mx1, 1));
        mx1 = fmaxf(mx1, __shfl_xor_sync(0xffffffffu, mx1, 2));

        float mnew0 = fmaxf(m_run0, mx0);
        float mnew1 = fmaxf(m_run1, mx1);
        float corr0 = __expf(m_run0 - mnew0);
        float corr1 = __expf(m_run1 - mnew1);

        float ps0 = 0.f, ps1 = 0.f;
#pragma unroll
        for (int nt = 0; nt < 16; nt++) {
            float p0 = __expf(acc_s[nt][0] - mnew0);
            float p1 = __expf(acc_s[nt][1] - mnew0);
            float p2 = __expf(acc_s[nt][2] - mnew1);
            float p3 = __expf(acc_s[nt][3] - mnew1);
            ps0 += p0 + p1; ps1 += p2 + p3;
            uint32_t* r0p = &p_s[(wm + gid) * APITCH + nt * 8 + 2 * tg];
            uint32_t* r1p = &p_s[(wm + gid + 8) * APITCH + nt * 8 + 2 * tg];
            r0p[0] = f2tf32(p0); r0p[1] = f2tf32(p1);
            r1p[0] = f2tf32(p2); r1p[1] = f2tf32(p3);
        }
        ps0 += __shfl_xor_sync(0xffffffffu, ps0, 1);
        ps0 += __shfl_xor_sync(0xffffffffu, ps0, 2);
        ps1 += __shfl_xor_sync(0xffffffffu, ps1, 1);
        ps1 += __shfl_xor_sync(0xffffffffu, ps1, 2);
        l_run0 = l_run0 * corr0 + ps0;
        l_run1 = l_run1 * corr1 + ps1;
        m_run0 = mnew0; m_run1 = mnew1;
        if (tg == 0) {
            corr_s[warp][gid] = corr0;
            corr_s[warp][gid + 8] = corr1;
        }
        __syncwarp();

        // Rescale O columns by corr of that q
#pragma unroll
        for (int nq = 0; nq < 2; nq++) {
            float cc0 = corr_s[warp][nq * 8 + 2 * tg];
            float cc1 = corr_s[warp][nq * 8 + 2 * tg + 1];
#pragma unroll
            for (int mt = 0; mt < 4; mt++) {
                acc_o[mt][nq][0] *= cc0; acc_o[mt][nq][1] *= cc1;
                acc_o[mt][nq][2] *= cc0; acc_o[mt][nq][3] *= cc1;
            }
        }

        // ---- Phase 2: O^T[c64][q16] += V[c][k] @ P^T[k][q] ----
#pragma unroll
        for (int kc = 0; kc < 16; kc++) {
            int kb = kc * 8;
            uint32_t bq[2][2];
#pragma unroll
            for (int nq = 0; nq < 2; nq++) {
                bq[nq][0] = p_s[(wm + nq * 8 + gid) * APITCH + kb + tg];
                bq[nq][1] = p_s[(wm + nq * 8 + gid) * APITCH + kb + tg + 4];
            }
#pragma unroll
            for (int mt = 0; mt < 4; mt++) {
                uint32_t af[4];
                af[0] = vs[(mt * 16 + gid) * APITCH + kb + tg];
                af[1] = vs[(mt * 16 + gid + 8) * APITCH + kb + tg];
                af[2] = vs[(mt * 16 + gid) * APITCH + kb + tg + 4];
                af[3] = vs[(mt * 16 + gid + 8) * APITCH + kb + tg + 4];
                MMA_TF32(acc_o[mt][0], af, bq[0][0], bq[0][1]);
                MMA_TF32(acc_o[mt][1], af, bq[1][0], bq[1][1]);
            }
        }
    }

    // Publish l per row, then epilogue
    if (tg == 0) {
        l_s[warp][gid] = l_run0;
        l_s[warp][gid + 8] = l_run1;
    }
    __syncwarp();

#pragma unroll
    for (int nq = 0; nq < 2; nq++) {
        float il0 = 1.f / l_s[warp][nq * 8 + 2 * tg];
        float il1 = 1.f / l_s[warp][nq * 8 + 2 * tg + 1];
        int s = qt + wm + nq * 8 + 2 * tg;
#pragma unroll
        for (int mt = 0; mt < 4; mt++) {
            int c0r = mt * 16 + gid;
            float2 v0, v1;
            v0.x = acc_o[mt][nq][0] * il0; v0.y = acc_o[mt][nq][1] * il1;
            v1.x = acc_o[mt][nq][2] * il0; v1.y = acc_o[mt][nq][3] * il1;
            *(float2*)&og[(size_t)c0r * SP + s]       = v0;
            *(float2*)&og[(size_t)(c0r + 8) * SP + s] = v1;
        }
    }
}

// ---------------------------------------------------------------------------
extern "C" void kernel_launch(void* const* d_in, const int* in_sizes, int n_in,
                              void* d_out, int out_size) {
    const float* x     = (const float*)d_in[0];
    const float* gamma = (const float*)d_in[1];
    const float* beta  = (const float*)d_in[2];
    const float* w_in  = (const float*)d_in[3];
    const float* b_in  = (const float*)d_in[4];
    const float* w_out = (const float*)d_in[5];
    const float* b_out = (const float*)d_in[6];
    float* out = (float*)d_out;

    float *h, *qkv, *att;
    cudaGetSymbolAddress((void**)&h,   g_h);
    cudaGetSymbolAddress((void**)&qkv, g_qkv);
    cudaGetSymbolAddress((void**)&att, g_att);

    // 1. GroupNorm
    gn_kernel<<<BATCH * NGRP, 256>>>(x, gamma, beta, h);

    // 2. QKV projection (tf32 tensor cores)
    tf32_gemm_kernel<<<dim3(SP / 128, (3 * CH) / 128, BATCH), 256>>>(
        w_in, h, b_in, nullptr, qkv, 3 * CH, SP, CH);

    // 3. Attention (tf32 tensor cores)
    cudaFuncSetAttribute(attn_tc_kernel, cudaFuncAttributeMaxDynamicSharedMemorySize,
                         ATTN_SMEM_BYTES);
    attn_tc_kernel<<<dim3(SP / 128, NHEAD, BATCH), 256, ATTN_SMEM_BYTES>>>(qkv, att);

    // 4. Output projection + bias + residual (tf32 tensor cores)
    tf32_gemm_kernel<<<dim3(SP / 128, CH / 128, BATCH), 256>>>(
        w_out, att, b_out, x, out, CH, SP, CH);
}

// round 4
// speedup vs baseline: 4.2871x; 2.4462x over previous
#include <cuda_runtime.h>
#include <math.h>
#include <stdint.h>

// Problem constants
#define BATCH 8
#define CH    512
#define SP    1024      // H*W = 32*32
#define NHEAD 8
#define HDIM  64
#define NGRP  32
#define GCH   16        // channels per group

// Scratch (device globals: allocation-free per harness rules)
__device__ float g_h[BATCH * CH * SP];
__device__ float g_qkv[BATCH * 3 * CH * SP];
__device__ float g_att[BATCH * CH * SP];

// ---------------------------------------------------------------------------
// Helpers
// ---------------------------------------------------------------------------
__device__ __forceinline__ uint32_t pk(float lo, float hi) {
    uint32_t r;
    asm("cvt.rn.bf16x2.f32 %0, %1, %2;" : "=r"(r) : "f"(hi), "f"(lo));
    return r;
}

#define MMA_BF16(d, a, b0, b1)                                              \
    asm volatile(                                                           \
        "mma.sync.aligned.m16n8k16.row.col.f32.bf16.bf16.f32 "              \
        "{%0,%1,%2,%3}, {%4,%5,%6,%7}, {%8,%9}, {%0,%1,%2,%3};"             \
        : "+f"(d[0]), "+f"(d[1]), "+f"(d[2]), "+f"(d[3])                    \
        : "r"(a[0]), "r"(a[1]), "r"(a[2]), "r"(a[3]), "r"(b0), "r"(b1))

// ---------------------------------------------------------------------------
// GroupNorm (unchanged)
// ---------------------------------------------------------------------------
__global__ void gn_kernel(const float* __restrict__ x,
                          const float* __restrict__ gamma,
                          const float* __restrict__ beta,
                          float* __restrict__ h) {
    int b = blockIdx.x >> 5;
    int g = blockIdx.x & 31;
    const float* xp = x + ((size_t)b * CH + g * GCH) * SP;
    float* hp       = h + ((size_t)b * CH + g * GCH) * SP;
    int t = threadIdx.x;

    float sum = 0.f, sq = 0.f;
    for (int i4 = t; i4 < GCH * SP / 4; i4 += 256) {
        float4 v = *(const float4*)(xp + i4 * 4);
        sum += v.x + v.y + v.z + v.w;
        sq  += v.x * v.x + v.y * v.y + v.z * v.z + v.w * v.w;
    }
    __shared__ float s1[256], s2[256];
    s1[t] = sum; s2[t] = sq;
    __syncthreads();
    for (int off = 128; off > 0; off >>= 1) {
        if (t < off) { s1[t] += s1[t + off]; s2[t] += s2[t + off]; }
        __syncthreads();
    }
    const float invN = 1.f / (GCH * SP);
    float mean = s1[0] * invN;
    float var  = s2[0] * invN - mean * mean;
    float inv  = rsqrtf(var + 1e-6f);

    for (int i4 = t; i4 < GCH * SP / 4; i4 += 256) {
        int c = i4 >> 8;
        float ga = gamma[g * GCH + c];
        float be = beta[g * GCH + c];
        float4 v = *(const float4*)(xp + i4 * 4);
        float4 o;
        o.x = (v.x - mean) * inv * ga + be;
        o.y = (v.y - mean) * inv * ga + be;
        o.z = (v.z - mean) * inv * ga + be;
        o.w = (v.w - mean) * inv * ga + be;
        *(float4*)(hp + i4 * 4) = o;
    }
}

// ---------------------------------------------------------------------------
// BF16 tensor-core GEMM: C[bz] = A[M,K] @ B[bz][K,N] + bias[M] (+ resid)
// Block 128x128, K-tile 32 (16 packed word-rows). 8 warps, warp tile 32x64,
// mma.m16n8k16. smem word layout [k2][m]/[k2][n], pitch 136 (conflict-free:
// (8*tg + gid) % 32 distinct).
// ---------------------------------------------------------------------------
#define GPITCH 136

__global__ __launch_bounds__(256) void bf16_gemm_kernel(
    const float* __restrict__ A, const float* __restrict__ Bm,
    const float* __restrict__ bias, const float* __restrict__ resid,
    float* __restrict__ C, int M, int N, int K) {
    __shared__ uint32_t As[16 * GPITCH];  // [k2][m], word = bf16(k even)|bf16(k odd)<<16
    __shared__ uint32_t Bs[16 * GPITCH];  // [k2][n]

    int tid  = threadIdx.x;
    int warp = tid >> 5, lane = tid & 31;
    int gid = lane >> 2, tg = lane & 3;
    int wm = (warp >> 1) * 32, wn = (warp & 1) * 64;
    int m0 = blockIdx.y * 128, n0 = blockIdx.x * 128;

    const float* Bp = Bm + (size_t)blockIdx.z * K * N;
    float* Cp       = C  + (size_t)blockIdx.z * M * N;
    const float* Rp = resid ? resid + (size_t)blockIdx.z * M * N : nullptr;

    float acc[2][8][4];
#pragma unroll
    for (int mt = 0; mt < 2; mt++)
#pragma unroll
        for (int nt = 0; nt < 8; nt++)
#pragma unroll
            for (int e = 0; e < 4; e++) acc[mt][nt][e] = 0.f;

    int a_row = tid >> 1;             // 0..127 (m)
    int a_k   = (tid & 1) * 16;       // k float base
    int a_k2  = (tid & 1) * 8;        // k2 word base
    const float* Ap = A + (size_t)(m0 + a_row) * K + a_k;

    float4 pa[4];
    float4 pb0[2], pb1[2];

    // Prefetch tile 0
#pragma unroll
    for (int j = 0; j < 4; j++) pa[j] = *(const float4*)(Ap + j * 4);
#pragma unroll
    for (int l = 0; l < 2; l++) {
        int slot = tid + l * 256;            // 0..511
        int rp = slot >> 5;                  // k-pair row 0..15
        int n4 = (slot & 31) * 4;
        pb0[l] = *(const float4*)&Bp[(size_t)(2 * rp) * N + n0 + n4];
        pb1[l] = *(const float4*)&Bp[(size_t)(2 * rp + 1) * N + n0 + n4];
    }

    for (int k0 = 0; k0 < K; k0 += 32) {
#pragma unroll
        for (int j = 0; j < 4; j++) {
            As[(a_k2 + 2 * j + 0) * GPITCH + a_row] = pk(pa[j].x, pa[j].y);
            As[(a_k2 + 2 * j + 1) * GPITCH + a_row] = pk(pa[j].z, pa[j].w);
        }
#pragma unroll
        for (int l = 0; l < 2; l++) {
            int slot = tid + l * 256;
            int rp = slot >> 5;
            int n4 = (slot & 31) * 4;
            uint4 u;
            u.x = pk(pb0[l].x, pb1[l].x);
            u.y = pk(pb0[l].y, pb1[l].y);
            u.z = pk(pb0[l].z, pb1[l].z);
            u.w = pk(pb0[l].w, pb1[l].w);
            *(uint4*)&Bs[rp * GPITCH + n4] = u;
        }
        __syncthreads();

        if (k0 + 32 < K) {
#pragma unroll
            for (int j = 0; j < 4; j++)
                pa[j] = *(const float4*)(Ap + k0 + 32 + j * 4);
#pragma unroll
            for (int l = 0; l < 2; l++) {
                int slot = tid + l * 256;
                int rp = slot >> 5;
                int n4 = (slot & 31) * 4;
                pb0[l] = *(const float4*)&Bp[(size_t)(k0 + 32 + 2 * rp) * N + n0 + n4];
                pb1[l] = *(const float4*)&Bp[(size_t)(k0 + 32 + 2 * rp + 1) * N + n0 + n4];
            }
        }

        // 2 k-chunks of 16 (8 word-rows each)
#pragma unroll
        for (int kk = 0; kk < 2; kk++) {
            int kb2 = kk * 8;
            uint32_t af[2][4];
#pragma unroll
            for (int mt = 0; mt < 2; mt++) {
                int mr = wm + mt * 16 + gid;
                af[mt][0] = As[(kb2 + tg) * GPITCH + mr];
                af[mt][1] = As[(kb2 + tg) * GPITCH + mr + 8];
                af[mt][2] = As[(kb2 + tg + 4) * GPITCH + mr];
                af[mt][3] = As[(kb2 + tg + 4) * GPITCH + mr + 8];
            }
#pragma unroll
            for (int nt = 0; nt < 8; nt++) {
                uint32_t b0 = Bs[(kb2 + tg) * GPITCH + wn + nt * 8 + gid];
                uint32_t b1 = Bs[(kb2 + tg + 4) * GPITCH + wn + nt * 8 + gid];
                MMA_BF16(acc[0][nt], af[0], b0, b1);
                MMA_BF16(acc[1][nt], af[1], b0, b1);
            }
        }
        __syncthreads();
    }

#pragma unroll
    for (int mt = 0; mt < 2; mt++) {
        int r0 = m0 + wm + mt * 16 + gid;
        int r1 = r0 + 8;
        float bv0 = bias[r0], bv1 = bias[r1];
#pragma unroll
        for (int nt = 0; nt < 8; nt++) {
            int col = n0 + wn + nt * 8 + tg * 2;
            float2 v0, v1;
            v0.x = acc[mt][nt][0] + bv0; v0.y = acc[mt][nt][1] + bv0;
            v1.x = acc[mt][nt][2] + bv1; v1.y = acc[mt][nt][3] + bv1;
            if (Rp) {
                float2 q0 = *(const float2*)&Rp[(size_t)r0 * N + col];
                float2 q1 = *(const float2*)&Rp[(size_t)r1 * N + col];
                v0.x += q0.x; v0.y += q0.y;
                v1.x += q1.x; v1.y += q1.y;
            }
            *(float2*)&Cp[(size_t)r0 * N + col] = v0;
            *(float2*)&Cp[(size_t)r1 * N + col] = v1;
        }
    }
}

// ---------------------------------------------------------------------------
// BF16 flash attention.
// Block = (q-tile 128, head, batch), 256 threads = 8 warps; warp owns 16 q.
// Phase 1: S = Q^T K, contraction c=64 (4 chunks of k16), m16n8k16.
// Phase 2: O^T = V @ P^T, contraction k=128 (8 chunks of k16).
// smem word layouts: qs[c2 32][q 128] p136 | ks[c2 32][k 128] p136 |
//                    vs[c 64][k2 64] p68  | p_s[q 128][k2 64] p68
// exp2-domain softmax (log2e folded into qk scale).
// ---------------------------------------------------------------------------
#define VPITCH 68
#define ATTN_WORDS (2 * 32 * GPITCH + 64 * VPITCH + 128 * VPITCH)
#define ATTN_SMEM_BYTES (ATTN_WORDS * 4)

__global__ __launch_bounds__(256, 1) void attn_bf16_kernel(
    const float* __restrict__ qkv, float* __restrict__ out) {
    extern __shared__ uint32_t smw[];
    uint32_t* qs  = smw;                          // [c2][q]
    uint32_t* ks  = qs + 32 * GPITCH;             // [c2][k]
    uint32_t* vs  = ks + 32 * GPITCH;             // [c][k2]
    uint32_t* p_s = vs + 64 * VPITCH;             // [q][k2]
    __shared__ float corr_s[8][16];
    __shared__ float l_s[8][16];

    int tid  = threadIdx.x;
    int warp = tid >> 5, lane = tid & 31;
    int gid = lane >> 2, tg = lane & 3;
    int wm = warp * 16;
    int qt = blockIdx.x * 128;
    int hn = blockIdx.y, b = blockIdx.z;

    const float* qg = qkv + ((size_t)b * 3 * CH + hn * HDIM) * SP;
    const float* kg = qg + (size_t)CH * SP;
    const float* vg = kg + (size_t)CH * SP;
    float* og = out + ((size_t)b * CH + hn * HDIM) * SP;

    const float SC = 0.125f * 1.44269504088896f;  // (1/sqrt(64)) * log2(e)

    // Load Q tile once: qs[c2][q], packed c pairs
#pragma unroll
    for (int l = 0; l < 4; l++) {
        int slot = tid + l * 256;        // 0..1023
        int r = slot >> 5;               // c2 0..31
        int q4 = (slot & 31) * 4;
        float4 v0 = *(const float4*)&qg[(size_t)(2 * r) * SP + qt + q4];
        float4 v1 = *(const float4*)&qg[(size_t)(2 * r + 1) * SP + qt + q4];
        uint4 u;
        u.x = pk(v0.x, v1.x); u.y = pk(v0.y, v1.y);
        u.z = pk(v0.z, v1.z); u.w = pk(v0.w, v1.w);
        *(uint4*)&qs[r * GPITCH + q4] = u;
    }

    float m_run0 = -INFINITY, m_run1 = -INFINITY;
    float l_run0 = 0.f, l_run1 = 0.f;

    float acc_o[4][2][4];
#pragma unroll
    for (int mt = 0; mt < 4; mt++)
#pragma unroll
        for (int nq = 0; nq < 2; nq++)
#pragma unroll
            for (int e = 0; e < 4; e++) acc_o[mt][nq][e] = 0.f;

    for (int kt = 0; kt < SP; kt += 128) {
        __syncthreads();   // prev tile done with ks/vs (covers Q-load on iter 0)

        // K tile: ks[c2][k] packed c pairs
#pragma unroll
        for (int l = 0; l < 4; l++) {
            int slot = tid + l * 256;
            int r = slot >> 5;
            int k4 = (slot & 31) * 4;
            float4 v0 = *(const float4*)&kg[(size_t)(2 * r) * SP + kt + k4];
            float4 v1 = *(const float4*)&kg[(size_t)(2 * r + 1) * SP + kt + k4];
            uint4 u;
            u.x = pk(v0.x, v1.x); u.y = pk(v0.y, v1.y);
            u.z = pk(v0.z, v1.z); u.w = pk(v0.w, v1.w);
            *(uint4*)&ks[r * GPITCH + k4] = u;
        }
        // V tile: vs[c][k2] packed k pairs
#pragma unroll
        for (int l = 0; l < 4; l++) {
            int slot = tid + l * 256;
            int c = slot >> 4;            // 0..63
            int k8 = (slot & 15) * 8;
            float4 a4 = *(const float4*)&vg[(size_t)c * SP + kt + k8];
            float4 b4 = *(const float4*)&vg[(size_t)c * SP + kt + k8 + 4];
            uint4 u;
            u.x = pk(a4.x, a4.y); u.y = pk(a4.z, a4.w);
            u.z = pk(b4.x, b4.y); u.w = pk(b4.z, b4.w);
            *(uint4*)&vs[c * VPITCH + k8 / 2] = u;
        }
        __syncthreads();

        // ---- Phase 1: S[q16][k128] ----
        float acc_s[16][4];
#pragma unroll
        for (int nt = 0; nt < 16; nt++)
#pragma unroll
            for (int e = 0; e < 4; e++) acc_s[nt][e] = 0.f;

#pragma unroll
        for (int cc = 0; cc < 4; cc++) {
            int cb2 = cc * 8;
            uint32_t af[4];
            af[0] = qs[(cb2 + tg) * GPITCH + wm + gid];
            af[1] = qs[(cb2 + tg) * GPITCH + wm + gid + 8];
            af[2] = qs[(cb2 + tg + 4) * GPITCH + wm + gid];
            af[3] = qs[(cb2 + tg + 4) * GPITCH + wm + gid + 8];
#pragma unroll
            for (int nt = 0; nt < 16; nt++) {
                uint32_t b0 = ks[(cb2 + tg) * GPITCH + nt * 8 + gid];
                uint32_t b1 = ks[(cb2 + tg + 4) * GPITCH + nt * 8 + gid];
                MMA_BF16(acc_s[nt], af, b0, b1);
            }
        }

        // ---- Online softmax (exp2 domain), rows within quad ----
        float mx0 = -INFINITY, mx1 = -INFINITY;
#pragma unroll
        for (int nt = 0; nt < 16; nt++) {
            acc_s[nt][0] *= SC; acc_s[nt][1] *= SC;
            acc_s[nt][2] *= SC; acc_s[nt][3] *= SC;
            mx0 = fmaxf(mx0, fmaxf(acc_s[nt][0], acc_s[nt][1]));
            mx1 = fmaxf(mx1, fmaxf(acc_s[nt][2], acc_s[nt][3]));
        }
        mx0 = fmaxf(mx0, __shfl_xor_sync(0xffffffffu, mx0, 1));
        mx0 = fmaxf(mx0, __shfl_xor_sync(0xffffffffu, mx0, 2));
        mx1 = fmaxf(mx1, __shfl_xor_sync(0xffffffffu, mx1, 1));
        mx1 = fmaxf(mx1, __shfl_xor_sync(0xffffffffu, mx1, 2));

        float mnew0 = fmaxf(m_run0, mx0);
        float mnew1 = fmaxf(m_run1, mx1);
        float corr0 = exp2f(m_run0 - mnew0);
        float corr1 = exp2f(m_run1 - mnew1);

        float ps0 = 0.f, ps1 = 0.f;
#pragma unroll
        for (int nt = 0; nt < 16; nt++) {
            float p0 = exp2f(acc_s[nt][0] - mnew0);
            float p1 = exp2f(acc_s[nt][1] - mnew0);
            float p2 = exp2f(acc_s[nt][2] - mnew1);
            float p3 = exp2f(acc_s[nt][3] - mnew1);
            ps0 += p0 + p1; ps1 += p2 + p3;
            p_s[(wm + gid) * VPITCH + nt * 4 + tg]     = pk(p0, p1);
            p_s[(wm + gid + 8) * VPITCH + nt * 4 + tg] = pk(p2, p3);
        }
        ps0 += __shfl_xor_sync(0xffffffffu, ps0, 1);
        ps0 += __shfl_xor_sync(0xffffffffu, ps0, 2);
        ps1 += __shfl_xor_sync(0xffffffffu, ps1, 1);
        ps1 += __shfl_xor_sync(0xffffffffu, ps1, 2);
        l_run0 = l_run0 * corr0 + ps0;
        l_run1 = l_run1 * corr1 + ps1;
        m_run0 = mnew0; m_run1 = mnew1;
        if (tg == 0) {
            corr_s[warp][gid] = corr0;
            corr_s[warp][gid + 8] = corr1;
        }
        __syncwarp();

        // Rescale O columns by corr of that q
#pragma unroll
        for (int nq = 0; nq < 2; nq++) {
            float cc0 = corr_s[warp][nq * 8 + 2 * tg];
            float cc1 = corr_s[warp][nq * 8 + 2 * tg + 1];
#pragma unroll
            for (int mt = 0; mt < 4; mt++) {
                acc_o[mt][nq][0] *= cc0; acc_o[mt][nq][1] *= cc1;
                acc_o[mt][nq][2] *= cc0; acc_o[mt][nq][3] *= cc1;
            }
        }

        // ---- Phase 2: O^T[c64][q16] += V @ P^T, k=128 in 8 chunks ----
#pragma unroll
        for (int kc = 0; kc < 8; kc++) {
            int kb2 = kc * 8;
            uint32_t bq[2][2];
#pragma unroll
            for (int nq = 0; nq < 2; nq++) {
                bq[nq][0] = p_s[(wm + nq * 8 + gid) * VPITCH + kb2 + tg];
                bq[nq][1] = p_s[(wm + nq * 8 + gid) * VPITCH + kb2 + tg + 4];
            }
#pragma unroll
            for (int mt = 0; mt < 4; mt++) {
                uint32_t af[4];
                af[0] = vs[(mt * 16 + gid) * VPITCH + kb2 + tg];
                af[1] = vs[(mt * 16 + gid + 8) * VPITCH + kb2 + tg];
                af[2] = vs[(mt * 16 + gid) * VPITCH + kb2 + tg + 4];
                af[3] = vs[(mt * 16 + gid + 8) * VPITCH + kb2 + tg + 4];
                MMA_BF16(acc_o[mt][0], af, bq[0][0], bq[0][1]);
                MMA_BF16(acc_o[mt][1], af, bq[1][0], bq[1][1]);
            }
        }
    }

    if (tg == 0) {
        l_s[warp][gid] = l_run0;
        l_s[warp][gid + 8] = l_run1;
    }
    __syncwarp();

#pragma unroll
    for (int nq = 0; nq < 2; nq++) {
        float il0 = 1.f / l_s[warp][nq * 8 + 2 * tg];
        float il1 = 1.f / l_s[warp][nq * 8 + 2 * tg + 1];
        int s = qt + wm + nq * 8 + 2 * tg;
#pragma unroll
        for (int mt = 0; mt < 4; mt++) {
            int c0r = mt * 16 + gid;
            float2 v0, v1;
            v0.x = acc_o[mt][nq][0] * il0; v0.y = acc_o[mt][nq][1] * il1;
            v1.x = acc_o[mt][nq][2] * il0; v1.y = acc_o[mt][nq][3] * il1;
            *(float2*)&og[(size_t)c0r * SP + s]       = v0;
            *(float2*)&og[(size_t)(c0r + 8) * SP + s] = v1;
        }
    }
}

// ---------------------------------------------------------------------------
extern "C" void kernel_launch(void* const* d_in, const int* in_sizes, int n_in,
                              void* d_out, int out_size) {
    const float* x     = (const float*)d_in[0];
    const float* gamma = (const float*)d_in[1];
    const float* beta  = (const float*)d_in[2];
    const float* w_in  = (const float*)d_in[3];
    const float* b_in  = (const float*)d_in[4];
    const float* w_out = (const float*)d_in[5];
    const float* b_out = (const float*)d_in[6];
    float* out = (float*)d_out;

    float *h, *qkv, *att;
    cudaGetSymbolAddress((void**)&h,   g_h);
    cudaGetSymbolAddress((void**)&qkv, g_qkv);
    cudaGetSymbolAddress((void**)&att, g_att);

    // 1. GroupNorm
    gn_kernel<<<BATCH * NGRP, 256>>>(x, gamma, beta, h);

    // 2. QKV projection (bf16 tensor cores)
    bf16_gemm_kernel<<<dim3(SP / 128, (3 * CH) / 128, BATCH), 256>>>(
        w_in, h, b_in, nullptr, qkv, 3 * CH, SP, CH);

    // 3. Attention (bf16 tensor cores)
    cudaFuncSetAttribute(attn_bf16_kernel, cudaFuncAttributeMaxDynamicSharedMemorySize,
                         ATTN_SMEM_BYTES);
    attn_bf16_kernel<<<dim3(SP / 128, NHEAD, BATCH), 256, ATTN_SMEM_BYTES>>>(qkv, att);

    // 4. Output projection + bias + residual (bf16 tensor cores)
    bf16_gemm_kernel<<<dim3(SP / 128, CH / 128, BATCH), 256>>>(
        w_out, att, b_out, x, out, CH, SP, CH);
}

// round 7
// speedup vs baseline: 4.3993x; 1.0262x over previous
#include <cuda_runtime.h>
#include <cuda_bf16.h>
#include <math.h>
#include <stdint.h>

// Problem constants
#define BATCH 8
#define CH    512
#define SP    1024      // H*W = 32*32
#define NHEAD 8
#define HDIM  64
#define NGRP  32
#define GCH   16        // channels per group

// Scratch (device globals: allocation-free per harness rules)
__device__ __nv_bfloat16 g_qkv[BATCH * 3 * CH * SP];  // qkv (bf16, 25 MB)
__device__ __nv_bfloat16 g_att[BATCH * CH * SP];      // attention out (bf16)
__device__ float g_scale[BATCH * CH];                 // fused GN scale
__device__ float g_shift[BATCH * CH];                 // fused GN shift

// ---------------------------------------------------------------------------
// Helpers
// ---------------------------------------------------------------------------
__device__ __forceinline__ uint32_t pk(float lo, float hi) {
    uint32_t r;
    asm("cvt.rn.bf16x2.f32 %0, %1, %2;" : "=r"(r) : "f"(hi), "f"(lo));
    return r;
}

#define MMA_BF16(d, a, b0, b1)                                              \
    asm volatile(                                                           \
        "mma.sync.aligned.m16n8k16.row.col.f32.bf16.bf16.f32 "              \
        "{%0,%1,%2,%3}, {%4,%5,%6,%7}, {%8,%9}, {%0,%1,%2,%3};"             \
        : "+f"(d[0]), "+f"(d[1]), "+f"(d[2]), "+f"(d[3])                    \
        : "r"(a[0]), "r"(a[1]), "r"(a[2]), "r"(a[3]), "r"(b0), "r"(b1))

// ---------------------------------------------------------------------------
// GroupNorm stats: one block per (batch, group); emits scale/shift per chan.
// ---------------------------------------------------------------------------
__global__ void gn_stats_kernel(const float* __restrict__ x,
                                const float* __restrict__ gamma,
                                const float* __restrict__ beta,
                                float* __restrict__ scale,
                                float* __restrict__ shift) {
    int b = blockIdx.x >> 5;
    int g = blockIdx.x & 31;
    const float* xp = x + ((size_t)b * CH + g * GCH) * SP;
    int t = threadIdx.x;

    float sum = 0.f, sq = 0.f;
    for (int i4 = t; i4 < GCH * SP / 4; i4 += 256) {
        float4 v = *(const float4*)(xp + i4 * 4);
        sum += v.x + v.y + v.z + v.w;
        sq  += v.x * v.x + v.y * v.y + v.z * v.z + v.w * v.w;
    }
    __shared__ float s1[256], s2[256];
    s1[t] = sum; s2[t] = sq;
    __syncthreads();
    for (int off = 128; off > 0; off >>= 1) {
        if (t < off) { s1[t] += s1[t + off]; s2[t] += s2[t + off]; }
        __syncthreads();
    }
    const float invN = 1.f / (GCH * SP);
    float mean = s1[0] * invN;
    float var  = s2[0] * invN - mean * mean;
    float inv  = rsqrtf(var + 1e-6f);

    if (t < GCH) {
        int c = g * GCH + t;
        float sc = inv * gamma[c];
        scale[b * CH + c] = sc;
        shift[b * CH + c] = beta[c] - mean * sc;
    }
}

// ---------------------------------------------------------------------------
// QKV GEMM: C_bf16[bz] = w_in[M,K] @ (x[bz]*scale+shift)[K,N] + bias[M]
// Block 128x128, K-tile 32. GroupNorm fused into the B-tile load.
// ---------------------------------------------------------------------------
#define GPITCH 136

__global__ __launch_bounds__(256) void gemm_qkv_kernel(
    const float* __restrict__ A, const float* __restrict__ X,
    const float* __restrict__ scale_g, const float* __restrict__ shift_g,
    const float* __restrict__ bias, __nv_bfloat16* __restrict__ Cb,
    int M, int N, int K) {
    __shared__ uint32_t As[16 * GPITCH];  // [k2][m]
    __shared__ uint32_t Bs[16 * GPITCH];  // [k2][n]

    int tid  = threadIdx.x;
    int warp = tid >> 5, lane = tid & 31;
    int gid = lane >> 2, tg = lane & 3;
    int wm = (warp >> 1) * 32, wn = (warp & 1) * 64;
    int m0 = blockIdx.y * 128, n0 = blockIdx.x * 128;
    int z  = blockIdx.z;

    const float* Bp = X + (size_t)z * K * N;
    const float* scp = scale_g + z * CH;
    const float* shp = shift_g + z * CH;
    __nv_bfloat16* Cp = Cb + (size_t)z * M * N;

    float acc[2][8][4];
#pragma unroll
    for (int mt = 0; mt < 2; mt++)
#pragma unroll
        for (int nt = 0; nt < 8; nt++)
#pragma unroll
            for (int e = 0; e < 4; e++) acc[mt][nt][e] = 0.f;

    int a_row = tid >> 1;
    int a_k2  = (tid & 1) * 8;
    const float* Ap = A + (size_t)(m0 + a_row) * K + (tid & 1) * 16;

    float4 pa[4];
    float4 pb0[2], pb1[2];
    float ps0[2], ph0[2], ps1[2], ph1[2];

#pragma unroll
    for (int j = 0; j < 4; j++) pa[j] = *(const float4*)(Ap + j * 4);
#pragma unroll
    for (int l = 0; l < 2; l++) {
        int slot = tid + l * 256;
        int rp = slot >> 5, n4 = (slot & 31) * 4;
        pb0[l] = *(const float4*)&Bp[(size_t)(2 * rp) * N + n0 + n4];
        pb1[l] = *(const float4*)&Bp[(size_t)(2 * rp + 1) * N + n0 + n4];
        ps0[l] = scp[2 * rp];     ph0[l] = shp[2 * rp];
        ps1[l] = scp[2 * rp + 1]; ph1[l] = shp[2 * rp + 1];
    }

    for (int k0 = 0; k0 < K; k0 += 32) {
#pragma unroll
        for (int j = 0; j < 4; j++) {
            As[(a_k2 + 2 * j + 0) * GPITCH + a_row] = pk(pa[j].x, pa[j].y);
            As[(a_k2 + 2 * j + 1) * GPITCH + a_row] = pk(pa[j].z, pa[j].w);
        }
#pragma unroll
        for (int l = 0; l < 2; l++) {
            int slot = tid + l * 256;
            int rp = slot >> 5, n4 = (slot & 31) * 4;
            uint4 u;
            u.x = pk(pb0[l].x * ps0[l] + ph0[l], pb1[l].x * ps1[l] + ph1[l]);
            u.y = pk(pb0[l].y * ps0[l] + ph0[l], pb1[l].y * ps1[l] + ph1[l]);
            u.z = pk(pb0[l].z * ps0[l] + ph0[l], pb1[l].z * ps1[l] + ph1[l]);
            u.w = pk(pb0[l].w * ps0[l] + ph0[l], pb1[l].w * ps1[l] + ph1[l]);
            *(uint4*)&Bs[rp * GPITCH + n4] = u;
        }
        __syncthreads();

        if (k0 + 32 < K) {
#pragma unroll
            for (int j = 0; j < 4; j++)
                pa[j] = *(const float4*)(Ap + k0 + 32 + j * 4);
#pragma unroll
            for (int l = 0; l < 2; l++) {
                int slot = tid + l * 256;
                int rp = slot >> 5, n4 = (slot & 31) * 4;
                int row = k0 + 32 + 2 * rp;
                pb0[l] = *(const float4*)&Bp[(size_t)row * N + n0 + n4];
                pb1[l] = *(const float4*)&Bp[(size_t)(row + 1) * N + n0 + n4];
                ps0[l] = scp[row];     ph0[l] = shp[row];
                ps1[l] = scp[row + 1]; ph1[l] = shp[row + 1];
            }
        }

#pragma unroll
        for (int kk = 0; kk < 2; kk++) {
            int kb2 = kk * 8;
            uint32_t af[2][4];
#pragma unroll
            for (int mt = 0; mt < 2; mt++) {
                int mr = wm + mt * 16 + gid;
                af[mt][0] = As[(kb2 + tg) * GPITCH + mr];
                af[mt][1] = As[(kb2 + tg) * GPITCH + mr + 8];
                af[mt][2] = As[(kb2 + tg + 4) * GPITCH + mr];
                af[mt][3] = As[(kb2 + tg + 4) * GPITCH + mr + 8];
            }
#pragma unroll
            for (int nt = 0; nt < 8; nt++) {
                uint32_t b0 = Bs[(kb2 + tg) * GPITCH + wn + nt * 8 + gid];
                uint32_t b1 = Bs[(kb2 + tg + 4) * GPITCH + wn + nt * 8 + gid];
                MMA_BF16(acc[0][nt], af[0], b0, b1);
                MMA_BF16(acc[1][nt], af[1], b0, b1);
            }
        }
        __syncthreads();
    }

#pragma unroll
    for (int mt = 0; mt < 2; mt++) {
        int r0 = m0 + wm + mt * 16 + gid;
        int r1 = r0 + 8;
        float bv0 = bias[r0], bv1 = bias[r1];
#pragma unroll
        for (int nt = 0; nt < 8; nt++) {
            int col = n0 + wn + nt * 8 + tg * 2;
            ((uint32_t*)Cp)[((size_t)r0 * N + col) >> 1] =
                pk(acc[mt][nt][0] + bv0, acc[mt][nt][1] + bv0);
            ((uint32_t*)Cp)[((size_t)r1 * N + col) >> 1] =
                pk(acc[mt][nt][2] + bv1, acc[mt][nt][3] + bv1);
        }
    }
}

// ---------------------------------------------------------------------------
// Out-proj GEMM: C[bz] = w_out[M,K] @ att_bf16[bz][K,N] + bias + resid(x)
// B tile is already bf16: c-pair packing via PRMT only.  (K = CH = 512)
// ---------------------------------------------------------------------------
__global__ __launch_bounds__(256) void gemm_out_kernel(
    const float* __restrict__ A, const __nv_bfloat16* __restrict__ Bm,
    const float* __restrict__ bias, const float* __restrict__ resid,
    float* __restrict__ C, int M, int N, int K) {
    __shared__ uint32_t As[16 * GPITCH];
    __shared__ uint32_t Bs[16 * GPITCH];

    int tid  = threadIdx.x;
    int warp = tid >> 5, lane = tid & 31;
    int gid = lane >> 2, tg = lane & 3;
    int wm = (warp >> 1) * 32, wn = (warp & 1) * 64;
    int m0 = blockIdx.y * 128, n0 = blockIdx.x * 128;

    const __nv_bfloat16* Bp = Bm + (size_t)blockIdx.z * K * N;
    float* Cp       = C + (size_t)blockIdx.z * M * N;
    const float* Rp = resid + (size_t)blockIdx.z * M * N;

    float acc[2][8][4];
#pragma unroll
    for (int mt = 0; mt < 2; mt++)
#pragma unroll
        for (int nt = 0; nt < 8; nt++)
#pragma unroll
            for (int e = 0; e < 4; e++) acc[mt][nt][e] = 0.f;

    int a_row = tid >> 1;
    int a_k2  = (tid & 1) * 8;
    const float* Ap = A + (size_t)(m0 + a_row) * K + (tid & 1) * 16;

    float4 pa[4];
    uint2 pb0[2], pb1[2];

#pragma unroll
    for (int j = 0; j < 4; j++) pa[j] = *(const float4*)(Ap + j * 4);
#pragma unroll
    for (int l = 0; l < 2; l++) {
        int slot = tid + l * 256;
        int rp = slot >> 5, n4 = (slot & 31) * 4;
        const uint32_t* r0w = (const uint32_t*)(Bp + (size_t)(2 * rp) * N);
        const uint32_t* r1w = (const uint32_t*)(Bp + (size_t)(2 * rp + 1) * N);
        pb0[l] = *(const uint2*)&r0w[(n0 + n4) >> 1];
        pb1[l] = *(const uint2*)&r1w[(n0 + n4) >> 1];
    }

    for (int k0 = 0; k0 < K; k0 += 32) {
#pragma unroll
        for (int j = 0; j < 4; j++) {
            As[(a_k2 + 2 * j + 0) * GPITCH + a_row] = pk(pa[j].x, pa[j].y);
            As[(a_k2 + 2 * j + 1) * GPITCH + a_row] = pk(pa[j].z, pa[j].w);
        }
#pragma unroll
        for (int l = 0; l < 2; l++) {
            int slot = tid + l * 256;
            int rp = slot >> 5, n4 = (slot & 31) * 4;
            uint4 u;
            u.x = __byte_perm(pb0[l].x, pb1[l].x, 0x5410);
            u.y = __byte_perm(pb0[l].x, pb1[l].x, 0x7632);
            u.z = __byte_perm(pb0[l].y, pb1[l].y, 0x5410);
            u.w = __byte_perm(pb0[l].y, pb1[l].y, 0x7632);
            *(uint4*)&Bs[rp * GPITCH + n4] = u;
        }
        __syncthreads();

        if (k0 + 32 < K) {
#pragma unroll
            for (int j = 0; j < 4; j++)
                pa[j] = *(const float4*)(Ap + k0 + 32 + j * 4);
#pragma unroll
            for (int l = 0; l < 2; l++) {
                int slot = tid + l * 256;
                int rp = slot >> 5, n4 = (slot & 31) * 4;
                const uint32_t* r0w =
                    (const uint32_t*)(Bp + (size_t)(k0 + 32 + 2 * rp) * N);
                const uint32_t* r1w =
                    (const uint32_t*)(Bp + (size_t)(k0 + 32 + 2 * rp + 1) * N);
                pb0[l] = *(const uint2*)&r0w[(n0 + n4) >> 1];
                pb1[l] = *(const uint2*)&r1w[(n0 + n4) >> 1];
            }
        }

#pragma unroll
        for (int kk = 0; kk < 2; kk++) {
            int kb2 = kk * 8;
            uint32_t af[2][4];
#pragma unroll
            for (int mt = 0; mt < 2; mt++) {
                int mr = wm + mt * 16 + gid;
                af[mt][0] = As[(kb2 + tg) * GPITCH + mr];
                af[mt][1] = As[(kb2 + tg) * GPITCH + mr + 8];
                af[mt][2] = As[(kb2 + tg + 4) * GPITCH + mr];
                af[mt][3] = As[(kb2 + tg + 4) * GPITCH + mr + 8];
            }
#pragma unroll
            for (int nt = 0; nt < 8; nt++) {
                uint32_t b0 = Bs[(kb2 + tg) * GPITCH + wn + nt * 8 + gid];
                uint32_t b1 = Bs[(kb2 + tg + 4) * GPITCH + wn + nt * 8 + gid];
                MMA_BF16(acc[0][nt], af[0], b0, b1);
                MMA_BF16(acc[1][nt], af[1], b0, b1);
            }
        }
        __syncthreads();
    }

#pragma unroll
    for (int mt = 0; mt < 2; mt++) {
        int r0 = m0 + wm + mt * 16 + gid;
        int r1 = r0 + 8;
        float bv0 = bias[r0], bv1 = bias[r1];
#pragma unroll
        for (int nt = 0; nt < 8; nt++) {
            int col = n0 + wn + nt * 8 + tg * 2;
            float2 v0, v1;
            v0.x = acc[mt][nt][0] + bv0; v0.y = acc[mt][nt][1] + bv0;
            v1.x = acc[mt][nt][2] + bv1; v1.y = acc[mt][nt][3] + bv1;
            float2 q0 = *(const float2*)&Rp[(size_t)r0 * N + col];
            float2 q1 = *(const float2*)&Rp[(size_t)r1 * N + col];
            v0.x += q0.x; v0.y += q0.y;
            v1.x += q1.x; v1.y += q1.y;
            *(float2*)&Cp[(size_t)r0 * N + col] = v0;
            *(float2*)&Cp[(size_t)r1 * N + col] = v1;
        }
    }
}

// ---------------------------------------------------------------------------
// BF16 flash attention (qkv already bf16 in gmem; out written bf16).
// Loads: V = straight uint4 copy; Q/K = c-pair interleave via PRMT.
// ---------------------------------------------------------------------------
#define VPITCH 68
#define ATTN_WORDS (2 * 32 * GPITCH + 64 * VPITCH + 128 * VPITCH)
#define ATTN_SMEM_BYTES (ATTN_WORDS * 4)

__global__ __launch_bounds__(256) void attn_bf16_kernel(
    const __nv_bfloat16* __restrict__ qkv, __nv_bfloat16* __restrict__ out) {
    extern __shared__ uint32_t smw[];
    uint32_t* qs  = smw;                          // [c2][q]
    uint32_t* ks  = qs + 32 * GPITCH;             // [c2][k]
    uint32_t* vs  = ks + 32 * GPITCH;             // [c][k2]
    uint32_t* p_s = vs + 64 * VPITCH;             // [q][k2]
    __shared__ float corr_s[8][16];
    __shared__ float l_s[8][16];

    int tid  = threadIdx.x;
    int warp = tid >> 5, lane = tid & 31;
    int gid = lane >> 2, tg = lane & 3;
    int wm = warp * 16;
    int qt = blockIdx.x * 128;
    int hn = blockIdx.y, b = blockIdx.z;

    const __nv_bfloat16* qg = qkv + ((size_t)b * 3 * CH + hn * HDIM) * SP;
    const __nv_bfloat16* kg = qg + (size_t)CH * SP;
    const __nv_bfloat16* vg = kg + (size_t)CH * SP;
    __nv_bfloat16* og = out + ((size_t)b * CH + hn * HDIM) * SP;

    const float SC = 0.125f * 1.44269504088896f;  // (1/sqrt(64)) * log2(e)

    // Load Q tile: qs[c2][q] via PRMT interleave
#pragma unroll
    for (int l = 0; l < 4; l++) {
        int slot = tid + l * 256;        // 0..1023
        int r = slot >> 5;               // c2 0..31
        int q4 = (slot & 31) * 4;
        const uint32_t* r0w = (const uint32_t*)(qg + (size_t)(2 * r) * SP + qt);
        const uint32_t* r1w = (const uint32_t*)(qg + (size_t)(2 * r + 1) * SP + qt);
        uint2 u0 = *(const uint2*)&r0w[q4 >> 1];
        uint2 u1 = *(const uint2*)&r1w[q4 >> 1];
        uint4 u;
        u.x = __byte_perm(u0.x, u1.x, 0x5410);
        u.y = __byte_perm(u0.x, u1.x, 0x7632);
        u.z = __byte_perm(u0.y, u1.y, 0x5410);
        u.w = __byte_perm(u0.y, u1.y, 0x7632);
        *(uint4*)&qs[r * GPITCH + q4] = u;
    }

    float m_run0 = -INFINITY, m_run1 = -INFINITY;
    float l_run0 = 0.f, l_run1 = 0.f;

    float acc_o[4][2][4];
#pragma unroll
    for (int mt = 0; mt < 4; mt++)
#pragma unroll
        for (int nq = 0; nq < 2; nq++)
#pragma unroll
            for (int e = 0; e < 4; e++) acc_o[mt][nq][e] = 0.f;

    for (int kt = 0; kt < SP; kt += 128) {
        __syncthreads();

        // K tile: ks[c2][k] via PRMT
#pragma unroll
        for (int l = 0; l < 4; l++) {
            int slot = tid + l * 256;
            int r = slot >> 5;
            int k4 = (slot & 31) * 4;
            const uint32_t* r0w = (const uint32_t*)(kg + (size_t)(2 * r) * SP + kt);
            const uint32_t* r1w = (const uint32_t*)(kg + (size_t)(2 * r + 1) * SP + kt);
            uint2 u0 = *(const uint2*)&r0w[k4 >> 1];
            uint2 u1 = *(const uint2*)&r1w[k4 >> 1];
            uint4 u;
            u.x = __byte_perm(u0.x, u1.x, 0x5410);
            u.y = __byte_perm(u0.x, u1.x, 0x7632);
            u.z = __byte_perm(u0.y, u1.y, 0x5410);
            u.w = __byte_perm(u0.y, u1.y, 0x7632);
            *(uint4*)&ks[r * GPITCH + k4] = u;
        }
        // V tile: vs[c][k2] straight copy (k-pairs native)
#pragma unroll
        for (int l = 0; l < 4; l++) {
            int slot = tid + l * 256;
            int c = slot >> 4;            // 0..63
            int k8 = (slot & 15) * 8;
            const uint32_t* vw = (const uint32_t*)(vg + (size_t)c * SP + kt);
            *(uint4*)&vs[c * VPITCH + (k8 >> 1)] = *(const uint4*)&vw[k8 >> 1];
        }
        __syncthreads();

        // ---- Phase 1: S[q16][k128] ----
        float acc_s[16][4];
#pragma unroll
        for (int nt = 0; nt < 16; nt++)
#pragma unroll
            for (int e = 0; e < 4; e++) acc_s[nt][e] = 0.f;

#pragma unroll
        for (int cc = 0; cc < 4; cc++) {
            int cb2 = cc * 8;
            uint32_t af[4];
            af[0] = qs[(cb2 + tg) * GPITCH + wm + gid];
            af[1] = qs[(cb2 + tg) * GPITCH + wm + gid + 8];
            af[2] = qs[(cb2 + tg + 4) * GPITCH + wm + gid];
            af[3] = qs[(cb2 + tg + 4) * GPITCH + wm + gid + 8];
#pragma unroll
            for (int nt = 0; nt < 16; nt++) {
                uint32_t b0 = ks[(cb2 + tg) * GPITCH + nt * 8 + gid];
                uint32_t b1 = ks[(cb2 + tg + 4) * GPITCH + nt * 8 + gid];
                MMA_BF16(acc_s[nt], af, b0, b1);
            }
        }

        // ---- Online softmax (exp2 domain) ----
        float mx0 = -INFINITY, mx1 = -INFINITY;
#pragma unroll
        for (int nt = 0; nt < 16; nt++) {
            acc_s[nt][0] *= SC; acc_s[nt][1] *= SC;
            acc_s[nt][2] *= SC; acc_s[nt][3] *= SC;
            mx0 = fmaxf(mx0, fmaxf(acc_s[nt][0], acc_s[nt][1]));
            mx1 = fmaxf(mx1, fmaxf(acc_s[nt][2], acc_s[nt][3]));
        }
        mx0 = fmaxf(mx0, __shfl_xor_sync(0xffffffffu, mx0, 1));
        mx0 = fmaxf(mx0, __shfl_xor_sync(0xffffffffu, mx0, 2));
        mx1 = fmaxf(mx1, __shfl_xor_sync(0xffffffffu, mx1, 1));
        mx1 = fmaxf(mx1, __shfl_xor_sync(0xffffffffu, mx1, 2));

        float mnew0 = fmaxf(m_run0, mx0);
        float mnew1 = fmaxf(m_run1, mx1);
        float corr0 = exp2f(m_run0 - mnew0);
        float corr1 = exp2f(m_run1 - mnew1);

        float ps0 = 0.f, ps1 = 0.f;
#pragma unroll
        for (int nt = 0; nt < 16; nt++) {
            float p0 = exp2f(acc_s[nt][0] - mnew0);
            float p1 = exp2f(acc_s[nt][1] - mnew0);
            float p2 = exp2f(acc_s[nt][2] - mnew1);
            float p3 = exp2f(acc_s[nt][3] - mnew1);
            ps0 += p0 + p1; ps1 += p2 + p3;
            p_s[(wm + gid) * VPITCH + nt * 4 + tg]     = pk(p0, p1);
            p_s[(wm + gid + 8) * VPITCH + nt * 4 + tg] = pk(p2, p3);
        }
        ps0 += __shfl_xor_sync(0xffffffffu, ps0, 1);
        ps0 += __shfl_xor_sync(0xffffffffu, ps0, 2);
        ps1 += __shfl_xor_sync(0xffffffffu, ps1, 1);
        ps1 += __shfl_xor_sync(0xffffffffu, ps1, 2);
        l_run0 = l_run0 * corr0 + ps0;
        l_run1 = l_run1 * corr1 + ps1;
        m_run0 = mnew0; m_run1 = mnew1;
        if (tg == 0) {
            corr_s[warp][gid] = corr0;
            corr_s[warp][gid + 8] = corr1;
        }
        __syncwarp();

#pragma unroll
        for (int nq = 0; nq < 2; nq++) {
            float cc0 = corr_s[warp][nq * 8 + 2 * tg];
            float cc1 = corr_s[warp][nq * 8 + 2 * tg + 1];
#pragma unroll
            for (int mt = 0; mt < 4; mt++) {
                acc_o[mt][nq][0] *= cc0; acc_o[mt][nq][1] *= cc1;
                acc_o[mt][nq][2] *= cc0; acc_o[mt][nq][3] *= cc1;
            }
        }

        // ---- Phase 2: O^T[c64][q16] += V @ P^T ----
#pragma unroll
        for (int kc = 0; kc < 8; kc++) {
            int kb2 = kc * 8;
            uint32_t bq[2][2];
#pragma unroll
            for (int nq = 0; nq < 2; nq++) {
                bq[nq][0] = p_s[(wm + nq * 8 + gid) * VPITCH + kb2 + tg];
                bq[nq][1] = p_s[(wm + nq * 8 + gid) * VPITCH + kb2 + tg + 4];
            }
#pragma unroll
            for (int mt = 0; mt < 4; mt++) {
                uint32_t af[4];
                af[0] = vs[(mt * 16 + gid) * VPITCH + kb2 + tg];
                af[1] = vs[(mt * 16 + gid + 8) * VPITCH + kb2 + tg];
                af[2] = vs[(mt * 16 + gid) * VPITCH + kb2 + tg + 4];
                af[3] = vs[(mt * 16 + gid + 8) * VPITCH + kb2 + tg + 4];
                MMA_BF16(acc_o[mt][0], af, bq[0][0], bq[0][1]);
                MMA_BF16(acc_o[mt][1], af, bq[1][0], bq[1][1]);
            }
        }
    }

    if (tg == 0) {
        l_s[warp][gid] = l_run0;
        l_s[warp][gid + 8] = l_run1;
    }
    __syncwarp();

#pragma unroll
    for (int nq = 0; nq < 2; nq++) {
        float il0 = 1.f / l_s[warp][nq * 8 + 2 * tg];
        float il1 = 1.f / l_s[warp][nq * 8 + 2 * tg + 1];
        int s = qt + wm + nq * 8 + 2 * tg;
#pragma unroll
        for (int mt = 0; mt < 4; mt++) {
            int c0r = mt * 16 + gid;
            ((uint32_t*)og)[((size_t)c0r * SP + s) >> 1] =
                pk(acc_o[mt][nq][0] * il0, acc_o[mt][nq][1] * il1);
            ((uint32_t*)og)[((size_t)(c0r + 8) * SP + s) >> 1] =
                pk(acc_o[mt][nq][2] * il0, acc_o[mt][nq][3] * il1);
        }
    }
}

// ---------------------------------------------------------------------------
extern "C" void kernel_launch(void* const* d_in, const int* in_sizes, int n_in,
                              void* d_out, int out_size) {
    const float* x     = (const float*)d_in[0];
    const float* gamma = (const float*)d_in[1];
    const float* beta  = (const float*)d_in[2];
    const float* w_in  = (const float*)d_in[3];
    const float* b_in  = (const float*)d_in[4];
    const float* w_out = (const float*)d_in[5];
    const float* b_out = (const float*)d_in[6];
    float* out = (float*)d_out;

    __nv_bfloat16 *qkv, *att;
    float *sc, *sh;
    cudaGetSymbolAddress((void**)&qkv, g_qkv);
    cudaGetSymbolAddress((void**)&att, g_att);
    cudaGetSymbolAddress((void**)&sc,  g_scale);
    cudaGetSymbolAddress((void**)&sh,  g_shift);

    // 1. GroupNorm stats (scale/shift only)
    gn_stats_kernel<<<BATCH * NGRP, 256>>>(x, gamma, beta, sc, sh);

    // 2. QKV projection with fused GroupNorm, bf16 output
    gemm_qkv_kernel<<<dim3(SP / 128, (3 * CH) / 128, BATCH), 256>>>(
        w_in, x, sc, sh, b_in, qkv, 3 * CH, SP, CH);

    // 3. Attention (bf16 in/out)
    cudaFuncSetAttribute(attn_bf16_kernel, cudaFuncAttributeMaxDynamicSharedMemorySize,
                         ATTN_SMEM_BYTES);
    attn_bf16_kernel<<<dim3(SP / 128, NHEAD, BATCH), 256, ATTN_SMEM_BYTES>>>(qkv, att);

    // 4. Output projection + bias + residual (fp32 out)  — K = CH (fixed)
    gemm_out_kernel<<<dim3(SP / 128, CH / 128, BATCH), 256>>>(
        w_out, att, b_out, x, out, CH, SP, CH);
}

// round 8
// speedup vs baseline: 4.5982x; 1.0452x over previous
#include <cuda_runtime.h>
#include <cuda_bf16.h>
#include <math.h>
#include <stdint.h>

// Problem constants
#define BATCH 8
#define CH    512
#define SP    1024      // H*W = 32*32
#define NHEAD 8
#define HDIM  64
#define NGRP  32
#define GCH   16        // channels per group

// Scratch (device globals: allocation-free per harness rules)
__device__ __nv_bfloat16 g_qkv[BATCH * 3 * CH * SP];  // qkv (bf16)
__device__ __nv_bfloat16 g_att[BATCH * CH * SP];      // attention out (bf16)
__device__ float g_scale[BATCH * CH];                 // fused GN scale
__device__ float g_shift[BATCH * CH];                 // fused GN shift
__device__ uint32_t g_winp[(CH / 2) * (3 * CH)];      // packed w_in  [k2][M]
__device__ uint32_t g_woutp[(CH / 2) * CH];           // packed w_out [k2][M]

// ---------------------------------------------------------------------------
// Helpers
// ---------------------------------------------------------------------------
__device__ __forceinline__ uint32_t pk(float lo, float hi) {
    uint32_t r;
    asm("cvt.rn.bf16x2.f32 %0, %1, %2;" : "=r"(r) : "f"(hi), "f"(lo));
    return r;
}

#define MMA_BF16(d, a, b0, b1)                                              \
    asm volatile(                                                           \
        "mma.sync.aligned.m16n8k16.row.col.f32.bf16.bf16.f32 "              \
        "{%0,%1,%2,%3}, {%4,%5,%6,%7}, {%8,%9}, {%0,%1,%2,%3};"             \
        : "+f"(d[0]), "+f"(d[1]), "+f"(d[2]), "+f"(d[3])                    \
        : "r"(a[0]), "r"(a[1]), "r"(a[2]), "r"(a[3]), "r"(b0), "r"(b1))

// ---------------------------------------------------------------------------
// Weight prepack: w[M,K] fp32 -> wp[k2][M] bf16x2 words (transpose + pack).
// Block: 32 m x 32 k2. Coalesced both phases via smem tile.
// ---------------------------------------------------------------------------
__global__ __launch_bounds__(256) void prepack_kernel(
    const float* __restrict__ w, uint32_t* __restrict__ wp, int M, int K) {
    __shared__ uint32_t s[32][33];
    int k20 = blockIdx.x * 32, m0 = blockIdx.y * 32;
    int tid = threadIdx.x;
#pragma unroll
    for (int i = 0; i < 4; i++) {
        int l = tid + i * 256;
        int ml = l >> 5, k2l = l & 31;
        float2 v = *(const float2*)&w[(size_t)(m0 + ml) * K + 2 * (k20 + k2l)];
        s[k2l][ml] = pk(v.x, v.y);
    }
    __syncthreads();
#pragma unroll
    for (int i = 0; i < 4; i++) {
        int l = tid + i * 256;
        int k2l = l >> 5, ml = l & 31;
        wp[(size_t)(k20 + k2l) * M + m0 + ml] = s[k2l][ml];
    }
}

// ---------------------------------------------------------------------------
// GroupNorm stats: one block per (batch, group); emits scale/shift per chan.
// ---------------------------------------------------------------------------
__global__ void gn_stats_kernel(const float* __restrict__ x,
                                const float* __restrict__ gamma,
                                const float* __restrict__ beta,
                                float* __restrict__ scale,
                                float* __restrict__ shift) {
    int b = blockIdx.x >> 5;
    int g = blockIdx.x & 31;
    const float* xp = x + ((size_t)b * CH + g * GCH) * SP;
    int t = threadIdx.x;

    float sum = 0.f, sq = 0.f;
    for (int i4 = t; i4 < GCH * SP / 4; i4 += 256) {
        float4 v = *(const float4*)(xp + i4 * 4);
        sum += v.x + v.y + v.z + v.w;
        sq  += v.x * v.x + v.y * v.y + v.z * v.z + v.w * v.w;
    }
    __shared__ float s1[256], s2[256];
    s1[t] = sum; s2[t] = sq;
    __syncthreads();
    for (int off = 128; off > 0; off >>= 1) {
        if (t < off) { s1[t] += s1[t + off]; s2[t] += s2[t + off]; }
        __syncthreads();
    }
    const float invN = 1.f / (GCH * SP);
    float mean = s1[0] * invN;
    float var  = s2[0] * invN - mean * mean;
    float inv  = rsqrtf(var + 1e-6f);

    if (t < GCH) {
        int c = g * GCH + t;
        float sc = inv * gamma[c];
        scale[b * CH + c] = sc;
        shift[b * CH + c] = beta[c] - mean * sc;
    }
}

// ---------------------------------------------------------------------------
// QKV GEMM: C_bf16 = wp(packed bf16) @ (x*scale+shift) + bias.
// Double-buffered smem, one sync per 32-K tile, register prefetch.
// ---------------------------------------------------------------------------
#define GPITCH 136

__global__ __launch_bounds__(256) void gemm_qkv_kernel(
    const uint32_t* __restrict__ Awp, const float* __restrict__ X,
    const float* __restrict__ scale_g, const float* __restrict__ shift_g,
    const float* __restrict__ bias, __nv_bfloat16* __restrict__ Cb,
    int M, int N, int K) {
    __shared__ uint32_t As[2][16 * GPITCH];  // [k2][m]
    __shared__ uint32_t Bs[2][16 * GPITCH];  // [k2][n]

    int tid  = threadIdx.x;
    int warp = tid >> 5, lane = tid & 31;
    int gid = lane >> 2, tg = lane & 3;
    int wm = (warp >> 1) * 32, wn = (warp & 1) * 64;
    int m0 = blockIdx.y * 128, n0 = blockIdx.x * 128;
    int z  = blockIdx.z;

    const float* Bp  = X + (size_t)z * K * N;
    const float* scp = scale_g + z * CH;
    const float* shp = shift_g + z * CH;
    __nv_bfloat16* Cp = Cb + (size_t)z * M * N;

    float acc[2][8][4];
#pragma unroll
    for (int mt = 0; mt < 2; mt++)
#pragma unroll
        for (int nt = 0; nt < 8; nt++)
#pragma unroll
            for (int e = 0; e < 4; e++) acc[mt][nt][e] = 0.f;

    // A prefetch mapping: 512 uint4 slots cover 16 k2-rows x 128 m
    int a_row  = tid >> 5;             // +0 and +8 for l=0,1... (slot>>5)
    int a_col4 = (tid & 31) * 4;
    // B prefetch mapping
    uint4 pa[2];
    float4 pb0[2], pb1[2];
    float ps0[2], ph0[2], ps1[2], ph1[2];

#define QKV_LOAD_A(k0)                                                       \
    {                                                                        \
        _Pragma("unroll") for (int l = 0; l < 2; l++) {                      \
            int row = a_row + l * 8;                                         \
            pa[l] = *(const uint4*)&Awp[(size_t)(((k0) >> 1) + row) * M +    \
                                        m0 + a_col4];                        \
        }                                                                    \
    }
#define QKV_LOAD_B(k0)                                                       \
    {                                                                        \
        _Pragma("unroll") for (int l = 0; l < 2; l++) {                      \
            int slot = tid + l * 256;                                        \
            int rp = slot >> 5, n4 = (slot & 31) * 4;                        \
            int row = (k0) + 2 * rp;                                         \
            pb0[l] = *(const float4*)&Bp[(size_t)row * N + n0 + n4];         \
            pb1[l] = *(const float4*)&Bp[(size_t)(row + 1) * N + n0 + n4];   \
            ps0[l] = scp[row];     ph0[l] = shp[row];                        \
            ps1[l] = scp[row + 1]; ph1[l] = shp[row + 1];                    \
        }                                                                    \
    }
#define QKV_STORE(buf)                                                       \
    {                                                                        \
        _Pragma("unroll") for (int l = 0; l < 2; l++) {                      \
            int row = a_row + l * 8;                                         \
            *(uint4*)&As[buf][row * GPITCH + a_col4] = pa[l];                \
        }                                                                    \
        _Pragma("unroll") for (int l = 0; l < 2; l++) {                      \
            int slot = tid + l * 256;                                        \
            int rp = slot >> 5, n4 = (slot & 31) * 4;                        \
            uint4 u;                                                         \
            u.x = pk(pb0[l].x * ps0[l] + ph0[l], pb1[l].x * ps1[l] + ph1[l]);\
            u.y = pk(pb0[l].y * ps0[l] + ph0[l], pb1[l].y * ps1[l] + ph1[l]);\
            u.z = pk(pb0[l].z * ps0[l] + ph0[l], pb1[l].z * ps1[l] + ph1[l]);\
            u.w = pk(pb0[l].w * ps0[l] + ph0[l], pb1[l].w * ps1[l] + ph1[l]);\
            *(uint4*)&Bs[buf][rp * GPITCH + n4] = u;                         \
        }                                                                    \
    }

    QKV_LOAD_A(0); QKV_LOAD_B(0);
    QKV_STORE(0);
    __syncthreads();

    for (int k0 = 0; k0 < K; k0 += 32) {
        int cur = (k0 >> 5) & 1;
        bool nxt = (k0 + 32) < K;
        if (nxt) { QKV_LOAD_A(k0 + 32); QKV_LOAD_B(k0 + 32); }

#pragma unroll
        for (int kk = 0; kk < 2; kk++) {
            int kb2 = kk * 8;
            uint32_t af[2][4];
#pragma unroll
            for (int mt = 0; mt < 2; mt++) {
                int mr = wm + mt * 16 + gid;
                af[mt][0] = As[cur][(kb2 + tg) * GPITCH + mr];
                af[mt][1] = As[cur][(kb2 + tg) * GPITCH + mr + 8];
                af[mt][2] = As[cur][(kb2 + tg + 4) * GPITCH + mr];
                af[mt][3] = As[cur][(kb2 + tg + 4) * GPITCH + mr + 8];
            }
#pragma unroll
            for (int nt = 0; nt < 8; nt++) {
                uint32_t b0 = Bs[cur][(kb2 + tg) * GPITCH + wn + nt * 8 + gid];
                uint32_t b1 = Bs[cur][(kb2 + tg + 4) * GPITCH + wn + nt * 8 + gid];
                MMA_BF16(acc[0][nt], af[0], b0, b1);
                MMA_BF16(acc[1][nt], af[1], b0, b1);
            }
        }
        if (nxt) QKV_STORE(cur ^ 1);
        __syncthreads();
    }

#pragma unroll
    for (int mt = 0; mt < 2; mt++) {
        int r0 = m0 + wm + mt * 16 + gid;
        int r1 = r0 + 8;
        float bv0 = bias[r0], bv1 = bias[r1];
#pragma unroll
        for (int nt = 0; nt < 8; nt++) {
            int col = n0 + wn + nt * 8 + tg * 2;
            ((uint32_t*)Cp)[((size_t)r0 * N + col) >> 1] =
                pk(acc[mt][nt][0] + bv0, acc[mt][nt][1] + bv0);
            ((uint32_t*)Cp)[((size_t)r1 * N + col) >> 1] =
                pk(acc[mt][nt][2] + bv1, acc[mt][nt][3] + bv1);
        }
    }
}

// ---------------------------------------------------------------------------
// Out-proj GEMM: C = wp(packed) @ att_bf16 + bias + resid(x). Double-buffered.
// ---------------------------------------------------------------------------
__global__ __launch_bounds__(256) void gemm_out_kernel(
    const uint32_t* __restrict__ Awp, const __nv_bfloat16* __restrict__ Bm,
    const float* __restrict__ bias, const float* __restrict__ resid,
    float* __restrict__ C, int M, int N, int K) {
    __shared__ uint32_t As[2][16 * GPITCH];
    __shared__ uint32_t Bs[2][16 * GPITCH];

    int tid  = threadIdx.x;
    int warp = tid >> 5, lane = tid & 31;
    int gid = lane >> 2, tg = lane & 3;
    int wm = (warp >> 1) * 32, wn = (warp & 1) * 64;
    int m0 = blockIdx.y * 128, n0 = blockIdx.x * 128;

    const __nv_bfloat16* Bp = Bm + (size_t)blockIdx.z * K * N;
    float* Cp       = C + (size_t)blockIdx.z * M * N;
    const float* Rp = resid + (size_t)blockIdx.z * M * N;

    float acc[2][8][4];
#pragma unroll
    for (int mt = 0; mt < 2; mt++)
#pragma unroll
        for (int nt = 0; nt < 8; nt++)
#pragma unroll
            for (int e = 0; e < 4; e++) acc[mt][nt][e] = 0.f;

    int a_row  = tid >> 5;
    int a_col4 = (tid & 31) * 4;
    uint4 pa[2];
    uint2 pb0[2], pb1[2];

#define OUT_LOAD_A(k0)                                                       \
    {                                                                        \
        _Pragma("unroll") for (int l = 0; l < 2; l++) {                      \
            int row = a_row + l * 8;                                         \
            pa[l] = *(const uint4*)&Awp[(size_t)(((k0) >> 1) + row) * M +    \
                                        m0 + a_col4];                        \
        }                                                                    \
    }
#define OUT_LOAD_B(k0)                                                       \
    {                                                                        \
        _Pragma("unroll") for (int l = 0; l < 2; l++) {                      \
            int slot = tid + l * 256;                                        \
            int rp = slot >> 5, n4 = (slot & 31) * 4;                        \
            const uint32_t* r0w =                                            \
                (const uint32_t*)(Bp + (size_t)((k0) + 2 * rp) * N);         \
            const uint32_t* r1w =                                            \
                (const uint32_t*)(Bp + (size_t)((k0) + 2 * rp + 1) * N);     \
            pb0[l] = *(const uint2*)&r0w[(n0 + n4) >> 1];                    \
            pb1[l] = *(const uint2*)&r1w[(n0 + n4) >> 1];                    \
        }                                                                    \
    }
#define OUT_STORE(buf)                                                       \
    {                                                                        \
        _Pragma("unroll") for (int l = 0; l < 2; l++) {                      \
            int row = a_row + l * 8;                                         \
            *(uint4*)&As[buf][row * GPITCH + a_col4] = pa[l];                \
        }                                                                    \
        _Pragma("unroll") for (int l = 0; l < 2; l++) {                      \
            int slot = tid + l * 256;                                        \
            int rp = slot >> 5, n4 = (slot & 31) * 4;                        \
            uint4 u;                                                         \
            u.x = __byte_perm(pb0[l].x, pb1[l].x, 0x5410);                   \
            u.y = __byte_perm(pb0[l].x, pb1[l].x, 0x7632);                   \
            u.z = __byte_perm(pb0[l].y, pb1[l].y, 0x5410);                   \
            u.w = __byte_perm(pb0[l].y, pb1[l].y, 0x7632);                   \
            *(uint4*)&Bs[buf][rp * GPITCH + n4] = u;                         \
        }                                                                    \
    }

    OUT_LOAD_A(0); OUT_LOAD_B(0);
    OUT_STORE(0);
    __syncthreads();

    for (int k0 = 0; k0 < K; k0 += 32) {
        int cur = (k0 >> 5) & 1;
        bool nxt = (k0 + 32) < K;
        if (nxt) { OUT_LOAD_A(k0 + 32); OUT_LOAD_B(k0 + 32); }

#pragma unroll
        for (int kk = 0; kk < 2; kk++) {
            int kb2 = kk * 8;
            uint32_t af[2][4];
#pragma unroll
            for (int mt = 0; mt < 2; mt++) {
                int mr = wm + mt * 16 + gid;
                af[mt][0] = As[cur][(kb2 + tg) * GPITCH + mr];
                af[mt][1] = As[cur][(kb2 + tg) * GPITCH + mr + 8];
                af[mt][2] = As[cur][(kb2 + tg + 4) * GPITCH + mr];
                af[mt][3] = As[cur][(kb2 + tg + 4) * GPITCH + mr + 8];
            }
#pragma unroll
            for (int nt = 0; nt < 8; nt++) {
                uint32_t b0 = Bs[cur][(kb2 + tg) * GPITCH + wn + nt * 8 + gid];
                uint32_t b1 = Bs[cur][(kb2 + tg + 4) * GPITCH + wn + nt * 8 + gid];
                MMA_BF16(acc[0][nt], af[0], b0, b1);
                MMA_BF16(acc[1][nt], af[1], b0, b1);
            }
        }
        if (nxt) OUT_STORE(cur ^ 1);
        __syncthreads();
    }

#pragma unroll
    for (int mt = 0; mt < 2; mt++) {
        int r0 = m0 + wm + mt * 16 + gid;
        int r1 = r0 + 8;
        float bv0 = bias[r0], bv1 = bias[r1];
#pragma unroll
        for (int nt = 0; nt < 8; nt++) {
            int col = n0 + wn + nt * 8 + tg * 2;
            float2 v0, v1;
            v0.x = acc[mt][nt][0] + bv0; v0.y = acc[mt][nt][1] + bv0;
            v1.x = acc[mt][nt][2] + bv1; v1.y = acc[mt][nt][3] + bv1;
            float2 q0 = *(const float2*)&Rp[(size_t)r0 * N + col];
            float2 q1 = *(const float2*)&Rp[(size_t)r1 * N + col];
            v0.x += q0.x; v0.y += q0.y;
            v1.x += q1.x; v1.y += q1.y;
            *(float2*)&Cp[(size_t)r0 * N + col] = v0;
            *(float2*)&Cp[(size_t)r1 * N + col] = v1;
        }
    }
}

// ---------------------------------------------------------------------------
// BF16 flash attention: double-buffered K/V smem + register prefetch.
// One __syncthreads per k-tile.
// ---------------------------------------------------------------------------
#define VPITCH 68
#define ATTN_WORDS (32 * GPITCH + 2 * (32 * GPITCH + 64 * VPITCH) + 128 * VPITCH)
#define ATTN_SMEM_BYTES (ATTN_WORDS * 4)

__global__ __launch_bounds__(256, 1) void attn_bf16_kernel(
    const __nv_bfloat16* __restrict__ qkv, __nv_bfloat16* __restrict__ out) {
    extern __shared__ uint32_t smw[];
    uint32_t* qs  = smw;                                 // [c2][q]
    uint32_t* ks0 = qs + 32 * GPITCH;
    uint32_t* ks1 = ks0 + 32 * GPITCH;
    uint32_t* vs0 = ks1 + 32 * GPITCH;
    uint32_t* vs1 = vs0 + 64 * VPITCH;
    uint32_t* p_s = vs1 + 64 * VPITCH;                   // [q][k2]
    uint32_t* ksb[2] = {ks0, ks1};
    uint32_t* vsb[2] = {vs0, vs1};
    __shared__ float corr_s[8][16];
    __shared__ float l_s[8][16];

    int tid  = threadIdx.x;
    int warp = tid >> 5, lane = tid & 31;
    int gid = lane >> 2, tg = lane & 3;
    int wm = warp * 16;
    int qt = blockIdx.x * 128;
    int hn = blockIdx.y, b = blockIdx.z;

    const __nv_bfloat16* qg = qkv + ((size_t)b * 3 * CH + hn * HDIM) * SP;
    const __nv_bfloat16* kg = qg + (size_t)CH * SP;
    const __nv_bfloat16* vg = kg + (size_t)CH * SP;
    __nv_bfloat16* og = out + ((size_t)b * CH + hn * HDIM) * SP;

    const float SC = 0.125f * 1.44269504088896f;

    // Q tile -> qs via PRMT interleave
#pragma unroll
    for (int l = 0; l < 4; l++) {
        int slot = tid + l * 256;
        int r = slot >> 5;
        int q4 = (slot & 31) * 4;
        const uint32_t* r0w = (const uint32_t*)(qg + (size_t)(2 * r) * SP + qt);
        const uint32_t* r1w = (const uint32_t*)(qg + (size_t)(2 * r + 1) * SP + qt);
        uint2 u0 = *(const uint2*)&r0w[q4 >> 1];
        uint2 u1 = *(const uint2*)&r1w[q4 >> 1];
        uint4 u;
        u.x = __byte_perm(u0.x, u1.x, 0x5410);
        u.y = __byte_perm(u0.x, u1.x, 0x7632);
        u.z = __byte_perm(u0.y, u1.y, 0x5410);
        u.w = __byte_perm(u0.y, u1.y, 0x7632);
        *(uint4*)&qs[r * GPITCH + q4] = u;
    }

    // Prefetch registers for K (uint2 pairs) and V (uint4)
    uint2 ku0[4], ku1[4];
    uint4 kv[4];

#define ATTN_PREFETCH(kt)                                                    \
    {                                                                        \
        _Pragma("unroll") for (int l = 0; l < 4; l++) {                      \
            int slot = tid + l * 256;                                        \
            int r = slot >> 5;                                               \
            int k4 = (slot & 31) * 4;                                        \
            const uint32_t* r0w =                                            \
                (const uint32_t*)(kg + (size_t)(2 * r) * SP + (kt));         \
            const uint32_t* r1w =                                            \
                (const uint32_t*)(kg + (size_t)(2 * r + 1) * SP + (kt));     \
            ku0[l] = *(const uint2*)&r0w[k4 >> 1];                           \
            ku1[l] = *(const uint2*)&r1w[k4 >> 1];                           \
        }                                                                    \
        _Pragma("unroll") for (int l = 0; l < 4; l++) {                      \
            int slot = tid + l * 256;                                        \
            int c = slot >> 4;                                               \
            int k8 = (slot & 15) * 8;                                        \
            const uint32_t* vw =                                             \
                (const uint32_t*)(vg + (size_t)c * SP + (kt));               \
            kv[l] = *(const uint4*)&vw[k8 >> 1];                             \
        }                                                                    \
    }
#define ATTN_STORE(buf)                                                      \
    {                                                                        \
        _Pragma("unroll") for (int l = 0; l < 4; l++) {                      \
            int slot = tid + l * 256;                                        \
            int r = slot >> 5;                                               \
            int k4 = (slot & 31) * 4;                                        \
            uint4 u;                                                         \
            u.x = __byte_perm(ku0[l].x, ku1[l].x, 0x5410);                   \
            u.y = __byte_perm(ku0[l].x, ku1[l].x, 0x7632);                   \
            u.z = __byte_perm(ku0[l].y, ku1[l].y, 0x5410);                   \
            u.w = __byte_perm(ku0[l].y, ku1[l].y, 0x7632);                   \
            *(uint4*)&ksb[buf][r * GPITCH + k4] = u;                         \
        }                                                                    \
        _Pragma("unroll") for (int l = 0; l < 4; l++) {                      \
            int slot = tid + l * 256;                                        \
            int c = slot >> 4;                                               \
            int k8 = (slot & 15) * 8;                                        \
            *(uint4*)&vsb[buf][c * VPITCH + (k8 >> 1)] = kv[l];              \
        }                                                                    \
    }

    ATTN_PREFETCH(0);
    ATTN_STORE(0);
    __syncthreads();   // covers Q tile + tile 0

    float m_run0 = -INFINITY, m_run1 = -INFINITY;
    float l_run0 = 0.f, l_run1 = 0.f;

    float acc_o[4][2][4];
#pragma unroll
    for (int mt = 0; mt < 4; mt++)
#pragma unroll
        for (int nq = 0; nq < 2; nq++)
#pragma unroll
            for (int e = 0; e < 4; e++) acc_o[mt][nq][e] = 0.f;

    for (int it = 0; it < SP / 128; it++) {
        int cur = it & 1;
        bool nxt = it < SP / 128 - 1;
        if (nxt) ATTN_PREFETCH((it + 1) * 128);
        const uint32_t* ks = ksb[cur];
        const uint32_t* vs = vsb[cur];

        // ---- Phase 1: S[q16][k128] ----
        float acc_s[16][4];
#pragma unroll
        for (int nt = 0; nt < 16; nt++)
#pragma unroll
            for (int e = 0; e < 4; e++) acc_s[nt][e] = 0.f;

#pragma unroll
        for (int cc = 0; cc < 4; cc++) {
            int cb2 = cc * 8;
            uint32_t af[4];
            af[0] = qs[(cb2 + tg) * GPITCH + wm + gid];
            af[1] = qs[(cb2 + tg) * GPITCH + wm + gid + 8];
            af[2] = qs[(cb2 + tg + 4) * GPITCH + wm + gid];
            af[3] = qs[(cb2 + tg + 4) * GPITCH + wm + gid + 8];
#pragma unroll
            for (int nt = 0; nt < 16; nt++) {
                uint32_t b0 = ks[(cb2 + tg) * GPITCH + nt * 8 + gid];
                uint32_t b1 = ks[(cb2 + tg + 4) * GPITCH + nt * 8 + gid];
                MMA_BF16(acc_s[nt], af, b0, b1);
            }
        }

        // ---- Online softmax (exp2 domain) ----
        float mx0 = -INFINITY, mx1 = -INFINITY;
#pragma unroll
        for (int nt = 0; nt < 16; nt++) {
            acc_s[nt][0] *= SC; acc_s[nt][1] *= SC;
            acc_s[nt][2] *= SC; acc_s[nt][3] *= SC;
            mx0 = fmaxf(mx0, fmaxf(acc_s[nt][0], acc_s[nt][1]));
            mx1 = fmaxf(mx1, fmaxf(acc_s[nt][2], acc_s[nt][3]));
        }
        mx0 = fmaxf(mx0, __shfl_xor_sync(0xffffffffu, mx0, 1));
        mx0 = fmaxf(mx0, __shfl_xor_sync(0xffffffffu, mx0, 2));
        mx1 = fmaxf(mx1, __shfl_xor_sync(0xffffffffu, mx1, 1));
        mx1 = fmaxf(mx1, __shfl_xor_sync(0xffffffffu, mx1, 2));

        float mnew0 = fmaxf(m_run0, mx0);
        float mnew1 = fmaxf(m_run1, mx1);
        float corr0 = exp2f(m_run0 - mnew0);
        float corr1 = exp2f(m_run1 - mnew1);

        float ps0 = 0.f, ps1 = 0.f;
#pragma unroll
        for (int nt = 0; nt < 16; nt++) {
            float p0 = exp2f(acc_s[nt][0] - mnew0);
            float p1 = exp2f(acc_s[nt][1] - mnew0);
            float p2 = exp2f(acc_s[nt][2] - mnew1);
            float p3 = exp2f(acc_s[nt][3] - mnew1);
            ps0 += p0 + p1; ps1 += p2 + p3;
            p_s[(wm + gid) * VPITCH + nt * 4 + tg]     = pk(p0, p1);
            p_s[(wm + gid + 8) * VPITCH + nt * 4 + tg] = pk(p2, p3);
        }
        ps0 += __shfl_xor_sync(0xffffffffu, ps0, 1);
        ps0 += __shfl_xor_sync(0xffffffffu, ps0, 2);
        ps1 += __shfl_xor_sync(0xffffffffu, ps1, 1);
        ps1 += __shfl_xor_sync(0xffffffffu, ps1, 2);
        l_run0 = l_run0 * corr0 + ps0;
        l_run1 = l_run1 * corr1 + ps1;
        m_run0 = mnew0; m_run1 = mnew1;
        if (tg == 0) {
            corr_s[warp][gid] = corr0;
            corr_s[warp][gid + 8] = corr1;
        }
        __syncwarp();

#pragma unroll
        for (int nq = 0; nq < 2; nq++) {
            float cc0 = corr_s[warp][nq * 8 + 2 * tg];
            float cc1 = corr_s[warp][nq * 8 + 2 * tg + 1];
#pragma unroll
            for (int mt = 0; mt < 4; mt++) {
                acc_o[mt][nq][0] *= cc0; acc_o[mt][nq][1] *= cc1;
                acc_o[mt][nq][2] *= cc0; acc_o[mt][nq][3] *= cc1;
            }
        }

        // ---- Phase 2: O^T[c64][q16] += V @ P^T ----
#pragma unroll
        for (int kc = 0; kc < 8; kc++) {
            int kb2 = kc * 8;
            uint32_t bq[2][2];
#pragma unroll
            for (int nq = 0; nq < 2; nq++) {
                bq[nq][0] = p_s[(wm + nq * 8 + gid) * VPITCH + kb2 + tg];
                bq[nq][1] = p_s[(wm + nq * 8 + gid) * VPITCH + kb2 + tg + 4];
            }
#pragma unroll
            for (int mt = 0; mt < 4; mt++) {
                uint32_t af[4];
                af[0] = vs[(mt * 16 + gid) * VPITCH + kb2 + tg];
                af[1] = vs[(mt * 16 + gid + 8) * VPITCH + kb2 + tg];
                af[2] = vs[(mt * 16 + gid) * VPITCH + kb2 + tg + 4];
                af[3] = vs[(mt * 16 + gid + 8) * VPITCH + kb2 + tg + 4];
                MMA_BF16(acc_o[mt][0], af, bq[0][0], bq[0][1]);
                MMA_BF16(acc_o[mt][1], af, bq[1][0], bq[1][1]);
            }
        }

        if (nxt) ATTN_STORE(cur ^ 1);
        __syncthreads();
    }

    if (tg == 0) {
        l_s[warp][gid] = l_run0;
        l_s[warp][gid + 8] = l_run1;
    }
    __syncwarp();

#pragma unroll
    for (int nq = 0; nq < 2; nq++) {
        float il0 = 1.f / l_s[warp][nq * 8 + 2 * tg];
        float il1 = 1.f / l_s[warp][nq * 8 + 2 * tg + 1];
        int s = qt + wm + nq * 8 + 2 * tg;
#pragma unroll
        for (int mt = 0; mt < 4; mt++) {
            int c0r = mt * 16 + gid;
            ((uint32_t*)og)[((size_t)c0r * SP + s) >> 1] =
                pk(acc_o[mt][nq][0] * il0, acc_o[mt][nq][1] * il1);
            ((uint32_t*)og)[((size_t)(c0r + 8) * SP + s) >> 1] =
                pk(acc_o[mt][nq][2] * il0, acc_o[mt][nq][3] * il1);
        }
    }
}

// ---------------------------------------------------------------------------
extern "C" void kernel_launch(void* const* d_in, const int* in_sizes, int n_in,
                              void* d_out, int out_size) {
    const float* x     = (const float*)d_in[0];
    const float* gamma = (const float*)d_in[1];
    const float* beta  = (const float*)d_in[2];
    const float* w_in  = (const float*)d_in[3];
    const float* b_in  = (const float*)d_in[4];
    const float* w_out = (const float*)d_in[5];
    const float* b_out = (const float*)d_in[6];
    float* out = (float*)d_out;

    __nv_bfloat16 *qkv, *att;
    float *sc, *sh;
    uint32_t *winp, *woutp;
    cudaGetSymbolAddress((void**)&qkv,  g_qkv);
    cudaGetSymbolAddress((void**)&att,  g_att);
    cudaGetSymbolAddress((void**)&sc,   g_scale);
    cudaGetSymbolAddress((void**)&sh,   g_shift);
    cudaGetSymbolAddress((void**)&winp, g_winp);
    cudaGetSymbolAddress((void**)&woutp, g_woutp);

    // 0. Weight prepack (bf16, [k2][M])
    prepack_kernel<<<dim3(CH / 64, (3 * CH) / 32), 256>>>(w_in, winp, 3 * CH, CH);
    prepack_kernel<<<dim3(CH / 64, CH / 32), 256>>>(w_out, woutp, CH, CH);

    // 1. GroupNorm stats
    gn_stats_kernel<<<BATCH * NGRP, 256>>>(x, gamma, beta, sc, sh);

    // 2. QKV projection (fused GN, bf16 out, double-buffered)
    gemm_qkv_kernel<<<dim3(SP / 128, (3 * CH) / 128, BATCH), 256>>>(
        winp, x, sc, sh, b_in, qkv, 3 * CH, SP, CH);

    // 3. Attention (bf16 in/out, double-buffered + prefetch)
    cudaFuncSetAttribute(attn_bf16_kernel, cudaFuncAttributeMaxDynamicSharedMemorySize,
                         ATTN_SMEM_BYTES);
    attn_bf16_kernel<<<dim3(SP / 128, NHEAD, BATCH), 256, ATTN_SMEM_BYTES>>>(qkv, att);

    // 4. Output projection + bias + residual
    gemm_out_kernel<<<dim3(SP / 128, CH / 128, BATCH), 256>>>(
        woutp, att, b_out, x, out, CH, SP, CH);
}

// round 9
// speedup vs baseline: 5.4256x; 1.1799x over previous
#include <cuda_runtime.h>
#include <cuda_bf16.h>
#include <math.h>
#include <stdint.h>

// Problem constants
#define BATCH 8
#define CH    512
#define SP    1024      // H*W = 32*32
#define NHEAD 8
#define HDIM  64
#define NGRP  32
#define GCH   16        // channels per group

// Scratch (device globals: allocation-free per harness rules)
__device__ __nv_bfloat16 g_qkv[BATCH * 3 * CH * SP];  // qkv (bf16)
__device__ __nv_bfloat16 g_att[BATCH * CH * SP];      // attention out (bf16)
__device__ float g_scale[BATCH * CH];                 // fused GN scale
__device__ float g_shift[BATCH * CH];                 // fused GN shift
__device__ uint32_t g_winp[(3 * CH) * (CH / 2)];      // bf16 w_in  [M][K] row-major
__device__ uint32_t g_woutp[CH * (CH / 2)];           // bf16 w_out [M][K] row-major

// ---------------------------------------------------------------------------
// Helpers
// ---------------------------------------------------------------------------
__device__ __forceinline__ uint32_t pk(float lo, float hi) {
    uint32_t r;
    asm("cvt.rn.bf16x2.f32 %0, %1, %2;" : "=r"(r) : "f"(hi), "f"(lo));
    return r;
}

#define MMA_BF16(d, a, b0, b1)                                              \
    asm volatile(                                                           \
        "mma.sync.aligned.m16n8k16.row.col.f32.bf16.bf16.f32 "              \
        "{%0,%1,%2,%3}, {%4,%5,%6,%7}, {%8,%9}, {%0,%1,%2,%3};"             \
        : "+f"(d[0]), "+f"(d[1]), "+f"(d[2]), "+f"(d[3])                    \
        : "r"(a[0]), "r"(a[1]), "r"(a[2]), "r"(a[3]), "r"(b0), "r"(b1))

#define LDSM4(d, addr)                                                      \
    asm volatile("ldmatrix.sync.aligned.m8n8.x4.shared.b16 "                \
                 "{%0,%1,%2,%3}, [%4];"                                     \
                 : "=r"((d)[0]), "=r"((d)[1]), "=r"((d)[2]), "=r"((d)[3])   \
                 : "r"(addr))

#define LDSM4T(d, addr)                                                     \
    asm volatile("ldmatrix.sync.aligned.m8n8.x4.trans.shared.b16 "          \
                 "{%0,%1,%2,%3}, [%4];"                                     \
                 : "=r"((d)[0]), "=r"((d)[1]), "=r"((d)[2]), "=r"((d)[3])   \
                 : "r"(addr))

// ---------------------------------------------------------------------------
// Weight prepack: fp32 [M][K] -> bf16 [M][K] row-major (elementwise pack).
// ---------------------------------------------------------------------------
__global__ __launch_bounds__(256) void prepack_kernel(
    const float* __restrict__ w, uint32_t* __restrict__ wp, int nwords) {
    int i = blockIdx.x * 256 + threadIdx.x;
    if (i < nwords) {
        float2 v = *(const float2*)&w[2 * i];
        wp[i] = pk(v.x, v.y);
    }
}

// ---------------------------------------------------------------------------
// GroupNorm stats
// ---------------------------------------------------------------------------
__global__ void gn_stats_kernel(const float* __restrict__ x,
                                const float* __restrict__ gamma,
                                const float* __restrict__ beta,
                                float* __restrict__ scale,
                                float* __restrict__ shift) {
    int b = blockIdx.x >> 5;
    int g = blockIdx.x & 31;
    const float* xp = x + ((size_t)b * CH + g * GCH) * SP;
    int t = threadIdx.x;

    float sum = 0.f, sq = 0.f;
    for (int i4 = t; i4 < GCH * SP / 4; i4 += 256) {
        float4 v = *(const float4*)(xp + i4 * 4);
        sum += v.x + v.y + v.z + v.w;
        sq  += v.x * v.x + v.y * v.y + v.z * v.z + v.w * v.w;
    }
    __shared__ float s1[256], s2[256];
    s1[t] = sum; s2[t] = sq;
    __syncthreads();
    for (int off = 128; off > 0; off >>= 1) {
        if (t < off) { s1[t] += s1[t + off]; s2[t] += s2[t + off]; }
        __syncthreads();
    }
    const float invN = 1.f / (GCH * SP);
    float mean = s1[0] * invN;
    float var  = s2[0] * invN - mean * mean;
    float inv  = rsqrtf(var + 1e-6f);

    if (t < GCH) {
        int c = g * GCH + t;
        float sc = inv * gamma[c];
        scale[b * CH + c] = sc;
        shift[b * CH + c] = beta[c] - mean * sc;
    }
}

// ---------------------------------------------------------------------------
// Shared GEMM geometry:
//   As: [m 128][k 32 halves] pitch 40 halves (20 words)  -> non-trans ldmatrix
//   Bs: [k 32][n 128 halves] pitch 136 halves (68 words) -> trans ldmatrix
// Block 128x128, K-tile 32, double-buffered, 8 warps (warp tile 32x64).
// ---------------------------------------------------------------------------
#define APW 20    // A pitch in words
#define BPW 68    // B pitch in words (=136 halves)

// ---------------------------------------------------------------------------
// QKV GEMM: C_bf16 = w_in_bf16 @ (x*scale+shift) + bias
// ---------------------------------------------------------------------------
__global__ __launch_bounds__(256) void gemm_qkv_kernel(
    const uint32_t* __restrict__ Awp, const float* __restrict__ X,
    const float* __restrict__ scale_g, const float* __restrict__ shift_g,
    const float* __restrict__ bias, __nv_bfloat16* __restrict__ Cb,
    int M, int N, int K) {
    __shared__ uint32_t As[2][128 * APW];
    __shared__ uint32_t Bs[2][32 * BPW];

    int tid  = threadIdx.x;
    int warp = tid >> 5, lane = tid & 31;
    int gid = lane >> 2, tg = lane & 3;
    int g8 = lane >> 3, lr = lane & 7;
    int wm = (warp >> 1) * 32, wn = (warp & 1) * 64;
    int m0 = blockIdx.y * 128, n0 = blockIdx.x * 128;
    int z  = blockIdx.z;

    const float* Bp  = X + (size_t)z * K * N;
    const float* scp = scale_g + z * CH;
    const float* shp = shift_g + z * CH;
    __nv_bfloat16* Cp = Cb + (size_t)z * M * N;

    uint32_t asb[2] = {(uint32_t)__cvta_generic_to_shared(&As[0][0]),
                       (uint32_t)__cvta_generic_to_shared(&As[1][0])};
    uint32_t bsb[2] = {(uint32_t)__cvta_generic_to_shared(&Bs[0][0]),
                       (uint32_t)__cvta_generic_to_shared(&Bs[1][0])};

    // ldmatrix lane offsets (bytes)
    int nt_ro = (g8 & 1) * 8 + lr;   // row offset (A rows m / B rows k)
    int nt_co = (g8 >> 1) * 8;       // col offset halves
    uint32_t a_off[2];
#pragma unroll
    for (int mt = 0; mt < 2; mt++)
        a_off[mt] = ((wm + mt * 16 + nt_ro) * 40 + nt_co) * 2;

    float acc[2][8][4];
#pragma unroll
    for (int mt = 0; mt < 2; mt++)
#pragma unroll
        for (int nt = 0; nt < 8; nt++)
#pragma unroll
            for (int e = 0; e < 4; e++) acc[mt][nt][e] = 0.f;

    uint4 pa[2];
    float4 pb0[2], pb1[2];
    float psc[2], psh[2];

#define QKV_LOAD(k0)                                                         \
    {                                                                        \
        _Pragma("unroll") for (int l = 0; l < 2; l++) {                      \
            int slot = tid + l * 256;                                        \
            int row = slot >> 2, c8 = (slot & 3) * 8;                        \
            pa[l] = *(const uint4*)&Awp[(size_t)(m0 + row) * (K >> 1) +      \
                                        (((k0) + c8) >> 1)];                 \
        }                                                                    \
        _Pragma("unroll") for (int l = 0; l < 2; l++) {                      \
            int slot = tid + l * 256;                                        \
            int kk2 = slot >> 4, n8 = (slot & 15) * 8;                       \
            int ch = (k0) + kk2;                                             \
            pb0[l] = *(const float4*)&Bp[(size_t)ch * N + n0 + n8];          \
            pb1[l] = *(const float4*)&Bp[(size_t)ch * N + n0 + n8 + 4];      \
            psc[l] = scp[ch]; psh[l] = shp[ch];                              \
        }                                                                    \
    }
#define QKV_STORE(buf)                                                       \
    {                                                                        \
        _Pragma("unroll") for (int l = 0; l < 2; l++) {                      \
            int slot = tid + l * 256;                                        \
            int row = slot >> 2, c4 = (slot & 3) * 4;                        \
            *(uint4*)&As[buf][row * APW + c4] = pa[l];                       \
        }                                                                    \
        _Pragma("unroll") for (int l = 0; l < 2; l++) {                      \
            int slot = tid + l * 256;                                        \
            int kk2 = slot >> 4, n4 = (slot & 15) * 4;                       \
            float s = psc[l], h = psh[l];                                    \
            uint4 u;                                                         \
            u.x = pk(pb0[l].x * s + h, pb0[l].y * s + h);                    \
            u.y = pk(pb0[l].z * s + h, pb0[l].w * s + h);                    \
            u.z = pk(pb1[l].x * s + h, pb1[l].y * s + h);                    \
            u.w = pk(pb1[l].z * s + h, pb1[l].w * s + h);                    \
            *(uint4*)&Bs[buf][kk2 * BPW + n4] = u;                           \
        }                                                                    \
    }

    QKV_LOAD(0);
    QKV_STORE(0);
    __syncthreads();

    for (int k0 = 0; k0 < K; k0 += 32) {
        int cur = (k0 >> 5) & 1;
        bool nxt = (k0 + 32) < K;
        if (nxt) QKV_LOAD(k0 + 32);

#pragma unroll
        for (int kk = 0; kk < 2; kk++) {
            int kb = kk * 16;   // halves
            uint32_t af[2][4];
            LDSM4(af[0], asb[cur] + a_off[0] + kb * 2);
            LDSM4(af[1], asb[cur] + a_off[1] + kb * 2);
#pragma unroll
            for (int ntp = 0; ntp < 4; ntp++) {
                uint32_t bb[4];
                LDSM4T(bb, bsb[cur] +
                           ((kb + nt_ro) * 136 + wn + ntp * 16 + nt_co) * 2);
                MMA_BF16(acc[0][2 * ntp],     af[0], bb[0], bb[1]);
                MMA_BF16(acc[1][2 * ntp],     af[1], bb[0], bb[1]);
                MMA_BF16(acc[0][2 * ntp + 1], af[0], bb[2], bb[3]);
                MMA_BF16(acc[1][2 * ntp + 1], af[1], bb[2], bb[3]);
            }
        }
        if (nxt) QKV_STORE(cur ^ 1);
        __syncthreads();
    }

#pragma unroll
    for (int mt = 0; mt < 2; mt++) {
        int r0 = m0 + wm + mt * 16 + gid;
        int r1 = r0 + 8;
        float bv0 = bias[r0], bv1 = bias[r1];
#pragma unroll
        for (int nt = 0; nt < 8; nt++) {
            int col = n0 + wn + nt * 8 + tg * 2;
            ((uint32_t*)Cp)[((size_t)r0 * N + col) >> 1] =
                pk(acc[mt][nt][0] + bv0, acc[mt][nt][1] + bv0);
            ((uint32_t*)Cp)[((size_t)r1 * N + col) >> 1] =
                pk(acc[mt][nt][2] + bv1, acc[mt][nt][3] + bv1);
        }
    }
}

// ---------------------------------------------------------------------------
// Out-proj GEMM: C = w_out_bf16 @ att_bf16 + bias + resid(x). Raw B copies.
// ---------------------------------------------------------------------------
__global__ __launch_bounds__(256) void gemm_out_kernel(
    const uint32_t* __restrict__ Awp, const __nv_bfloat16* __restrict__ Bm,
    const float* __restrict__ bias, const float* __restrict__ resid,
    float* __restrict__ C, int M, int N, int K) {
    __shared__ uint32_t As[2][128 * APW];
    __shared__ uint32_t Bs[2][32 * BPW];

    int tid  = threadIdx.x;
    int warp = tid >> 5, lane = tid & 31;
    int gid = lane >> 2, tg = lane & 3;
    int g8 = lane >> 3, lr = lane & 7;
    int wm = (warp >> 1) * 32, wn = (warp & 1) * 64;
    int m0 = blockIdx.y * 128, n0 = blockIdx.x * 128;

    const uint32_t* Bw = (const uint32_t*)(Bm + (size_t)blockIdx.z * K * N);
    float* Cp       = C + (size_t)blockIdx.z * M * N;
    const float* Rp = resid + (size_t)blockIdx.z * M * N;

    uint32_t asb[2] = {(uint32_t)__cvta_generic_to_shared(&As[0][0]),
                       (uint32_t)__cvta_generic_to_shared(&As[1][0])};
    uint32_t bsb[2] = {(uint32_t)__cvta_generic_to_shared(&Bs[0][0]),
                       (uint32_t)__cvta_generic_to_shared(&Bs[1][0])};

    int nt_ro = (g8 & 1) * 8 + lr;
    int nt_co = (g8 >> 1) * 8;
    uint32_t a_off[2];
#pragma unroll
    for (int mt = 0; mt < 2; mt++)
        a_off[mt] = ((wm + mt * 16 + nt_ro) * 40 + nt_co) * 2;

    float acc[2][8][4];
#pragma unroll
    for (int mt = 0; mt < 2; mt++)
#pragma unroll
        for (int nt = 0; nt < 8; nt++)
#pragma unroll
            for (int e = 0; e < 4; e++) acc[mt][nt][e] = 0.f;

    uint4 pa[2], pb[2];

#define OUT_LOAD(k0)                                                         \
    {                                                                        \
        _Pragma("unroll") for (int l = 0; l < 2; l++) {                      \
            int slot = tid + l * 256;                                        \
            int row = slot >> 2, c8 = (slot & 3) * 8;                        \
            pa[l] = *(const uint4*)&Awp[(size_t)(m0 + row) * (K >> 1) +      \
                                        (((k0) + c8) >> 1)];                 \
        }                                                                    \
        _Pragma("unroll") for (int l = 0; l < 2; l++) {                      \
            int slot = tid + l * 256;                                        \
            int kk2 = slot >> 4, n8 = (slot & 15) * 8;                       \
            pb[l] = *(const uint4*)&Bw[((size_t)((k0) + kk2) * N + n0 + n8)  \
                                       >> 1];                                \
        }                                                                    \
    }
#define OUT_STORE(buf)                                                       \
    {                                                                        \
        _Pragma("unroll") for (int l = 0; l < 2; l++) {                      \
            int slot = tid + l * 256;                                        \
            int row = slot >> 2, c4 = (slot & 3) * 4;                        \
            *(uint4*)&As[buf][row * APW + c4] = pa[l];                       \
        }                                                                    \
        _Pragma("unroll") for (int l = 0; l < 2; l++) {                      \
            int slot = tid + l * 256;                                        \
            int kk2 = slot >> 4, n4 = (slot & 15) * 4;                       \
            *(uint4*)&Bs[buf][kk2 * BPW + n4] = pb[l];                       \
        }                                                                    \
    }

    OUT_LOAD(0);
    OUT_STORE(0);
    __syncthreads();

    for (int k0 = 0; k0 < K; k0 += 32) {
        int cur = (k0 >> 5) & 1;
        bool nxt = (k0 + 32) < K;
        if (nxt) OUT_LOAD(k0 + 32);

#pragma unroll
        for (int kk = 0; kk < 2; kk++) {
            int kb = kk * 16;
            uint32_t af[2][4];
            LDSM4(af[0], asb[cur] + a_off[0] + kb * 2);
            LDSM4(af[1], asb[cur] + a_off[1] + kb * 2);
#pragma unroll
            for (int ntp = 0; ntp < 4; ntp++) {
                uint32_t bb[4];
                LDSM4T(bb, bsb[cur] +
                           ((kb + nt_ro) * 136 + wn + ntp * 16 + nt_co) * 2);
                MMA_BF16(acc[0][2 * ntp],     af[0], bb[0], bb[1]);
                MMA_BF16(acc[1][2 * ntp],     af[1], bb[0], bb[1]);
                MMA_BF16(acc[0][2 * ntp + 1], af[0], bb[2], bb[3]);
                MMA_BF16(acc[1][2 * ntp + 1], af[1], bb[2], bb[3]);
            }
        }
        if (nxt) OUT_STORE(cur ^ 1);
        __syncthreads();
    }

#pragma unroll
    for (int mt = 0; mt < 2; mt++) {
        int r0 = m0 + wm + mt * 16 + gid;
        int r1 = r0 + 8;
        float bv0 = bias[r0], bv1 = bias[r1];
#pragma unroll
        for (int nt = 0; nt < 8; nt++) {
            int col = n0 + wn + nt * 8 + tg * 2;
            float2 v0, v1;
            v0.x = acc[mt][nt][0] + bv0; v0.y = acc[mt][nt][1] + bv0;
            v1.x = acc[mt][nt][2] + bv1; v1.y = acc[mt][nt][3] + bv1;
            float2 q0 = *(const float2*)&Rp[(size_t)r0 * N + col];
            float2 q1 = *(const float2*)&Rp[(size_t)r1 * N + col];
            v0.x += q0.x; v0.y += q0.y;
            v1.x += q1.x; v1.y += q1.y;
            *(float2*)&Cp[(size_t)r0 * N + col] = v0;
            *(float2*)&Cp[(size_t)r1 * N + col] = v1;
        }
    }
}

// ---------------------------------------------------------------------------
// BF16 flash attention — natural [c][spatial] smem layouts + ldmatrix.
// qs/ks/vs: 64 rows x 128 halves, pitch 136 halves (raw uint4 copies).
// p_s: [q][k2] words, pitch 68 words (unchanged).
// ---------------------------------------------------------------------------
#define QPW 68   // words per row for qs/ks/vs and p_s
#define ATTN_WORDS (5 * 64 * QPW + 128 * QPW)
#define ATTN_SMEM_BYTES (ATTN_WORDS * 4)

__global__ __launch_bounds__(256, 1) void attn_bf16_kernel(
    const __nv_bfloat16* __restrict__ qkv, __nv_bfloat16* __restrict__ out) {
    extern __shared__ uint32_t smw[];
    uint32_t* qs  = smw;                        // [c 64][q 128h]
    uint32_t* ks0 = qs + 64 * QPW;
    uint32_t* ks1 = ks0 + 64 * QPW;
    uint32_t* vs0 = ks1 + 64 * QPW;
    uint32_t* vs1 = vs0 + 64 * QPW;
    uint32_t* p_s = vs1 + 64 * QPW;             // [q 128][k2 64] words
    __shared__ float corr_s[8][16];
    __shared__ float l_s[8][16];

    int tid  = threadIdx.x;
    int warp = tid >> 5, lane = tid & 31;
    int gid = lane >> 2, tg = lane & 3;
    int g8 = lane >> 3, lr = lane & 7;
    int wm = warp * 16;
    int qt = blockIdx.x * 128;
    int hn = blockIdx.y, b = blockIdx.z;

    const __nv_bfloat16* qg = qkv + ((size_t)b * 3 * CH + hn * HDIM) * SP;
    const __nv_bfloat16* kg = qg + (size_t)CH * SP;
    const __nv_bfloat16* vg = kg + (size_t)CH * SP;
    __nv_bfloat16* og = out + ((size_t)b * CH + hn * HDIM) * SP;

    const float SC = 0.125f * 1.44269504088896f;

    uint32_t qsb = (uint32_t)__cvta_generic_to_shared(qs);
    uint32_t ksbu[2] = {(uint32_t)__cvta_generic_to_shared(ks0),
                        (uint32_t)__cvta_generic_to_shared(ks1)};
    uint32_t vsbu[2] = {(uint32_t)__cvta_generic_to_shared(vs0),
                        (uint32_t)__cvta_generic_to_shared(vs1)};
    uint32_t* ksb[2] = {ks0, ks1};
    uint32_t* vsb[2] = {vs0, vs1};

    // ldmatrix lane offsets
    int nt_ro = (g8 & 1) * 8 + lr;   // K(trans rows c) / V(rows c)
    int nt_co = (g8 >> 1) * 8;
    int qa_ro = (g8 >> 1) * 8 + lr;  // Q trans rows c
    int qa_co = (g8 & 1) * 8;

    // Q tile: raw copy (4 uint4/thread)
    const uint32_t* qw = (const uint32_t*)qg;
#pragma unroll
    for (int l = 0; l < 4; l++) {
        int slot = tid + l * 256;
        int row = slot >> 4, h8 = (slot & 15) * 8;
        *(uint4*)&qs[row * QPW + (slot & 15) * 4] =
            *(const uint4*)&qw[((size_t)row * SP + qt + h8) >> 1];
    }

    uint4 kp[4], vp[4];
    const uint32_t* kw = (const uint32_t*)kg;
    const uint32_t* vw = (const uint32_t*)vg;

#define ATTN_PREFETCH(kt)                                                    \
    {                                                                        \
        _Pragma("unroll") for (int l = 0; l < 4; l++) {                      \
            int slot = tid + l * 256;                                        \
            int row = slot >> 4, h8 = (slot & 15) * 8;                       \
            kp[l] = *(const uint4*)&kw[((size_t)row * SP + (kt) + h8) >> 1]; \
            vp[l] = *(const uint4*)&vw[((size_t)row * SP + (kt) + h8) >> 1]; \
        }                                                                    \
    }
#define ATTN_STORE(buf)                                                      \
    {                                                                        \
        _Pragma("unroll") for (int l = 0; l < 4; l++) {                      \
            int slot = tid + l * 256;                                        \
            int row = slot >> 4, w4 = (slot & 15) * 4;                       \
            *(uint4*)&ksb[buf][row * QPW + w4] = kp[l];                      \
            *(uint4*)&vsb[buf][row * QPW + w4] = vp[l];                      \
        }                                                                    \
    }

    ATTN_PREFETCH(0);
    ATTN_STORE(0);
    __syncthreads();

    float m_run0 = -INFINITY, m_run1 = -INFINITY;
    float l_run0 = 0.f, l_run1 = 0.f;

    float acc_o[4][2][4];
#pragma unroll
    for (int mt = 0; mt < 4; mt++)
#pragma unroll
        for (int nq = 0; nq < 2; nq++)
#pragma unroll
            for (int e = 0; e < 4; e++) acc_o[mt][nq][e] = 0.f;

    for (int it = 0; it < SP / 128; it++) {
        int cur = it & 1;
        bool nxt = it < SP / 128 - 1;
        if (nxt) ATTN_PREFETCH((it + 1) * 128);

        // ---- Phase 1: S[q16][k128] ----
        float acc_s[16][4];
#pragma unroll
        for (int nt = 0; nt < 16; nt++)
#pragma unroll
            for (int e = 0; e < 4; e++) acc_s[nt][e] = 0.f;

#pragma unroll
        for (int cc = 0; cc < 4; cc++) {
            int cb = cc * 16;   // c halves
            uint32_t af[4];
            LDSM4T(af, qsb + ((cb + qa_ro) * 136 + wm + qa_co) * 2);
#pragma unroll
            for (int ntp = 0; ntp < 8; ntp++) {
                uint32_t bb[4];
                LDSM4T(bb, ksbu[cur] +
                           ((cb + nt_ro) * 136 + ntp * 16 + nt_co) * 2);
                MMA_BF16(acc_s[2 * ntp],     af, bb[0], bb[1]);
                MMA_BF16(acc_s[2 * ntp + 1], af, bb[2], bb[3]);
            }
        }

        // ---- Online softmax (exp2 domain) ----
        float mx0 = -INFINITY, mx1 = -INFINITY;
#pragma unroll
        for (int nt = 0; nt < 16; nt++) {
            acc_s[nt][0] *= SC; acc_s[nt][1] *= SC;
            acc_s[nt][2] *= SC; acc_s[nt][3] *= SC;
            mx0 = fmaxf(mx0, fmaxf(acc_s[nt][0], acc_s[nt][1]));
            mx1 = fmaxf(mx1, fmaxf(acc_s[nt][2], acc_s[nt][3]));
        }
        mx0 = fmaxf(mx0, __shfl_xor_sync(0xffffffffu, mx0, 1));
        mx0 = fmaxf(mx0, __shfl_xor_sync(0xffffffffu, mx0, 2));
        mx1 = fmaxf(mx1, __shfl_xor_sync(0xffffffffu, mx1, 1));
        mx1 = fmaxf(mx1, __shfl_xor_sync(0xffffffffu, mx1, 2));

        float mnew0 = fmaxf(m_run0, mx0);
        float mnew1 = fmaxf(m_run1, mx1);
        float corr0 = exp2f(m_run0 - mnew0);
        float corr1 = exp2f(m_run1 - mnew1);

        float ps0 = 0.f, ps1 = 0.f;
#pragma unroll
        for (int nt = 0; nt < 16; nt++) {
            float p0 = exp2f(acc_s[nt][0] - mnew0);
            float p1 = exp2f(acc_s[nt][1] - mnew0);
            float p2 = exp2f(acc_s[nt][2] - mnew1);
            float p3 = exp2f(acc_s[nt][3] - mnew1);
            ps0 += p0 + p1; ps1 += p2 + p3;
            p_s[(wm + gid) * QPW + nt * 4 + tg]     = pk(p0, p1);
            p_s[(wm + gid + 8) * QPW + nt * 4 + tg] = pk(p2, p3);
        }
        ps0 += __shfl_xor_sync(0xffffffffu, ps0, 1);
        ps0 += __shfl_xor_sync(0xffffffffu, ps0, 2);
        ps1 += __shfl_xor_sync(0xffffffffu, ps1, 1);
        ps1 += __shfl_xor_sync(0xffffffffu, ps1, 2);
        l_run0 = l_run0 * corr0 + ps0;
        l_run1 = l_run1 * corr1 + ps1;
        m_run0 = mnew0; m_run1 = mnew1;
        if (tg == 0) {
            corr_s[warp][gid] = corr0;
            corr_s[warp][gid + 8] = corr1;
        }
        __syncwarp();

#pragma unroll
        for (int nq = 0; nq < 2; nq++) {
            float cc0 = corr_s[warp][nq * 8 + 2 * tg];
            float cc1 = corr_s[warp][nq * 8 + 2 * tg + 1];
#pragma unroll
            for (int mt = 0; mt < 4; mt++) {
                acc_o[mt][nq][0] *= cc0; acc_o[mt][nq][1] *= cc1;
                acc_o[mt][nq][2] *= cc0; acc_o[mt][nq][3] *= cc1;
            }
        }

        // ---- Phase 2: O^T[c64][q16] += V @ P^T ----
#pragma unroll
        for (int kc = 0; kc < 8; kc++) {
            int kb = kc * 16;   // k halves
            uint32_t bq[2][2];
#pragma unroll
            for (int nq = 0; nq < 2; nq++) {
                bq[nq][0] = p_s[(wm + nq * 8 + gid) * QPW + (kb >> 1) + tg];
                bq[nq][1] = p_s[(wm + nq * 8 + gid) * QPW + (kb >> 1) + tg + 4];
            }
#pragma unroll
            for (int mt = 0; mt < 4; mt++) {
                uint32_t af[4];
                LDSM4(af, vsbu[cur] +
                          ((mt * 16 + nt_ro) * 136 + kb + nt_co) * 2);
                MMA_BF16(acc_o[mt][0], af, bq[0][0], bq[0][1]);
                MMA_BF16(acc_o[mt][1], af, bq[1][0], bq[1][1]);
            }
        }

        if (nxt) ATTN_STORE(cur ^ 1);
        __syncthreads();
    }

    if (tg == 0) {
        l_s[warp][gid] = l_run0;
        l_s[warp][gid + 8] = l_run1;
    }
    __syncwarp();

#pragma unroll
    for (int nq = 0; nq < 2; nq++) {
        float il0 = 1.f / l_s[warp][nq * 8 + 2 * tg];
        float il1 = 1.f / l_s[warp][nq * 8 + 2 * tg + 1];
        int s = qt + wm + nq * 8 + 2 * tg;
#pragma unroll
        for (int mt = 0; mt < 4; mt++) {
            int c0r = mt * 16 + gid;
            ((uint32_t*)og)[((size_t)c0r * SP + s) >> 1] =
                pk(acc_o[mt][nq][0] * il0, acc_o[mt][nq][1] * il1);
            ((uint32_t*)og)[((size_t)(c0r + 8) * SP + s) >> 1] =
                pk(acc_o[mt][nq][2] * il0, acc_o[mt][nq][3] * il1);
        }
    }
}

// ---------------------------------------------------------------------------
extern "C" void kernel_launch(void* const* d_in, const int* in_sizes, int n_in,
                              void* d_out, int out_size) {
    const float* x     = (const float*)d_in[0];
    const float* gamma = (const float*)d_in[1];
    const float* beta  = (const float*)d_in[2];
    const float* w_in  = (const float*)d_in[3];
    const float* b_in  = (const float*)d_in[4];
    const float* w_out = (const float*)d_in[5];
    const float* b_out = (const float*)d_in[6];
    float* out = (float*)d_out;

    __nv_bfloat16 *qkv, *att;
    float *sc, *sh;
    uint32_t *winp, *woutp;
    cudaGetSymbolAddress((void**)&qkv,   g_qkv);
    cudaGetSymbolAddress((void**)&att,   g_att);
    cudaGetSymbolAddress((void**)&sc,    g_scale);
    cudaGetSymbolAddress((void**)&sh,    g_shift);
    cudaGetSymbolAddress((void**)&winp,  g_winp);
    cudaGetSymbolAddress((void**)&woutp, g_woutp);

    // 0. Weight prepack (bf16 row-major)
    prepack_kernel<<<(3 * CH * CH / 2 + 255) / 256, 256>>>(w_in, winp,
                                                           3 * CH * CH / 2);
    prepack_kernel<<<(CH * CH / 2 + 255) / 256, 256>>>(w_out, woutp,
                                                       CH * CH / 2);

    // 1. GroupNorm stats
    gn_stats_kernel<<<BATCH * NGRP, 256>>>(x, gamma, beta, sc, sh);

    // 2. QKV projection (fused GN, bf16 out, ldmatrix)
    gemm_qkv_kernel<<<dim3(SP / 128, (3 * CH) / 128, BATCH), 256>>>(
        winp, x, sc, sh, b_in, qkv, 3 * CH, SP, CH);

    // 3. Attention (raw-copy tiles + ldmatrix)
    cudaFuncSetAttribute(attn_bf16_kernel, cudaFuncAttributeMaxDynamicSharedMemorySize,
                         ATTN_SMEM_BYTES);
    attn_bf16_kernel<<<dim3(SP / 128, NHEAD, BATCH), 256, ATTN_SMEM_BYTES>>>(qkv, att);

    // 4. Output projection + bias + residual
    gemm_out_kernel<<<dim3(SP / 128, CH / 128, BATCH), 256>>>(
        woutp, att, b_out, x, out, CH, SP, CH);
}

// round 12
// speedup vs baseline: 5.9098x; 1.0893x over previous
#include <cuda_runtime.h>
#include <cuda_bf16.h>
#include <math.h>
#include <stdint.h>

// Problem constants
#define BATCH 8
#define CH    512
#define SP    1024      // H*W = 32*32
#define NHEAD 8
#define HDIM  64
#define NGRP  32
#define GCH   16        // channels per group

// Scratch (device globals: allocation-free per harness rules)
__device__ __nv_bfloat16 g_h[BATCH * CH * SP];        // groupnorm out (bf16)
__device__ __nv_bfloat16 g_qkv[BATCH * 3 * CH * SP];  // qkv (bf16)
__device__ __nv_bfloat16 g_att[BATCH * CH * SP];      // attention out (bf16)
__device__ uint32_t g_winp[(3 * CH) * (CH / 2)];      // bf16 w_in  [M][K]
__device__ uint32_t g_woutp[CH * (CH / 2)];           // bf16 w_out [M][K]

// ---------------------------------------------------------------------------
// Helpers
// ---------------------------------------------------------------------------
__device__ __forceinline__ uint32_t pk(float lo, float hi) {
    uint32_t r;
    asm("cvt.rn.bf16x2.f32 %0, %1, %2;" : "=r"(r) : "f"(hi), "f"(lo));
    return r;
}

#define MMA_BF16(d, a, b0, b1)                                              \
    asm volatile(                                                           \
        "mma.sync.aligned.m16n8k16.row.col.f32.bf16.bf16.f32 "              \
        "{%0,%1,%2,%3}, {%4,%5,%6,%7}, {%8,%9}, {%0,%1,%2,%3};"             \
        : "+f"(d[0]), "+f"(d[1]), "+f"(d[2]), "+f"(d[3])                    \
        : "r"(a[0]), "r"(a[1]), "r"(a[2]), "r"(a[3]), "r"(b0), "r"(b1))

#define LDSM4(d, addr)                                                      \
    asm volatile("ldmatrix.sync.aligned.m8n8.x4.shared.b16 "                \
                 "{%0,%1,%2,%3}, [%4];"                                     \
                 : "=r"((d)[0]), "=r"((d)[1]), "=r"((d)[2]), "=r"((d)[3])   \
                 : "r"(addr))

#define LDSM4T(d, addr)                                                     \
    asm volatile("ldmatrix.sync.aligned.m8n8.x4.trans.shared.b16 "          \
                 "{%0,%1,%2,%3}, [%4];"                                     \
                 : "=r"((d)[0]), "=r"((d)[1]), "=r"((d)[2]), "=r"((d)[3])   \
                 : "r"(addr))

#define CPA16(dst, src)                                                     \
    asm volatile("cp.async.cg.shared.global [%0], [%1], 16;"                \
                 :: "r"(dst), "l"(src))
#define CPA_COMMIT() asm volatile("cp.async.commit_group;")
#define CPA_WAIT0()  asm volatile("cp.async.wait_group 0;" ::: "memory")

// ---------------------------------------------------------------------------
// Weight prepack: fp32 [M][K] -> bf16 [M][K]
// ---------------------------------------------------------------------------
__global__ __launch_bounds__(256) void prepack_kernel(
    const float* __restrict__ w, uint32_t* __restrict__ wp, int nwords) {
    int i = blockIdx.x * 256 + threadIdx.x;
    if (i < nwords) {
        float2 v = *(const float2*)&w[2 * i];
        wp[i] = pk(v.x, v.y);
    }
}

// ---------------------------------------------------------------------------
// GroupNorm: stats + normalize, writes h bf16. One block per (batch, group).
// ---------------------------------------------------------------------------
__global__ void gn_kernel(const float* __restrict__ x,
                          const float* __restrict__ gamma,
                          const float* __restrict__ beta,
                          uint32_t* __restrict__ hw_all) {
    int b = blockIdx.x >> 5;
    int g = blockIdx.x & 31;
    const float* xp = x + ((size_t)b * CH + g * GCH) * SP;
    uint32_t* hw = hw_all + (((size_t)b * CH + g * GCH) * SP >> 1);
    int t = threadIdx.x;

    float sum = 0.f, sq = 0.f;
    for (int i4 = t; i4 < GCH * SP / 4; i4 += 256) {
        float4 v = *(const float4*)(xp + i4 * 4);
        sum += v.x + v.y + v.z + v.w;
        sq  += v.x * v.x + v.y * v.y + v.z * v.z + v.w * v.w;
    }
    __shared__ float s1[256], s2[256];
    s1[t] = sum; s2[t] = sq;
    __syncthreads();
    for (int off = 128; off > 0; off >>= 1) {
        if (t < off) { s1[t] += s1[t + off]; s2[t] += s2[t + off]; }
        __syncthreads();
    }
    const float invN = 1.f / (GCH * SP);
    float mean = s1[0] * invN;
    float var  = s2[0] * invN - mean * mean;
    float inv  = rsqrtf(var + 1e-6f);

    for (int i4 = t; i4 < GCH * SP / 4; i4 += 256) {
        int c = i4 >> 8;
        float sc = inv * gamma[g * GCH + c];
        float sh = beta[g * GCH + c] - mean * sc;
        float4 v = *(const float4*)(xp + i4 * 4);
        uint2 u;
        u.x = pk(v.x * sc + sh, v.y * sc + sh);
        u.y = pk(v.z * sc + sh, v.w * sc + sh);
        *(uint2*)&hw[i4 * 2] = u;
    }
}

// ---------------------------------------------------------------------------
// Templated GEMM (both projections):
//   MODE 0: C bf16 = A@B + bias          (QKV)
//   MODE 1: C fp32 = A@B + bias + resid  (out-proj)
//   As: [m 128][k 32 halves] pitch 40 halves (20 words) -> non-trans ldmatrix
//   Bs: [k 32][n 128 halves] pitch 136 halves (68 words) -> trans ldmatrix
// Block 128x128, K-tile 32, cp.async double-buffered, 8 warps (32x64 tiles).
// ---------------------------------------------------------------------------
#define APW 20
#define BPW 68

template <int MODE>
__global__ __launch_bounds__(256, 2) void gemm_kernel(
    const uint32_t* __restrict__ Awp, const __nv_bfloat16* __restrict__ Bm,
    const float* __restrict__ bias, const float* __restrict__ resid,
    void* __restrict__ Cv, int M, int N, int K) {
    __shared__ uint32_t As[2][128 * APW];
    __shared__ uint32_t Bs[2][32 * BPW];

    int tid  = threadIdx.x;
    int warp = tid >> 5, lane = tid & 31;
    int gid = lane >> 2, tg = lane & 3;
    int g8 = lane >> 3, lr = lane & 7;
    int wm = (warp >> 1) * 32, wn = (warp & 1) * 64;
    int m0 = blockIdx.y * 128, n0 = blockIdx.x * 128;

    const uint32_t* Bw = (const uint32_t*)(Bm + (size_t)blockIdx.z * K * N);

    uint32_t asb[2] = {(uint32_t)__cvta_generic_to_shared(&As[0][0]),
                       (uint32_t)__cvta_generic_to_shared(&As[1][0])};
    uint32_t bsb[2] = {(uint32_t)__cvta_generic_to_shared(&Bs[0][0]),
                       (uint32_t)__cvta_generic_to_shared(&Bs[1][0])};

    int nt_ro = (g8 & 1) * 8 + lr;
    int nt_co = (g8 >> 1) * 8;
    uint32_t a_off[2];
#pragma unroll
    for (int mt = 0; mt < 2; mt++)
        a_off[mt] = ((wm + mt * 16 + nt_ro) * 40 + nt_co) * 2;

    float acc[2][8][4];
#pragma unroll
    for (int mt = 0; mt < 2; mt++)
#pragma unroll
        for (int nt = 0; nt < 8; nt++)
#pragma unroll
            for (int e = 0; e < 4; e++) acc[mt][nt][e] = 0.f;

    auto issue_tile = [&](int buf, int k0) {
#pragma unroll
        for (int l = 0; l < 2; l++) {
            int slot = tid + l * 256;
            int row = slot >> 2, c8 = (slot & 3) * 8, c4 = (slot & 3) * 4;
            CPA16(asb[buf] + (row * APW + c4) * 4,
                  &Awp[(size_t)(m0 + row) * (K >> 1) + ((k0 + c8) >> 1)]);
        }
#pragma unroll
        for (int l = 0; l < 2; l++) {
            int slot = tid + l * 256;
            int kk2 = slot >> 4, n8 = (slot & 15) * 8, n4 = (slot & 15) * 4;
            CPA16(bsb[buf] + (kk2 * BPW + n4) * 4,
                  &Bw[((size_t)(k0 + kk2) * N + n0 + n8) >> 1]);
        }
        CPA_COMMIT();
    };

    issue_tile(0, 0);
    CPA_WAIT0();
    __syncthreads();

    for (int k0 = 0; k0 < K; k0 += 32) {
        int cur = (k0 >> 5) & 1;
        bool nxt = (k0 + 32) < K;
        if (nxt) issue_tile(cur ^ 1, k0 + 32);

#pragma unroll
        for (int kk = 0; kk < 2; kk++) {
            int kb = kk * 16;
            uint32_t af[2][4];
            LDSM4(af[0], asb[cur] + a_off[0] + kb * 2);
            LDSM4(af[1], asb[cur] + a_off[1] + kb * 2);
#pragma unroll
            for (int ntp = 0; ntp < 4; ntp++) {
                uint32_t bb[4];
                LDSM4T(bb, bsb[cur] +
                           ((kb + nt_ro) * 136 + wn + ntp * 16 + nt_co) * 2);
                MMA_BF16(acc[0][2 * ntp],     af[0], bb[0], bb[1]);
                MMA_BF16(acc[1][2 * ntp],     af[1], bb[0], bb[1]);
                MMA_BF16(acc[0][2 * ntp + 1], af[0], bb[2], bb[3]);
                MMA_BF16(acc[1][2 * ntp + 1], af[1], bb[2], bb[3]);
            }
        }
        CPA_WAIT0();
        __syncthreads();
    }

    if (MODE == 0) {
        __nv_bfloat16* Cp = (__nv_bfloat16*)Cv + (size_t)blockIdx.z * M * N;
#pragma unroll
        for (int mt = 0; mt < 2; mt++) {
            int r0 = m0 + wm + mt * 16 + gid;
            int r1 = r0 + 8;
            float bv0 = bias[r0], bv1 = bias[r1];
#pragma unroll
            for (int nt = 0; nt < 8; nt++) {
                int col = n0 + wn + nt * 8 + tg * 2;
                ((uint32_t*)Cp)[((size_t)r0 * N + col) >> 1] =
                    pk(acc[mt][nt][0] + bv0, acc[mt][nt][1] + bv0);
                ((uint32_t*)Cp)[((size_t)r1 * N + col) >> 1] =
                    pk(acc[mt][nt][2] + bv1, acc[mt][nt][3] + bv1);
            }
        }
    } else {
        float* Cp       = (float*)Cv + (size_t)blockIdx.z * M * N;
        const float* Rp = resid + (size_t)blockIdx.z * M * N;
#pragma unroll
        for (int mt = 0; mt < 2; mt++) {
            int r0 = m0 + wm + mt * 16 + gid;
            int r1 = r0 + 8;
            float bv0 = bias[r0], bv1 = bias[r1];
#pragma unroll
            for (int nt = 0; nt < 8; nt++) {
                int col = n0 + wn + nt * 8 + tg * 2;
                float2 v0, v1;
                v0.x = acc[mt][nt][0] + bv0; v0.y = acc[mt][nt][1] + bv0;
                v1.x = acc[mt][nt][2] + bv1; v1.y = acc[mt][nt][3] + bv1;
                float2 q0 = *(const float2*)&Rp[(size_t)r0 * N + col];
                float2 q1 = *(const float2*)&Rp[(size_t)r1 * N + col];
                v0.x += q0.x; v0.y += q0.y;
                v1.x += q1.x; v1.y += q1.y;
                *(float2*)&Cp[(size_t)r0 * N + col] = v0;
                *(float2*)&Cp[(size_t)r1 * N + col] = v1;
            }
        }
    }
}

// ---------------------------------------------------------------------------
// BF16 flash attention — cp.async tile loads, ldmatrix fragments.
// qs/ks/vs: [c 64][sp 128 halves] pitch 136 halves; p_s [q 128][k2 64] words.
// ---------------------------------------------------------------------------
#define QPW 68
#define ATTN_WORDS (5 * 64 * QPW + 128 * QPW)
#define ATTN_SMEM_BYTES (ATTN_WORDS * 4)

__global__ __launch_bounds__(256, 1) void attn_bf16_kernel(
    const __nv_bfloat16* __restrict__ qkv, __nv_bfloat16* __restrict__ out) {
    extern __shared__ uint32_t smw[];
    uint32_t* qs  = smw;
    uint32_t* ks0 = qs + 64 * QPW;
    uint32_t* ks1 = ks0 + 64 * QPW;
    uint32_t* vs0 = ks1 + 64 * QPW;
    uint32_t* vs1 = vs0 + 64 * QPW;
    uint32_t* p_s = vs1 + 64 * QPW;
    __shared__ float corr_s[8][16];
    __shared__ float l_s[8][16];

    int tid  = threadIdx.x;
    int warp = tid >> 5, lane = tid & 31;
    int gid = lane >> 2, tg = lane & 3;
    int g8 = lane >> 3, lr = lane & 7;
    int wm = warp * 16;
    int qt = blockIdx.x * 128;
    int hn = blockIdx.y, b = blockIdx.z;

    const __nv_bfloat16* qg = qkv + ((size_t)b * 3 * CH + hn * HDIM) * SP;
    const __nv_bfloat16* kg = qg + (size_t)CH * SP;
    const __nv_bfloat16* vg = kg + (size_t)CH * SP;
    __nv_bfloat16* og = out + ((size_t)b * CH + hn * HDIM) * SP;

    const float SC = 0.125f * 1.44269504088896f;

    uint32_t qsb = (uint32_t)__cvta_generic_to_shared(qs);
    uint32_t ksbu[2] = {(uint32_t)__cvta_generic_to_shared(ks0),
                        (uint32_t)__cvta_generic_to_shared(ks1)};
    uint32_t vsbu[2] = {(uint32_t)__cvta_generic_to_shared(vs0),
                        (uint32_t)__cvta_generic_to_shared(vs1)};

    int nt_ro = (g8 & 1) * 8 + lr;
    int nt_co = (g8 >> 1) * 8;
    int qa_ro = (g8 >> 1) * 8 + lr;
    int qa_co = (g8 & 1) * 8;

    const uint32_t* qw = (const uint32_t*)qg;
    const uint32_t* kw = (const uint32_t*)kg;
    const uint32_t* vw = (const uint32_t*)vg;

    auto issue_kv = [&](int buf, int kt) {
#pragma unroll
        for (int l = 0; l < 4; l++) {
            int slot = tid + l * 256;
            int row = slot >> 4, h8 = (slot & 15) * 8, w4 = (slot & 15) * 4;
            CPA16(ksbu[buf] + (row * QPW + w4) * 4,
                  &kw[((size_t)row * SP + kt + h8) >> 1]);
            CPA16(vsbu[buf] + (row * QPW + w4) * 4,
                  &vw[((size_t)row * SP + kt + h8) >> 1]);
        }
        CPA_COMMIT();
    };

    // Q tile + K/V tile 0 in one group
#pragma unroll
    for (int l = 0; l < 4; l++) {
        int slot = tid + l * 256;
        int row = slot >> 4, h8 = (slot & 15) * 8, w4 = (slot & 15) * 4;
        CPA16(qsb + (row * QPW + w4) * 4,
              &qw[((size_t)row * SP + qt + h8) >> 1]);
    }
    issue_kv(0, 0);
    CPA_WAIT0();
    __syncthreads();

    float m_run0 = -INFINITY, m_run1 = -INFINITY;
    float l_run0 = 0.f, l_run1 = 0.f;

    float acc_o[4][2][4];
#pragma unroll
    for (int mt = 0; mt < 4; mt++)
#pragma unroll
        for (int nq = 0; nq < 2; nq++)
#pragma unroll
            for (int e = 0; e < 4; e++) acc_o[mt][nq][e] = 0.f;

    for (int it = 0; it < SP / 128; it++) {
        int cur = it & 1;
        bool nxt = it < SP / 128 - 1;
        if (nxt) issue_kv(cur ^ 1, (it + 1) * 128);

        // ---- Phase 1: S[q16][k128] ----
        float acc_s[16][4];
#pragma unroll
        for (int nt = 0; nt < 16; nt++)
#pragma unroll
            for (int e = 0; e < 4; e++) acc_s[nt][e] = 0.f;

#pragma unroll
        for (int cc = 0; cc < 4; cc++) {
            int cb = cc * 16;
            uint32_t af[4];
            LDSM4T(af, qsb + ((cb + qa_ro) * 136 + wm + qa_co) * 2);
#pragma unroll
            for (int ntp = 0; ntp < 8; ntp++) {
                uint32_t bb[4];
                LDSM4T(bb, ksbu[cur] +
                           ((cb + nt_ro) * 136 + ntp * 16 + nt_co) * 2);
                MMA_BF16(acc_s[2 * ntp],     af, bb[0], bb[1]);
                MMA_BF16(acc_s[2 * ntp + 1], af, bb[2], bb[3]);
            }
        }

        // ---- Online softmax (exp2 domain) ----
        float mx0 = -INFINITY, mx1 = -INFINITY;
#pragma unroll
        for (int nt = 0; nt < 16; nt++) {
            acc_s[nt][0] *= SC; acc_s[nt][1] *= SC;
            acc_s[nt][2] *= SC; acc_s[nt][3] *= SC;
            mx0 = fmaxf(mx0, fmaxf(acc_s[nt][0], acc_s[nt][1]));
            mx1 = fmaxf(mx1, fmaxf(acc_s[nt][2], acc_s[nt][3]));
        }
        mx0 = fmaxf(mx0, __shfl_xor_sync(0xffffffffu, mx0, 1));
        mx0 = fmaxf(mx0, __shfl_xor_sync(0xffffffffu, mx0, 2));
        mx1 = fmaxf(mx1, __shfl_xor_sync(0xffffffffu, mx1, 1));
        mx1 = fmaxf(mx1, __shfl_xor_sync(0xffffffffu, mx1, 2));

        float mnew0 = fmaxf(m_run0, mx0);
        float mnew1 = fmaxf(m_run1, mx1);
        float corr0 = exp2f(m_run0 - mnew0);
        float corr1 = exp2f(m_run1 - mnew1);

        float ps0 = 0.f, ps1 = 0.f;
#pragma unroll
        for (int nt = 0; nt < 16; nt++) {
            float p0 = exp2f(acc_s[nt][0] - mnew0);
            float p1 = exp2f(acc_s[nt][1] - mnew0);
            float p2 = exp2f(acc_s[nt][2] - mnew1);
            float p3 = exp2f(acc_s[nt][3] - mnew1);
            ps0 += p0 + p1; ps1 += p2 + p3;
            p_s[(wm + gid) * QPW + nt * 4 + tg]     = pk(p0, p1);
            p_s[(wm + gid + 8) * QPW + nt * 4 + tg] = pk(p2, p3);
        }
        ps0 += __shfl_xor_sync(0xffffffffu, ps0, 1);
        ps0 += __shfl_xor_sync(0xffffffffu, ps0, 2);
        ps1 += __shfl_xor_sync(0xffffffffu, ps1, 1);
        ps1 += __shfl_xor_sync(0xffffffffu, ps1, 2);
        l_run0 = l_run0 * corr0 + ps0;
        l_run1 = l_run1 * corr1 + ps1;
        m_run0 = mnew0; m_run1 = mnew1;
        if (tg == 0) {
            corr_s[warp][gid] = corr0;
            corr_s[warp][gid + 8] = corr1;
        }
        __syncwarp();

#pragma unroll
        for (int nq = 0; nq < 2; nq++) {
            float cc0 = corr_s[warp][nq * 8 + 2 * tg];
            float cc1 = corr_s[warp][nq * 8 + 2 * tg + 1];
#pragma unroll
            for (int mt = 0; mt < 4; mt++) {
                acc_o[mt][nq][0] *= cc0; acc_o[mt][nq][1] *= cc1;
                acc_o[mt][nq][2] *= cc0; acc_o[mt][nq][3] *= cc1;
            }
        }

        // ---- Phase 2: O^T[c64][q16] += V @ P^T ----
#pragma unroll
        for (int kc = 0; kc < 8; kc++) {
            int kb = kc * 16;
            uint32_t bq[2][2];
#pragma unroll
            for (int nq = 0; nq < 2; nq++) {
                bq[nq][0] = p_s[(wm + nq * 8 + gid) * QPW + (kb >> 1) + tg];
                bq[nq][1] = p_s[(wm + nq * 8 + gid) * QPW + (kb >> 1) + tg + 4];
            }
#pragma unroll
            for (int mt = 0; mt < 4; mt++) {
                uint32_t af[4];
                LDSM4(af, vsbu[cur] +
                          ((mt * 16 + nt_ro) * 136 + kb + nt_co) * 2);
                MMA_BF16(acc_o[mt][0], af, bq[0][0], bq[0][1]);
                MMA_BF16(acc_o[mt][1], af, bq[1][0], bq[1][1]);
            }
        }

        CPA_WAIT0();
        __syncthreads();
    }

    if (tg == 0) {
        l_s[warp][gid] = l_run0;
        l_s[warp][gid + 8] = l_run1;
    }
    __syncwarp();

#pragma unroll
    for (int nq = 0; nq < 2; nq++) {
        float il0 = 1.f / l_s[warp][nq * 8 + 2 * tg];
        float il1 = 1.f / l_s[warp][nq * 8 + 2 * tg + 1];
        int s = qt + wm + nq * 8 + 2 * tg;
#pragma unroll
        for (int mt = 0; mt < 4; mt++) {
            int c0r = mt * 16 + gid;
            ((uint32_t*)og)[((size_t)c0r * SP + s) >> 1] =
                pk(acc_o[mt][nq][0] * il0, acc_o[mt][nq][1] * il1);
            ((uint32_t*)og)[((size_t)(c0r + 8) * SP + s) >> 1] =
                pk(acc_o[mt][nq][2] * il0, acc_o[mt][nq][3] * il1);
        }
    }
}

// ---------------------------------------------------------------------------
extern "C" void kernel_launch(void* const* d_in, const int* in_sizes, int n_in,
                              void* d_out, int out_size) {
    const float* x     = (const float*)d_in[0];
    const float* gamma = (const float*)d_in[1];
    const float* beta  = (const float*)d_in[2];
    const float* w_in  = (const float*)d_in[3];
    const float* b_in  = (const float*)d_in[4];
    const float* w_out = (const float*)d_in[5];
    const float* b_out = (const float*)d_in[6];
    float* out = (float*)d_out;

    __nv_bfloat16 *h, *qkv, *att;
    uint32_t *winp, *woutp;
    cudaGetSymbolAddress((void**)&h,     g_h);
    cudaGetSymbolAddress((void**)&qkv,   g_qkv);
    cudaGetSymbolAddress((void**)&att,   g_att);
    cudaGetSymbolAddress((void**)&winp,  g_winp);
    cudaGetSymbolAddress((void**)&woutp, g_woutp);

    // 0. Weight prepack (bf16 row-major)
    prepack_kernel<<<(3 * CH * CH / 2 + 255) / 256, 256>>>(w_in, winp,
                                                           3 * CH * CH / 2);
    prepack_kernel<<<(CH * CH / 2 + 255) / 256, 256>>>(w_out, woutp,
                                                       CH * CH / 2);

    // 1. GroupNorm -> h bf16
    gn_kernel<<<BATCH * NGRP, 256>>>(x, gamma, beta, (uint32_t*)h);

    // 2. QKV projection (raw bf16 B tiles, cp.async)
    gemm_kernel<0><<<dim3(SP / 128, (3 * CH) / 128, BATCH), 256>>>(
        winp, h, b_in, nullptr, qkv, 3 * CH, SP, CH);

    // 3. Attention (cp.async + ldmatrix)
    cudaFuncSetAttribute(attn_bf16_kernel, cudaFuncAttributeMaxDynamicSharedMemorySize,
                         ATTN_SMEM_BYTES);
    attn_bf16_kernel<<<dim3(SP / 128, NHEAD, BATCH), 256, ATTN_SMEM_BYTES>>>(qkv, att);

    // 4. Output projection + bias + residual
    gemm_kernel<1><<<dim3(SP / 128, CH / 128, BATCH), 256>>>(
        woutp, att, b_out, x, out, CH, SP, CH);
}

// round 15
// speedup vs baseline: 6.3073x; 1.0673x over previous
#include <cuda_runtime.h>
#include <cuda_bf16.h>
#include <math.h>
#include <stdint.h>

// Problem constants
#define BATCH 8
#define CH    512
#define SP    1024      // H*W = 32*32
#define NHEAD 8
#define HDIM  64
#define NGRP  32
#define GCH   16        // channels per group

// Scratch (device globals: allocation-free per harness rules)
__device__ __nv_bfloat16 g_h[BATCH * CH * SP];        // groupnorm out (bf16)
__device__ __nv_bfloat16 g_qkv[BATCH * 3 * CH * SP];  // qkv (bf16)
__device__ __nv_bfloat16 g_att[BATCH * CH * SP];      // attention out (bf16)
__device__ uint32_t g_winp[(3 * CH) * (CH / 2)];      // bf16 w_in  [M][K]
__device__ uint32_t g_woutp[CH * (CH / 2)];           // bf16 w_out [M][K]

// ---------------------------------------------------------------------------
// Helpers
// ---------------------------------------------------------------------------
__device__ __forceinline__ uint32_t pk(float lo, float hi) {
    uint32_t r;
    asm("cvt.rn.bf16x2.f32 %0, %1, %2;" : "=r"(r) : "f"(hi), "f"(lo));
    return r;
}

#define MMA_BF16(d, a, b0, b1)                                              \
    asm volatile(                                                           \
        "mma.sync.aligned.m16n8k16.row.col.f32.bf16.bf16.f32 "              \
        "{%0,%1,%2,%3}, {%4,%5,%6,%7}, {%8,%9}, {%0,%1,%2,%3};"             \
        : "+f"(d[0]), "+f"(d[1]), "+f"(d[2]), "+f"(d[3])                    \
        : "r"(a[0]), "r"(a[1]), "r"(a[2]), "r"(a[3]), "r"(b0), "r"(b1))

#define LDSM4(d, addr)                                                      \
    asm volatile("ldmatrix.sync.aligned.m8n8.x4.shared.b16 "                \
                 "{%0,%1,%2,%3}, [%4];"                                     \
                 : "=r"((d)[0]), "=r"((d)[1]), "=r"((d)[2]), "=r"((d)[3])   \
                 : "r"(addr))

#define LDSM4T(d, addr)                                                     \
    asm volatile("ldmatrix.sync.aligned.m8n8.x4.trans.shared.b16 "          \
                 "{%0,%1,%2,%3}, [%4];"                                     \
                 : "=r"((d)[0]), "=r"((d)[1]), "=r"((d)[2]), "=r"((d)[3])   \
                 : "r"(addr))

#define CPA16(dst, src)                                                     \
    asm volatile("cp.async.cg.shared.global [%0], [%1], 16;"                \
                 :: "r"(dst), "l"(src))
#define CPA_COMMIT() asm volatile("cp.async.commit_group;")
#define CPA_WAIT0()  asm volatile("cp.async.wait_group 0;" ::: "memory")

// ---------------------------------------------------------------------------
// Weight prepack: fp32 [M][K] -> bf16 [M][K]
// ---------------------------------------------------------------------------
__global__ __launch_bounds__(256) void prepack_kernel(
    const float* __restrict__ w, uint32_t* __restrict__ wp, int nwords) {
    int i = blockIdx.x * 256 + threadIdx.x;
    if (i < nwords) {
        float2 v = *(const float2*)&w[2 * i];
        wp[i] = pk(v.x, v.y);
    }
}

// ---------------------------------------------------------------------------
// GroupNorm: stats + normalize, writes h bf16. One block per (batch, group).
// ---------------------------------------------------------------------------
__global__ void gn_kernel(const float* __restrict__ x,
                          const float* __restrict__ gamma,
                          const float* __restrict__ beta,
                          uint32_t* __restrict__ hw_all) {
    int b = blockIdx.x >> 5;
    int g = blockIdx.x & 31;
    const float* xp = x + ((size_t)b * CH + g * GCH) * SP;
    uint32_t* hw = hw_all + (((size_t)b * CH + g * GCH) * SP >> 1);
    int t = threadIdx.x;

    float sum = 0.f, sq = 0.f;
    for (int i4 = t; i4 < GCH * SP / 4; i4 += 256) {
        float4 v = *(const float4*)(xp + i4 * 4);
        sum += v.x + v.y + v.z + v.w;
        sq  += v.x * v.x + v.y * v.y + v.z * v.z + v.w * v.w;
    }
    __shared__ float s1[256], s2[256];
    s1[t] = sum; s2[t] = sq;
    __syncthreads();
    for (int off = 128; off > 0; off >>= 1) {
        if (t < off) { s1[t] += s1[t + off]; s2[t] += s2[t + off]; }
        __syncthreads();
    }
    const float invN = 1.f / (GCH * SP);
    float mean = s1[0] * invN;
    float var  = s2[0] * invN - mean * mean;
    float inv  = rsqrtf(var + 1e-6f);

    for (int i4 = t; i4 < GCH * SP / 4; i4 += 256) {
        int c = i4 >> 8;
        float sc = inv * gamma[g * GCH + c];
        float sh = beta[g * GCH + c] - mean * sc;
        float4 v = *(const float4*)(xp + i4 * 4);
        uint2 u;
        u.x = pk(v.x * sc + sh, v.y * sc + sh);
        u.y = pk(v.z * sc + sh, v.w * sc + sh);
        *(uint2*)&hw[i4 * 2] = u;
    }
}

// ---------------------------------------------------------------------------
// Templated GEMM (both projections) — unchanged from R12.
// ---------------------------------------------------------------------------
#define APW 20
#define BPW 68

template <int MODE>
__global__ __launch_bounds__(256, 2) void gemm_kernel(
    const uint32_t* __restrict__ Awp, const __nv_bfloat16* __restrict__ Bm,
    const float* __restrict__ bias, const float* __restrict__ resid,
    void* __restrict__ Cv, int M, int N, int K) {
    __shared__ uint32_t As[2][128 * APW];
    __shared__ uint32_t Bs[2][32 * BPW];

    int tid  = threadIdx.x;
    int warp = tid >> 5, lane = tid & 31;
    int gid = lane >> 2, tg = lane & 3;
    int g8 = lane >> 3, lr = lane & 7;
    int wm = (warp >> 1) * 32, wn = (warp & 1) * 64;
    int m0 = blockIdx.y * 128, n0 = blockIdx.x * 128;

    const uint32_t* Bw = (const uint32_t*)(Bm + (size_t)blockIdx.z * K * N);

    uint32_t asb[2] = {(uint32_t)__cvta_generic_to_shared(&As[0][0]),
                       (uint32_t)__cvta_generic_to_shared(&As[1][0])};
    uint32_t bsb[2] = {(uint32_t)__cvta_generic_to_shared(&Bs[0][0]),
                       (uint32_t)__cvta_generic_to_shared(&Bs[1][0])};

    int nt_ro = (g8 & 1) * 8 + lr;
    int nt_co = (g8 >> 1) * 8;
    uint32_t a_off[2];
#pragma unroll
    for (int mt = 0; mt < 2; mt++)
        a_off[mt] = ((wm + mt * 16 + nt_ro) * 40 + nt_co) * 2;

    float acc[2][8][4];
#pragma unroll
    for (int mt = 0; mt < 2; mt++)
#pragma unroll
        for (int nt = 0; nt < 8; nt++)
#pragma unroll
            for (int e = 0; e < 4; e++) acc[mt][nt][e] = 0.f;

    auto issue_tile = [&](int buf, int k0) {
#pragma unroll
        for (int l = 0; l < 2; l++) {
            int slot = tid + l * 256;
            int row = slot >> 2, c8 = (slot & 3) * 8, c4 = (slot & 3) * 4;
            CPA16(asb[buf] + (row * APW + c4) * 4,
                  &Awp[(size_t)(m0 + row) * (K >> 1) + ((k0 + c8) >> 1)]);
        }
#pragma unroll
        for (int l = 0; l < 2; l++) {
            int slot = tid + l * 256;
            int kk2 = slot >> 4, n8 = (slot & 15) * 8, n4 = (slot & 15) * 4;
            CPA16(bsb[buf] + (kk2 * BPW + n4) * 4,
                  &Bw[((size_t)(k0 + kk2) * N + n0 + n8) >> 1]);
        }
        CPA_COMMIT();
    };

    issue_tile(0, 0);
    CPA_WAIT0();
    __syncthreads();

    for (int k0 = 0; k0 < K; k0 += 32) {
        int cur = (k0 >> 5) & 1;
        bool nxt = (k0 + 32) < K;
        if (nxt) issue_tile(cur ^ 1, k0 + 32);

#pragma unroll
        for (int kk = 0; kk < 2; kk++) {
            int kb = kk * 16;
            uint32_t af[2][4];
            LDSM4(af[0], asb[cur] + a_off[0] + kb * 2);
            LDSM4(af[1], asb[cur] + a_off[1] + kb * 2);
#pragma unroll
            for (int ntp = 0; ntp < 4; ntp++) {
                uint32_t bb[4];
                LDSM4T(bb, bsb[cur] +
                           ((kb + nt_ro) * 136 + wn + ntp * 16 + nt_co) * 2);
                MMA_BF16(acc[0][2 * ntp],     af[0], bb[0], bb[1]);
                MMA_BF16(acc[1][2 * ntp],     af[1], bb[0], bb[1]);
                MMA_BF16(acc[0][2 * ntp + 1], af[0], bb[2], bb[3]);
                MMA_BF16(acc[1][2 * ntp + 1], af[1], bb[2], bb[3]);
            }
        }
        CPA_WAIT0();
        __syncthreads();
    }

    if (MODE == 0) {
        __nv_bfloat16* Cp = (__nv_bfloat16*)Cv + (size_t)blockIdx.z * M * N;
#pragma unroll
        for (int mt = 0; mt < 2; mt++) {
            int r0 = m0 + wm + mt * 16 + gid;
            int r1 = r0 + 8;
            float bv0 = bias[r0], bv1 = bias[r1];
#pragma unroll
            for (int nt = 0; nt < 8; nt++) {
                int col = n0 + wn + nt * 8 + tg * 2;
                ((uint32_t*)Cp)[((size_t)r0 * N + col) >> 1] =
                    pk(acc[mt][nt][0] + bv0, acc[mt][nt][1] + bv0);
                ((uint32_t*)Cp)[((size_t)r1 * N + col) >> 1] =
                    pk(acc[mt][nt][2] + bv1, acc[mt][nt][3] + bv1);
            }
        }
    } else {
        float* Cp       = (float*)Cv + (size_t)blockIdx.z * M * N;
        const float* Rp = resid + (size_t)blockIdx.z * M * N;
#pragma unroll
        for (int mt = 0; mt < 2; mt++) {
            int r0 = m0 + wm + mt * 16 + gid;
            int r1 = r0 + 8;
            float bv0 = bias[r0], bv1 = bias[r1];
#pragma unroll
            for (int nt = 0; nt < 8; nt++) {
                int col = n0 + wn + nt * 8 + tg * 2;
                float2 v0, v1;
                v0.x = acc[mt][nt][0] + bv0; v0.y = acc[mt][nt][1] + bv0;
                v1.x = acc[mt][nt][2] + bv1; v1.y = acc[mt][nt][3] + bv1;
                float2 q0 = *(const float2*)&Rp[(size_t)r0 * N + col];
                float2 q1 = *(const float2*)&Rp[(size_t)r1 * N + col];
                v0.x += q0.x; v0.y += q0.y;
                v1.x += q1.x; v1.y += q1.y;
                *(float2*)&Cp[(size_t)r0 * N + col] = v0;
                *(float2*)&Cp[(size_t)r1 * N + col] = v1;
            }
        }
    }
}

// ---------------------------------------------------------------------------
// BF16 flash attention — 64-q tiles, 4 warps/CTA, 2 CTAs/SM.
// qs: [c 64][q 64 halves] pitch 72 halves (36 words).
// ks/vs: [c 64][sp 128 halves] pitch 136 halves (68 words), double-buffered.
// p_s: [q 64][k2 64 words] pitch 68 words.
// smem = (2304 + 4*4352 + 4352) * 4 = 96256 B -> 2 CTAs per SM.
// ---------------------------------------------------------------------------
#define QSW 36   // qs pitch in words
#define KPW 68   // ks/vs/p_s pitch in words
#define ATTN_WORDS (64 * QSW + 4 * 64 * KPW + 64 * KPW)
#define ATTN_SMEM_BYTES (ATTN_WORDS * 4)

__global__ __launch_bounds__(128) void attn_bf16_kernel(
    const __nv_bfloat16* __restrict__ qkv, __nv_bfloat16* __restrict__ out) {
    extern __shared__ uint32_t smw[];
    uint32_t* qs  = smw;                        // 64 x 36
    uint32_t* ks0 = qs + 64 * QSW;
    uint32_t* ks1 = ks0 + 64 * KPW;
    uint32_t* vs0 = ks1 + 64 * KPW;
    uint32_t* vs1 = vs0 + 64 * KPW;
    uint32_t* p_s = vs1 + 64 * KPW;             // 64 x 68
    __shared__ float corr_s[4][16];
    __shared__ float l_s[4][16];

    int tid  = threadIdx.x;
    int warp = tid >> 5, lane = tid & 31;
    int gid = lane >> 2, tg = lane & 3;
    int g8 = lane >> 3, lr = lane & 7;
    int wm = warp * 16;                // q offset within 64-row tile
    int qt = blockIdx.x * 64;
    int hn = blockIdx.y, b = blockIdx.z;

    const __nv_bfloat16* qg = qkv + ((size_t)b * 3 * CH + hn * HDIM) * SP;
    const __nv_bfloat16* kg = qg + (size_t)CH * SP;
    const __nv_bfloat16* vg = kg + (size_t)CH * SP;
    __nv_bfloat16* og = out + ((size_t)b * CH + hn * HDIM) * SP;

    const float SC = 0.125f * 1.44269504088896f;

    uint32_t qsb = (uint32_t)__cvta_generic_to_shared(qs);
    uint32_t ksbu[2] = {(uint32_t)__cvta_generic_to_shared(ks0),
                        (uint32_t)__cvta_generic_to_shared(ks1)};
    uint32_t vsbu[2] = {(uint32_t)__cvta_generic_to_shared(vs0),
                        (uint32_t)__cvta_generic_to_shared(vs1)};

    int nt_ro = (g8 & 1) * 8 + lr;
    int nt_co = (g8 >> 1) * 8;
    int qa_ro = (g8 >> 1) * 8 + lr;
    int qa_co = (g8 & 1) * 8;

    const uint32_t* qw = (const uint32_t*)qg;
    const uint32_t* kw = (const uint32_t*)kg;
    const uint32_t* vw = (const uint32_t*)vg;

    auto issue_kv = [&](int buf, int kt) {
#pragma unroll
        for (int l = 0; l < 8; l++) {
            int slot = tid + l * 128;
            int row = slot >> 4, h8 = (slot & 15) * 8, w4 = (slot & 15) * 4;
            CPA16(ksbu[buf] + (row * KPW + w4) * 4,
                  &kw[((size_t)row * SP + kt + h8) >> 1]);
            CPA16(vsbu[buf] + (row * KPW + w4) * 4,
                  &vw[((size_t)row * SP + kt + h8) >> 1]);
        }
        CPA_COMMIT();
    };

    // Q tile (64c x 64 halves) + K/V tile 0 in one group
#pragma unroll
    for (int l = 0; l < 4; l++) {
        int slot = tid + l * 128;
        int row = slot >> 3, j = slot & 7;
        CPA16(qsb + (row * QSW + j * 4) * 4,
              &qw[((size_t)row * SP + qt + j * 8) >> 1]);
    }
    issue_kv(0, 0);
    CPA_WAIT0();
    __syncthreads();

    float m_run0 = -INFINITY, m_run1 = -INFINITY;
    float l_run0 = 0.f, l_run1 = 0.f;

    float acc_o[4][2][4];
#pragma unroll
    for (int mt = 0; mt < 4; mt++)
#pragma unroll
        for (int nq = 0; nq < 2; nq++)
#pragma unroll
            for (int e = 0; e < 4; e++) acc_o[mt][nq][e] = 0.f;

    for (int it = 0; it < SP / 128; it++) {
        int cur = it & 1;
        bool nxt = it < SP / 128 - 1;
        if (nxt) issue_kv(cur ^ 1, (it + 1) * 128);

        // ---- Phase 1: S[q16][k128] ----
        float acc_s[16][4];
#pragma unroll
        for (int nt = 0; nt < 16; nt++)
#pragma unroll
            for (int e = 0; e < 4; e++) acc_s[nt][e] = 0.f;

#pragma unroll
        for (int cc = 0; cc < 4; cc++) {
            int cb = cc * 16;
            uint32_t af[4];
            LDSM4T(af, qsb + ((cb + qa_ro) * 72 + wm + qa_co) * 2);
#pragma unroll
            for (int ntp = 0; ntp < 8; ntp++) {
                uint32_t bb[4];
                LDSM4T(bb, ksbu[cur] +
                           ((cb + nt_ro) * 136 + ntp * 16 + nt_co) * 2);
                MMA_BF16(acc_s[2 * ntp],     af, bb[0], bb[1]);
                MMA_BF16(acc_s[2 * ntp + 1], af, bb[2], bb[3]);
            }
        }

        // ---- Online softmax (exp2 domain) ----
        float mx0 = -INFINITY, mx1 = -INFINITY;
#pragma unroll
        for (int nt = 0; nt < 16; nt++) {
            acc_s[nt][0] *= SC; acc_s[nt][1] *= SC;
            acc_s[nt][2] *= SC; acc_s[nt][3] *= SC;
            mx0 = fmaxf(mx0, fmaxf(acc_s[nt][0], acc_s[nt][1]));
            mx1 = fmaxf(mx1, fmaxf(acc_s[nt][2], acc_s[nt][3]));
        }
        mx0 = fmaxf(mx0, __shfl_xor_sync(0xffffffffu, mx0, 1));
        mx0 = fmaxf(mx0, __shfl_xor_sync(0xffffffffu, mx0, 2));
        mx1 = fmaxf(mx1, __shfl_xor_sync(0xffffffffu, mx1, 1));
        mx1 = fmaxf(mx1, __shfl_xor_sync(0xffffffffu, mx1, 2));

        float mnew0 = fmaxf(m_run0, mx0);
        float mnew1 = fmaxf(m_run1, mx1);
        float corr0 = exp2f(m_run0 - mnew0);
        float corr1 = exp2f(m_run1 - mnew1);

        float ps0 = 0.f, ps1 = 0.f;
#pragma unroll
        for (int nt = 0; nt < 16; nt++) {
            float p0 = exp2f(acc_s[nt][0] - mnew0);
            float p1 = exp2f(acc_s[nt][1] - mnew0);
            float p2 = exp2f(acc_s[nt][2] - mnew1);
            float p3 = exp2f(acc_s[nt][3] - mnew1);
            ps0 += p0 + p1; ps1 += p2 + p3;
            p_s[(wm + gid) * KPW + nt * 4 + tg]     = pk(p0, p1);
            p_s[(wm + gid + 8) * KPW + nt * 4 + tg] = pk(p2, p3);
        }
        ps0 += __shfl_xor_sync(0xffffffffu, ps0, 1);
        ps0 += __shfl_xor_sync(0xffffffffu, ps0, 2);
        ps1 += __shfl_xor_sync(0xffffffffu, ps1, 1);
        ps1 += __shfl_xor_sync(0xffffffffu, ps1, 2);
        l_run0 = l_run0 * corr0 + ps0;
        l_run1 = l_run1 * corr1 + ps1;
        m_run0 = mnew0; m_run1 = mnew1;
        if (tg == 0) {
            corr_s[warp][gid] = corr0;
            corr_s[warp][gid + 8] = corr1;
        }
        __syncwarp();

#pragma unroll
        for (int nq = 0; nq < 2; nq++) {
            float cc0 = corr_s[warp][nq * 8 + 2 * tg];
            float cc1 = corr_s[warp][nq * 8 + 2 * tg + 1];
#pragma unroll
            for (int mt = 0; mt < 4; mt++) {
                acc_o[mt][nq][0] *= cc0; acc_o[mt][nq][1] *= cc1;
                acc_o[mt][nq][2] *= cc0; acc_o[mt][nq][3] *= cc1;
            }
        }

        // ---- Phase 2: O^T[c64][q16] += V @ P^T ----
#pragma unroll
        for (int kc = 0; kc < 8; kc++) {
            int kb = kc * 16;
            uint32_t bq[2][2];
#pragma unroll
            for (int nq = 0; nq < 2; nq++) {
                bq[nq][0] = p_s[(wm + nq * 8 + gid) * KPW + (kb >> 1) + tg];
                bq[nq][1] = p_s[(wm + nq * 8 + gid) * KPW + (kb >> 1) + tg + 4];
            }
#pragma unroll
            for (int mt = 0; mt < 4; mt++) {
                uint32_t af[4];
                LDSM4(af, vsbu[cur] +
                          ((mt * 16 + nt_ro) * 136 + kb + nt_co) * 2);
                MMA_BF16(acc_o[mt][0], af, bq[0][0], bq[0][1]);
                MMA_BF16(acc_o[mt][1], af, bq[1][0], bq[1][1]);
            }
        }

        CPA_WAIT0();
        __syncthreads();
    }

    if (tg == 0) {
        l_s[warp][gid] = l_run0;
        l_s[warp][gid + 8] = l_run1;
    }
    __syncwarp();

#pragma unroll
    for (int nq = 0; nq < 2; nq++) {
        float il0 = 1.f / l_s[warp][nq * 8 + 2 * tg];
        float il1 = 1.f / l_s[warp][nq * 8 + 2 * tg + 1];
        int s = qt + wm + nq * 8 + 2 * tg;
#pragma unroll
        for (int mt = 0; mt < 4; mt++) {
            int c0r = mt * 16 + gid;
            ((uint32_t*)og)[((size_t)c0r * SP + s) >> 1] =
                pk(acc_o[mt][nq][0] * il0, acc_o[mt][nq][1] * il1);
            ((uint32_t*)og)[((size_t)(c0r + 8) * SP + s) >> 1] =
                pk(acc_o[mt][nq][2] * il0, acc_o[mt][nq][3] * il1);
        }
    }
}

// ---------------------------------------------------------------------------
extern "C" void kernel_launch(void* const* d_in, const int* in_sizes, int n_in,
                              void* d_out, int out_size) {
    const float* x     = (const float*)d_in[0];
    const float* gamma = (const float*)d_in[1];
    const float* beta  = (const float*)d_in[2];
    const float* w_in  = (const float*)d_in[3];
    const float* b_in  = (const float*)d_in[4];
    const float* w_out = (const float*)d_in[5];
    const float* b_out = (const float*)d_in[6];
    float* out = (float*)d_out;

    __nv_bfloat16 *h, *qkv, *att;
    uint32_t *winp, *woutp;
    cudaGetSymbolAddress((void**)&h,     g_h);
    cudaGetSymbolAddress((void**)&qkv,   g_qkv);
    cudaGetSymbolAddress((void**)&att,   g_att);
    cudaGetSymbolAddress((void**)&winp,  g_winp);
    cudaGetSymbolAddress((void**)&woutp, g_woutp);

    // 0. Weight prepack (bf16 row-major)
    prepack_kernel<<<(3 * CH * CH / 2 + 255) / 256, 256>>>(w_in, winp,
                                                           3 * CH * CH / 2);
    prepack_kernel<<<(CH * CH / 2 + 255) / 256, 256>>>(w_out, woutp,
                                                       CH * CH / 2);

    // 1. GroupNorm -> h bf16
    gn_kernel<<<BATCH * NGRP, 256>>>(x, gamma, beta, (uint32_t*)h);

    // 2. QKV projection (raw bf16 B tiles, cp.async)
    gemm_kernel<0><<<dim3(SP / 128, (3 * CH) / 128, BATCH), 256>>>(
        winp, h, b_in, nullptr, qkv, 3 * CH, SP, CH);

    // 3. Attention (64-q tiles, 4 warps, 2 CTAs/SM)
    cudaFuncSetAttribute(attn_bf16_kernel, cudaFuncAttributeMaxDynamicSharedMemorySize,
                         ATTN_SMEM_BYTES);
    attn_bf16_kernel<<<dim3(SP / 64, NHEAD, BATCH), 128, ATTN_SMEM_BYTES>>>(qkv, att);

    // 4. Output projection + bias + residual
    gemm_kernel<1><<<dim3(SP / 128, CH / 128, BATCH), 256>>>(
        woutp, att, b_out, x, out, CH, SP, CH);
}